// round 3
// baseline (speedup 1.0000x reference)
#include <cuda_runtime.h>
#include <math.h>

#define BATCH 2
#define SEQ   2048
#define EMB   1024
#define NH    32
#define KSEL  8
#define HD    128
#define NTOK  (BATCH*SEQ)      // 4096
#define HDALL (NH*HD)          // 4096
#define KD    (KSEL*HD)        // 1024

// ---------------- scratch (device globals: no runtime alloc allowed) ----------------
__device__ float g_all[(size_t)NTOK*HDALL];        // 64MB, reused for q_all/k_all/v_all
__device__ float g_q[(size_t)BATCH*KSEL*SEQ*HD];   // 16MB
__device__ float g_k[(size_t)BATCH*KSEL*SEQ*HD];
__device__ float g_v[(size_t)BATCH*KSEL*SEQ*HD];
__device__ float g_attn[(size_t)NTOK*KD];          // 16MB  [B,S,K,D]
__device__ int   g_idx[NTOK*KSEL];
__device__ float g_hw[NTOK*KSEL];
__device__ float g_pacc[BATCH*NH];
__device__ float g_facc[BATCH*NH];
__device__ float g_ent[1];

// ---------------- zero the router-stat accumulators ----------------
__global__ void zero_stats_kernel() {
    int t = threadIdx.x;
    if (t < BATCH*NH) { g_pacc[t] = 0.f; g_facc[t] = 0.f; }
    if (t == 0) g_ent[0] = 0.f;
}

// ---------------- router: logits, softmax, top-8, aux stats ----------------
__global__ void router_kernel(const float* __restrict__ x, const float* __restrict__ Wr) {
    __shared__ float xs[EMB];
    __shared__ float lg[NH];
    int tok = blockIdx.x;
    int tid = threadIdx.x;                // 32 threads, one per head
    const float* xr = x + (size_t)tok * EMB;
    for (int e = tid; e < EMB; e += 32) xs[e] = xr[e];
    __syncwarp();
    float acc = 0.f;
    #pragma unroll 8
    for (int e = 0; e < EMB; e++) acc += xs[e] * Wr[e*NH + tid];
    lg[tid] = acc;
    // full-softmax probs (for p and entropy)
    float m = acc;
    #pragma unroll
    for (int o = 16; o; o >>= 1) m = fmaxf(m, __shfl_xor_sync(0xffffffffu, m, o));
    float ex = expf(acc - m);
    float sum = ex;
    #pragma unroll
    for (int o = 16; o; o >>= 1) sum += __shfl_xor_sync(0xffffffffu, sum, o);
    float p = ex / sum;
    int b = tok / SEQ;
    atomicAdd(&g_pacc[b*NH + tid], p);
    float term = p * logf(p + 1e-8f);
    float esum = term;
    #pragma unroll
    for (int o = 16; o; o >>= 1) esum += __shfl_xor_sync(0xffffffffu, esum, o);
    if (tid == 0) atomicAdd(&g_ent[0], -esum);
    __syncwarp();
    if (tid == 0) {
        float tl[KSEL]; int ti[KSEL];
        unsigned mask = 0;
        for (int k = 0; k < KSEL; k++) {
            float best = -1e30f; int bi = 0;
            for (int h = 0; h < NH; h++)
                if (!((mask >> h) & 1u) && lg[h] > best) { best = lg[h]; bi = h; }
            mask |= 1u << bi; tl[k] = best; ti[k] = bi;
        }
        float ws = 0.f, w[KSEL];
        for (int k = 0; k < KSEL; k++) { w[k] = expf(tl[k] - tl[0]); ws += w[k]; }
        for (int k = 0; k < KSEL; k++) {
            g_hw[tok*KSEL + k] = w[k] / ws;
            g_idx[tok*KSEL + k] = ti[k];
        }
        atomicAdd(&g_facc[b*NH + ti[0]], 1.0f);
    }
}

// ---------------- SGEMM: C[M,N] = A[M,Kd] * B[Kd,N], all row-major ----------------
// 128x128 block tile, BK=8, 256 threads, 8x8 micro-tile
__global__ void __launch_bounds__(256) sgemm_kernel(
    const float* __restrict__ A, const float* __restrict__ Bm, float* __restrict__ C,
    int M, int N, int Kd)
{
    __shared__ float As[8][132];
    __shared__ float Bs[8][128];
    int tid = threadIdx.x;
    int tx = tid & 15, ty = tid >> 4;
    int row0 = blockIdx.y * 128, col0 = blockIdx.x * 128;
    float acc[8][8] = {};
    int arow = tid >> 1, acol = (tid & 1) * 4;
    int brow = tid >> 5, bcol = (tid & 31) * 4;
    const float* Aptr = A + (size_t)(row0 + arow) * Kd + acol;
    const float* Bptr = Bm + (size_t)brow * N + col0 + bcol;

    for (int k0 = 0; k0 < Kd; k0 += 8) {
        float4 av = *(const float4*)(Aptr + k0);
        float4 bv = *(const float4*)(Bptr + (size_t)k0 * N);
        As[acol+0][arow] = av.x; As[acol+1][arow] = av.y;
        As[acol+2][arow] = av.z; As[acol+3][arow] = av.w;
        *(float4*)&Bs[brow][bcol] = bv;
        __syncthreads();
        #pragma unroll
        for (int kk = 0; kk < 8; kk++) {
            float a[8], bb[8];
            *(float4*)(a)   = *(float4*)&As[kk][ty*8];
            *(float4*)(a+4) = *(float4*)&As[kk][ty*8+4];
            *(float4*)(bb)   = *(float4*)&Bs[kk][tx*8];
            *(float4*)(bb+4) = *(float4*)&Bs[kk][tx*8+4];
            #pragma unroll
            for (int i = 0; i < 8; i++)
                #pragma unroll
                for (int j = 0; j < 8; j++)
                    acc[i][j] += a[i] * bb[j];
        }
        __syncthreads();
    }
    #pragma unroll
    for (int i = 0; i < 8; i++) {
        int row = row0 + ty*8 + i;
        float4 s0 = make_float4(acc[i][0], acc[i][1], acc[i][2], acc[i][3]);
        float4 s1 = make_float4(acc[i][4], acc[i][5], acc[i][6], acc[i][7]);
        *(float4*)&C[(size_t)row * N + col0 + tx*8]     = s0;
        *(float4*)&C[(size_t)row * N + col0 + tx*8 + 4] = s1;
    }
}

// ---------------- gather selected heads + optional RoPE ----------------
// src: [B,S,H,D] (g_all). dst: [B,K,S,D].
__global__ void gather_rope_kernel(const float* __restrict__ src, float* __restrict__ dst,
                                   int use_rope)
{
    int tok = blockIdx.x;          // 0..NTOK-1
    int d   = threadIdx.x;         // 0..127
    int b = tok / SEQ, s = tok % SEQ;
    float c = 1.f, sn = 0.f;
    if (use_rope) {
        int i = d & 63;
        float invf = powf(10000.0f, -(float)i / 64.0f);
        float ang = (float)s * invf;
        c = cosf(ang); sn = sinf(ang);
    }
    #pragma unroll
    for (int j = 0; j < KSEL; j++) {
        int h = g_idx[tok*KSEL + j];
        const float* sp = src + ((size_t)tok * NH + h) * HD;
        float v1 = sp[d];
        if (use_rope) {
            float v2 = sp[d ^ 64];
            float rot = (d < 64) ? -v2 : v2;
            v1 = v1 * c + rot * sn;
        }
        dst[(((size_t)(b*KSEL + j)) * SEQ + s) * HD + d] = v1;
    }
}

// ---------------- causal flash attention (fp32) ----------------
// grid: (SEQ/64, BATCH*KSEL); 256 threads; Br=64, Bc=32, D=128
#define FBR 64
#define FBC 32
__global__ void __launch_bounds__(256) flash_kernel(
    const float* __restrict__ Q, const float* __restrict__ Kx, const float* __restrict__ Vx,
    const float* __restrict__ HWp, float* __restrict__ Out)
{
    extern __shared__ float sm[];
    float* Qs   = sm;                  // [64][132]
    float* Ks   = Qs + 64*132;         // [32][132]
    float* Vs   = Ks + 32*132;         // [32][132]
    float* Ps   = Vs + 32*132;         // [64][33]
    float* mrow = Ps + 64*33;          // [64]
    float* lrow = mrow + 64;           // [64]
    float* arow = lrow + 64;           // [64]

    int tid = threadIdx.x;
    int bk = blockIdx.y;
    int q0 = blockIdx.x * FBR;
    const float* Qp = Q  + (size_t)bk * SEQ * HD;
    const float* Kp = Kx + (size_t)bk * SEQ * HD;
    const float* Vp = Vx + (size_t)bk * SEQ * HD;

    for (int i = tid; i < FBR * (HD/4); i += 256) {
        int r = i >> 5, cc = (i & 31) * 4;
        *(float4*)&Qs[r*132 + cc] = *(const float4*)(Qp + (size_t)(q0 + r) * HD + cc);
    }
    if (tid < FBR) { mrow[tid] = -1e30f; lrow[tid] = 0.f; }
    float Oa[4][8];
    #pragma unroll
    for (int r = 0; r < 4; r++)
        #pragma unroll
        for (int cidx = 0; cidx < 8; cidx++) Oa[r][cidx] = 0.f;
    int rg = tid >> 4, cg = tid & 15;
    __syncthreads();

    int nkt = (q0 + FBR) / FBC;
    const float scale = 0.08838834764831845f;   // 1/sqrt(128)

    for (int kt = 0; kt < nkt; kt++) {
        int kb = kt * FBC;
        for (int i = tid; i < FBC * (HD/4); i += 256) {
            int r = i >> 5, cc = (i & 31) * 4;
            *(float4*)&Ks[r*132 + cc] = *(const float4*)(Kp + (size_t)(kb + r) * HD + cc);
            *(float4*)&Vs[r*132 + cc] = *(const float4*)(Vp + (size_t)(kb + r) * HD + cc);
        }
        __syncthreads();

        // S = Q K^T tile (64x32): thread -> rows rg*4..+3, cols cg*2..+1
        float sa[4][2] = {};
        #pragma unroll 4
        for (int c4 = 0; c4 < 32; c4++) {
            float4 k0 = *(float4*)&Ks[(cg*2)   * 132 + c4*4];
            float4 k1 = *(float4*)&Ks[(cg*2+1) * 132 + c4*4];
            #pragma unroll
            for (int r = 0; r < 4; r++) {
                float4 q = *(float4*)&Qs[(rg*4 + r) * 132 + c4*4];
                sa[r][0] += q.x*k0.x + q.y*k0.y + q.z*k0.z + q.w*k0.w;
                sa[r][1] += q.x*k1.x + q.y*k1.y + q.z*k1.z + q.w*k1.w;
            }
        }
        #pragma unroll
        for (int r = 0; r < 4; r++) {
            Ps[(rg*4 + r)*33 + cg*2    ] = sa[r][0] * scale;
            Ps[(rg*4 + r)*33 + cg*2 + 1] = sa[r][1] * scale;
        }
        __syncthreads();

        // online softmax per row
        if (tid < FBR) {
            int r = tid, gq = q0 + r;
            int lim = gq - kb;                 // valid cols c <= lim
            float mx = -1e30f;
            for (int cc = 0; cc < FBC; cc++)
                if (cc <= lim) mx = fmaxf(mx, Ps[r*33 + cc]);
            float mo = mrow[r];
            float mn = fmaxf(mo, mx);
            float al = __expf(mo - mn);
            float ss = 0.f;
            for (int cc = 0; cc < FBC; cc++) {
                float pv = (cc <= lim) ? __expf(Ps[r*33 + cc] - mn) : 0.f;
                Ps[r*33 + cc] = pv;
                ss += pv;
            }
            lrow[r] = lrow[r] * al + ss;
            mrow[r] = mn;
            arow[r] = al;
        }
        __syncthreads();

        // O = O*alpha + P V : thread -> rows rg*4..+3, cols cg*8..+7
        float alr[4];
        #pragma unroll
        for (int r = 0; r < 4; r++) alr[r] = arow[rg*4 + r];
        #pragma unroll
        for (int r = 0; r < 4; r++)
            #pragma unroll
            for (int cidx = 0; cidx < 8; cidx++) Oa[r][cidx] *= alr[r];
        for (int jj = 0; jj < FBC; jj++) {
            float p0 = Ps[(rg*4+0)*33 + jj];
            float p1 = Ps[(rg*4+1)*33 + jj];
            float p2 = Ps[(rg*4+2)*33 + jj];
            float p3 = Ps[(rg*4+3)*33 + jj];
            float4 v0 = *(float4*)&Vs[jj*132 + cg*8];
            float4 v1 = *(float4*)&Vs[jj*132 + cg*8 + 4];
            Oa[0][0]+=p0*v0.x; Oa[0][1]+=p0*v0.y; Oa[0][2]+=p0*v0.z; Oa[0][3]+=p0*v0.w;
            Oa[0][4]+=p0*v1.x; Oa[0][5]+=p0*v1.y; Oa[0][6]+=p0*v1.z; Oa[0][7]+=p0*v1.w;
            Oa[1][0]+=p1*v0.x; Oa[1][1]+=p1*v0.y; Oa[1][2]+=p1*v0.z; Oa[1][3]+=p1*v0.w;
            Oa[1][4]+=p1*v1.x; Oa[1][5]+=p1*v1.y; Oa[1][6]+=p1*v1.z; Oa[1][7]+=p1*v1.w;
            Oa[2][0]+=p2*v0.x; Oa[2][1]+=p2*v0.y; Oa[2][2]+=p2*v0.z; Oa[2][3]+=p2*v0.w;
            Oa[2][4]+=p2*v1.x; Oa[2][5]+=p2*v1.y; Oa[2][6]+=p2*v1.z; Oa[2][7]+=p2*v1.w;
            Oa[3][0]+=p3*v0.x; Oa[3][1]+=p3*v0.y; Oa[3][2]+=p3*v0.z; Oa[3][3]+=p3*v0.w;
            Oa[3][4]+=p3*v1.x; Oa[3][5]+=p3*v1.y; Oa[3][6]+=p3*v1.z; Oa[3][7]+=p3*v1.w;
        }
        __syncthreads();
    }

    // epilogue: 1/l, head weight, store to [B,S,K,D]
    int b = bk >> 3, j = bk & 7;
    #pragma unroll
    for (int r = 0; r < 4; r++) {
        int row = rg*4 + r, gq = q0 + row;
        float w = HWp[((size_t)(b*SEQ + gq)) * KSEL + j] / lrow[row];
        float4 o0 = make_float4(Oa[r][0]*w, Oa[r][1]*w, Oa[r][2]*w, Oa[r][3]*w);
        float4 o1 = make_float4(Oa[r][4]*w, Oa[r][5]*w, Oa[r][6]*w, Oa[r][7]*w);
        size_t off = (((size_t)(b*SEQ + gq)) * KSEL + j) * HD + cg*8;
        *(float4*)&Out[off]     = o0;
        *(float4*)&Out[off + 4] = o1;
    }
}

// ---------------- aux loss + head_counts tail ----------------
__global__ void finalize_kernel(float* __restrict__ out, int out_size) {
    int base = NTOK * EMB;
    int extra = out_size - base;
    if (extra <= 0) return;
    bool has_aux = (extra == BATCH*NH + 1) || (extra == 1);
    int zend = has_aux ? out_size - 1 : out_size;
    int gtid = blockIdx.x * blockDim.x + threadIdx.x;
    for (int i = base + gtid; i < zend; i += gridDim.x * blockDim.x) out[i] = 0.f;
    if (gtid == 0 && has_aux) {
        float aux = 0.f;
        for (int b = 0; b < BATCH; b++) {
            float sb = 0.f;
            for (int h = 0; h < NH; h++)
                sb += (g_facc[b*NH + h] / (float)SEQ) * (g_pacc[b*NH + h] / (float)SEQ);
            aux += sb;
        }
        aux = (float)NH * aux / (float)BATCH - 0.01f * (g_ent[0] / (float)(BATCH*SEQ));
        out[out_size - 1] = aux;
    }
}

// ---------------- launcher ----------------
extern "C" void kernel_launch(void* const* d_in, const int* in_sizes, int n_in,
                              void* d_out, int out_size)
{
    (void)in_sizes; (void)n_in;
    const float* x  = (const float*)d_in[0];
    const float* Wq = (const float*)d_in[1];
    const float* Wk = (const float*)d_in[2];
    const float* Wv = (const float*)d_in[3];
    const float* Wr = (const float*)d_in[4];
    const float* Wo = (const float*)d_in[5];
    float* out = (float*)d_out;

    float *p_all, *p_q, *p_k, *p_v, *p_attn, *p_hw;
    cudaGetSymbolAddress((void**)&p_all,  g_all);
    cudaGetSymbolAddress((void**)&p_q,    g_q);
    cudaGetSymbolAddress((void**)&p_k,    g_k);
    cudaGetSymbolAddress((void**)&p_v,    g_v);
    cudaGetSymbolAddress((void**)&p_attn, g_attn);
    cudaGetSymbolAddress((void**)&p_hw,   g_hw);

    size_t flash_smem = (size_t)(64*132 + 32*132 + 32*132 + 64*33 + 3*64) * sizeof(float);
    cudaFuncSetAttribute(flash_kernel, cudaFuncAttributeMaxDynamicSharedMemorySize,
                         (int)flash_smem);

    zero_stats_kernel<<<1, 128>>>();
    router_kernel<<<NTOK, 32>>>(x, Wr);

    dim3 gproj(HDALL/128, NTOK/128);   // (32, 32)
    sgemm_kernel<<<gproj, 256>>>(x, Wq, p_all, NTOK, HDALL, EMB);
    gather_rope_kernel<<<NTOK, HD>>>(p_all, p_q, 1);
    sgemm_kernel<<<gproj, 256>>>(x, Wk, p_all, NTOK, HDALL, EMB);
    gather_rope_kernel<<<NTOK, HD>>>(p_all, p_k, 1);
    sgemm_kernel<<<gproj, 256>>>(x, Wv, p_all, NTOK, HDALL, EMB);
    gather_rope_kernel<<<NTOK, HD>>>(p_all, p_v, 0);

    dim3 gflash(SEQ/FBR, BATCH*KSEL);  // (32, 16)
    flash_kernel<<<gflash, 256, flash_smem>>>(p_q, p_k, p_v, p_hw, p_attn);

    dim3 gout(EMB/128, NTOK/128);      // (8, 32)
    sgemm_kernel<<<gout, 256>>>(p_attn, Wo, out, NTOK, EMB, EMB);

    finalize_kernel<<<32, 256>>>(out, out_size);
}

// round 5
// speedup vs baseline: 1.2466x; 1.2466x over previous
#include <cuda_runtime.h>
#include <mma.h>
#include <math.h>

using namespace nvcuda;

#define BATCH 2
#define SEQ   2048
#define EMB   1024
#define NH    32
#define KSEL  8
#define HD    128
#define NTOK  (BATCH*SEQ)      // 4096
#define HDALL (NH*HD)          // 4096
#define KD    (KSEL*HD)        // 1024

// ---------------- scratch (device globals: no runtime alloc allowed) ----------------
__device__ float g_all[(size_t)NTOK*HDALL];        // 64MB, reused for q_all/k_all/v_all
__device__ float g_q[(size_t)BATCH*KSEL*SEQ*HD];   // 16MB
__device__ float g_k[(size_t)BATCH*KSEL*SEQ*HD];
__device__ float g_v[(size_t)BATCH*KSEL*SEQ*HD];
__device__ float g_attn[(size_t)NTOK*KD];          // 16MB  [B,S,K,D]
__device__ int   g_idx[NTOK*KSEL];
__device__ float g_hw[NTOK*KSEL];
__device__ float g_pacc[BATCH*NH];
__device__ float g_facc[BATCH*NH];
__device__ float g_ent[1];

// ---------------- zero the router-stat accumulators ----------------
__global__ void zero_stats_kernel() {
    int t = threadIdx.x;
    if (t < BATCH*NH) { g_pacc[t] = 0.f; g_facc[t] = 0.f; }
    if (t == 0) g_ent[0] = 0.f;
}

// ---------------- router: logits, softmax, top-8, aux stats ----------------
__global__ void router_kernel(const float* __restrict__ x, const float* __restrict__ Wr) {
    __shared__ float xs[EMB];
    __shared__ float lg[NH];
    int tok = blockIdx.x;
    int tid = threadIdx.x;                // 32 threads, one per head
    const float* xr = x + (size_t)tok * EMB;
    for (int e = tid; e < EMB; e += 32) xs[e] = xr[e];
    __syncwarp();
    float acc = 0.f;
    #pragma unroll 8
    for (int e = 0; e < EMB; e++) acc += xs[e] * Wr[e*NH + tid];
    lg[tid] = acc;
    float m = acc;
    #pragma unroll
    for (int o = 16; o; o >>= 1) m = fmaxf(m, __shfl_xor_sync(0xffffffffu, m, o));
    float ex = expf(acc - m);
    float sum = ex;
    #pragma unroll
    for (int o = 16; o; o >>= 1) sum += __shfl_xor_sync(0xffffffffu, sum, o);
    float p = ex / sum;
    int b = tok / SEQ;
    atomicAdd(&g_pacc[b*NH + tid], p);
    float term = p * logf(p + 1e-8f);
    float esum = term;
    #pragma unroll
    for (int o = 16; o; o >>= 1) esum += __shfl_xor_sync(0xffffffffu, esum, o);
    if (tid == 0) atomicAdd(&g_ent[0], -esum);
    __syncwarp();
    if (tid == 0) {
        float tl[KSEL]; int ti[KSEL];
        unsigned mask = 0;
        for (int k = 0; k < KSEL; k++) {
            float best = -1e30f; int bi = 0;
            for (int h = 0; h < NH; h++)
                if (!((mask >> h) & 1u) && lg[h] > best) { best = lg[h]; bi = h; }
            mask |= 1u << bi; tl[k] = best; ti[k] = bi;
        }
        float ws = 0.f, w[KSEL];
        for (int k = 0; k < KSEL; k++) { w[k] = expf(tl[k] - tl[0]); ws += w[k]; }
        for (int k = 0; k < KSEL; k++) {
            g_hw[tok*KSEL + k] = w[k] / ws;
            g_idx[tok*KSEL + k] = ti[k];
        }
        atomicAdd(&g_facc[b*NH + ti[0]], 1.0f);
    }
}

// ---------------- TF32 tensor-core GEMM ----------------
// C[M,N] = A[M,Kd] * B[Kd,N], row-major. BM=BN=128, BK=32.
// 256 threads = 8 warps in 2x4 grid; warp tile 64x32 = 4x2 wmma 16x16 frags.
// cp.async double-buffered smem.
#define BM 128
#define BN 128
#define BKt 32
#define LDA 36      // 36*4B = 144B, multiple of 16
#define LDB 132

#define CPA16(dst, src) asm volatile("cp.async.cg.shared.global [%0], [%1], 16;\n" \
        :: "r"(dst), "l"(src))
#define CPA_COMMIT() asm volatile("cp.async.commit_group;\n")
#define CPA_WAIT1()  asm volatile("cp.async.wait_group 1;\n")
#define CPA_WAIT0()  asm volatile("cp.async.wait_group 0;\n")

__global__ void __launch_bounds__(256) tf32_gemm_kernel(
    const float* __restrict__ A, const float* __restrict__ Bm, float* __restrict__ C,
    int M, int N, int Kd)
{
    extern __shared__ float sm[];
    float* As[2] = { sm, sm + BM*LDA };
    float* Bs[2] = { sm + 2*BM*LDA, sm + 2*BM*LDA + BKt*LDB };

    int tid = threadIdx.x;
    int wid = tid >> 5;
    int wm = wid >> 2;          // 0..1  (64-row slab)
    int wn = wid & 3;           // 0..3  (32-col slab)
    int row0 = blockIdx.y * BM, col0 = blockIdx.x * BN;

    // loader mapping: 1024 float4 per tile, 4 per thread
    int ar[4], ac[4], br[4], bc[4];
    #pragma unroll
    for (int i = 0; i < 4; i++) {
        int idx = tid + i*256;
        ar[i] = idx >> 3;  ac[i] = (idx & 7) * 4;
        br[i] = idx >> 5;  bc[i] = (idx & 31) * 4;
    }

    wmma::fragment<wmma::accumulator, 16, 16, 8, float> cfr[4][2];
    #pragma unroll
    for (int i = 0; i < 4; i++)
        #pragma unroll
        for (int j = 0; j < 2; j++) wmma::fill_fragment(cfr[i][j], 0.0f);

    int ntiles = Kd / BKt;

    // prologue: tile 0 -> buf 0
    #pragma unroll
    for (int i = 0; i < 4; i++) {
        unsigned da = (unsigned)__cvta_generic_to_shared(As[0] + ar[i]*LDA + ac[i]);
        CPA16(da, A + (size_t)(row0 + ar[i]) * Kd + ac[i]);
        unsigned db = (unsigned)__cvta_generic_to_shared(Bs[0] + br[i]*LDB + bc[i]);
        CPA16(db, Bm + (size_t)br[i] * N + col0 + bc[i]);
    }
    CPA_COMMIT();

    for (int t = 0; t < ntiles; t++) {
        int buf = t & 1;
        if (t + 1 < ntiles) {
            int nb = (t + 1) & 1;
            int k0 = (t + 1) * BKt;
            #pragma unroll
            for (int i = 0; i < 4; i++) {
                unsigned da = (unsigned)__cvta_generic_to_shared(As[nb] + ar[i]*LDA + ac[i]);
                CPA16(da, A + (size_t)(row0 + ar[i]) * Kd + k0 + ac[i]);
                unsigned db = (unsigned)__cvta_generic_to_shared(Bs[nb] + br[i]*LDB + bc[i]);
                CPA16(db, Bm + (size_t)(k0 + br[i]) * N + col0 + bc[i]);
            }
            CPA_COMMIT();
            CPA_WAIT1();
        } else {
            CPA_WAIT0();
        }
        __syncthreads();

        float* Ab = As[buf];
        float* Bb = Bs[buf];
        #pragma unroll
        for (int kk = 0; kk < BKt/8; kk++) {
            wmma::fragment<wmma::matrix_a, 16, 16, 8, wmma::precision::tf32, wmma::row_major> af[4];
            wmma::fragment<wmma::matrix_b, 16, 16, 8, wmma::precision::tf32, wmma::row_major> bf[2];
            #pragma unroll
            for (int i = 0; i < 4; i++) {
                wmma::load_matrix_sync(af[i], Ab + (wm*64 + i*16)*LDA + kk*8, LDA);
                #pragma unroll
                for (int e = 0; e < af[i].num_elements; e++)
                    af[i].x[e] = wmma::__float_to_tf32(af[i].x[e]);
            }
            #pragma unroll
            for (int j = 0; j < 2; j++) {
                wmma::load_matrix_sync(bf[j], Bb + kk*8*LDB + wn*32 + j*16, LDB);
                #pragma unroll
                for (int e = 0; e < bf[j].num_elements; e++)
                    bf[j].x[e] = wmma::__float_to_tf32(bf[j].x[e]);
            }
            #pragma unroll
            for (int i = 0; i < 4; i++)
                #pragma unroll
                for (int j = 0; j < 2; j++)
                    wmma::mma_sync(cfr[i][j], af[i], bf[j], cfr[i][j]);
        }
        __syncthreads();
    }

    #pragma unroll
    for (int i = 0; i < 4; i++)
        #pragma unroll
        for (int j = 0; j < 2; j++)
            wmma::store_matrix_sync(
                C + (size_t)(row0 + wm*64 + i*16) * N + col0 + wn*32 + j*16,
                cfr[i][j], N, wmma::mem_row_major);
}

// ---------------- gather selected heads + optional RoPE ----------------
__global__ void gather_rope_kernel(const float* __restrict__ src, float* __restrict__ dst,
                                   int use_rope)
{
    int tok = blockIdx.x;
    int d   = threadIdx.x;
    int b = tok / SEQ, s = tok % SEQ;
    float c = 1.f, sn = 0.f;
    if (use_rope) {
        int i = d & 63;
        float invf = powf(10000.0f, -(float)i / 64.0f);
        float ang = (float)s * invf;
        c = cosf(ang); sn = sinf(ang);
    }
    #pragma unroll
    for (int j = 0; j < KSEL; j++) {
        int h = g_idx[tok*KSEL + j];
        const float* sp = src + ((size_t)tok * NH + h) * HD;
        float v1 = sp[d];
        if (use_rope) {
            float v2 = sp[d ^ 64];
            float rot = (d < 64) ? -v2 : v2;
            v1 = v1 * c + rot * sn;
        }
        dst[(((size_t)(b*KSEL + j)) * SEQ + s) * HD + d] = v1;
    }
}

// ---------------- causal flash attention (fp32) ----------------
#define FBR 64
#define FBC 32
__global__ void __launch_bounds__(256) flash_kernel(
    const float* __restrict__ Q, const float* __restrict__ Kx, const float* __restrict__ Vx,
    const float* __restrict__ HWp, float* __restrict__ Out)
{
    extern __shared__ float smf[];
    float* Qs   = smf;
    float* Ks   = Qs + 64*132;
    float* Vs   = Ks + 32*132;
    float* Ps   = Vs + 32*132;
    float* mrow = Ps + 64*33;
    float* lrow = mrow + 64;
    float* arow = lrow + 64;

    int tid = threadIdx.x;
    int bk = blockIdx.y;
    int q0 = blockIdx.x * FBR;
    const float* Qp = Q  + (size_t)bk * SEQ * HD;
    const float* Kp = Kx + (size_t)bk * SEQ * HD;
    const float* Vp = Vx + (size_t)bk * SEQ * HD;

    for (int i = tid; i < FBR * (HD/4); i += 256) {
        int r = i >> 5, cc = (i & 31) * 4;
        *(float4*)&Qs[r*132 + cc] = *(const float4*)(Qp + (size_t)(q0 + r) * HD + cc);
    }
    if (tid < FBR) { mrow[tid] = -1e30f; lrow[tid] = 0.f; }
    float Oa[4][8];
    #pragma unroll
    for (int r = 0; r < 4; r++)
        #pragma unroll
        for (int cidx = 0; cidx < 8; cidx++) Oa[r][cidx] = 0.f;
    int rg = tid >> 4, cg = tid & 15;
    __syncthreads();

    int nkt = (q0 + FBR) / FBC;
    const float scale = 0.08838834764831845f;

    for (int kt = 0; kt < nkt; kt++) {
        int kb = kt * FBC;
        for (int i = tid; i < FBC * (HD/4); i += 256) {
            int r = i >> 5, cc = (i & 31) * 4;
            *(float4*)&Ks[r*132 + cc] = *(const float4*)(Kp + (size_t)(kb + r) * HD + cc);
            *(float4*)&Vs[r*132 + cc] = *(const float4*)(Vp + (size_t)(kb + r) * HD + cc);
        }
        __syncthreads();

        float sa[4][2] = {};
        #pragma unroll 4
        for (int c4 = 0; c4 < 32; c4++) {
            float4 k0 = *(float4*)&Ks[(cg*2)   * 132 + c4*4];
            float4 k1 = *(float4*)&Ks[(cg*2+1) * 132 + c4*4];
            #pragma unroll
            for (int r = 0; r < 4; r++) {
                float4 q = *(float4*)&Qs[(rg*4 + r) * 132 + c4*4];
                sa[r][0] += q.x*k0.x + q.y*k0.y + q.z*k0.z + q.w*k0.w;
                sa[r][1] += q.x*k1.x + q.y*k1.y + q.z*k1.z + q.w*k1.w;
            }
        }
        #pragma unroll
        for (int r = 0; r < 4; r++) {
            Ps[(rg*4 + r)*33 + cg*2    ] = sa[r][0] * scale;
            Ps[(rg*4 + r)*33 + cg*2 + 1] = sa[r][1] * scale;
        }
        __syncthreads();

        if (tid < FBR) {
            int r = tid, gq = q0 + r;
            int lim = gq - kb;
            float mx = -1e30f;
            for (int cc = 0; cc < FBC; cc++)
                if (cc <= lim) mx = fmaxf(mx, Ps[r*33 + cc]);
            float mo = mrow[r];
            float mn = fmaxf(mo, mx);
            float al = __expf(mo - mn);
            float ss = 0.f;
            for (int cc = 0; cc < FBC; cc++) {
                float pv = (cc <= lim) ? __expf(Ps[r*33 + cc] - mn) : 0.f;
                Ps[r*33 + cc] = pv;
                ss += pv;
            }
            lrow[r] = lrow[r] * al + ss;
            mrow[r] = mn;
            arow[r] = al;
        }
        __syncthreads();

        float alr[4];
        #pragma unroll
        for (int r = 0; r < 4; r++) alr[r] = arow[rg*4 + r];
        #pragma unroll
        for (int r = 0; r < 4; r++)
            #pragma unroll
            for (int cidx = 0; cidx < 8; cidx++) Oa[r][cidx] *= alr[r];
        for (int jj = 0; jj < FBC; jj++) {
            float p0 = Ps[(rg*4+0)*33 + jj];
            float p1 = Ps[(rg*4+1)*33 + jj];
            float p2 = Ps[(rg*4+2)*33 + jj];
            float p3 = Ps[(rg*4+3)*33 + jj];
            float4 v0 = *(float4*)&Vs[jj*132 + cg*8];
            float4 v1 = *(float4*)&Vs[jj*132 + cg*8 + 4];
            Oa[0][0]+=p0*v0.x; Oa[0][1]+=p0*v0.y; Oa[0][2]+=p0*v0.z; Oa[0][3]+=p0*v0.w;
            Oa[0][4]+=p0*v1.x; Oa[0][5]+=p0*v1.y; Oa[0][6]+=p0*v1.z; Oa[0][7]+=p0*v1.w;
            Oa[1][0]+=p1*v0.x; Oa[1][1]+=p1*v0.y; Oa[1][2]+=p1*v0.z; Oa[1][3]+=p1*v0.w;
            Oa[1][4]+=p1*v1.x; Oa[1][5]+=p1*v1.y; Oa[1][6]+=p1*v1.z; Oa[1][7]+=p1*v1.w;
            Oa[2][0]+=p2*v0.x; Oa[2][1]+=p2*v0.y; Oa[2][2]+=p2*v0.z; Oa[2][3]+=p2*v0.w;
            Oa[2][4]+=p2*v1.x; Oa[2][5]+=p2*v1.y; Oa[2][6]+=p2*v1.z; Oa[2][7]+=p2*v1.w;
            Oa[3][0]+=p3*v0.x; Oa[3][1]+=p3*v0.y; Oa[3][2]+=p3*v0.z; Oa[3][3]+=p3*v0.w;
            Oa[3][4]+=p3*v1.x; Oa[3][5]+=p3*v1.y; Oa[3][6]+=p3*v1.z; Oa[3][7]+=p3*v1.w;
        }
        __syncthreads();
    }

    int b = bk >> 3, j = bk & 7;
    #pragma unroll
    for (int r = 0; r < 4; r++) {
        int row = rg*4 + r, gq = q0 + row;
        float w = HWp[((size_t)(b*SEQ + gq)) * KSEL + j] / lrow[row];
        float4 o0 = make_float4(Oa[r][0]*w, Oa[r][1]*w, Oa[r][2]*w, Oa[r][3]*w);
        float4 o1 = make_float4(Oa[r][4]*w, Oa[r][5]*w, Oa[r][6]*w, Oa[r][7]*w);
        size_t off = (((size_t)(b*SEQ + gq)) * KSEL + j) * HD + cg*8;
        *(float4*)&Out[off]     = o0;
        *(float4*)&Out[off + 4] = o1;
    }
}

// ---------------- aux loss + head_counts tail ----------------
__global__ void finalize_kernel(float* __restrict__ out, int out_size) {
    int base = NTOK * EMB;
    int extra = out_size - base;
    if (extra <= 0) return;
    bool has_aux = (extra == BATCH*NH + 1) || (extra == 1);
    int zend = has_aux ? out_size - 1 : out_size;
    int gtid = blockIdx.x * blockDim.x + threadIdx.x;
    for (int i = base + gtid; i < zend; i += gridDim.x * blockDim.x) out[i] = 0.f;
    if (gtid == 0 && has_aux) {
        float aux = 0.f;
        for (int b = 0; b < BATCH; b++) {
            float sb = 0.f;
            for (int h = 0; h < NH; h++)
                sb += (g_facc[b*NH + h] / (float)SEQ) * (g_pacc[b*NH + h] / (float)SEQ);
            aux += sb;
        }
        aux = (float)NH * aux / (float)BATCH - 0.01f * (g_ent[0] / (float)(BATCH*SEQ));
        out[out_size - 1] = aux;
    }
}

// ---------------- launcher ----------------
extern "C" void kernel_launch(void* const* d_in, const int* in_sizes, int n_in,
                              void* d_out, int out_size)
{
    (void)in_sizes; (void)n_in;
    const float* x  = (const float*)d_in[0];
    const float* Wq = (const float*)d_in[1];
    const float* Wk = (const float*)d_in[2];
    const float* Wv = (const float*)d_in[3];
    const float* Wr = (const float*)d_in[4];
    const float* Wo = (const float*)d_in[5];
    float* out = (float*)d_out;

    float *p_all, *p_q, *p_k, *p_v, *p_attn, *p_hw;
    cudaGetSymbolAddress((void**)&p_all,  g_all);
    cudaGetSymbolAddress((void**)&p_q,    g_q);
    cudaGetSymbolAddress((void**)&p_k,    g_k);
    cudaGetSymbolAddress((void**)&p_v,    g_v);
    cudaGetSymbolAddress((void**)&p_attn, g_attn);
    cudaGetSymbolAddress((void**)&p_hw,   g_hw);

    size_t gemm_smem = (size_t)(2*BM*LDA + 2*BKt*LDB) * sizeof(float);   // 70656 B
    cudaFuncSetAttribute(tf32_gemm_kernel, cudaFuncAttributeMaxDynamicSharedMemorySize,
                         (int)gemm_smem);
    size_t flash_smem = (size_t)(64*132 + 32*132 + 32*132 + 64*33 + 3*64) * sizeof(float);
    cudaFuncSetAttribute(flash_kernel, cudaFuncAttributeMaxDynamicSharedMemorySize,
                         (int)flash_smem);

    zero_stats_kernel<<<1, 128>>>();
    router_kernel<<<NTOK, 32>>>(x, Wr);

    dim3 gproj(HDALL/BN, NTOK/BM);     // (32, 32)
    tf32_gemm_kernel<<<gproj, 256, gemm_smem>>>(x, Wq, p_all, NTOK, HDALL, EMB);
    gather_rope_kernel<<<NTOK, HD>>>(p_all, p_q, 1);
    tf32_gemm_kernel<<<gproj, 256, gemm_smem>>>(x, Wk, p_all, NTOK, HDALL, EMB);
    gather_rope_kernel<<<NTOK, HD>>>(p_all, p_k, 1);
    tf32_gemm_kernel<<<gproj, 256, gemm_smem>>>(x, Wv, p_all, NTOK, HDALL, EMB);
    gather_rope_kernel<<<NTOK, HD>>>(p_all, p_v, 0);

    dim3 gflash(SEQ/FBR, BATCH*KSEL);  // (32, 16)
    flash_kernel<<<gflash, 256, flash_smem>>>(p_q, p_k, p_v, p_hw, p_attn);

    dim3 gout(EMB/BN, NTOK/BM);        // (8, 32)
    tf32_gemm_kernel<<<gout, 256, gemm_smem>>>(p_attn, Wo, out, NTOK, EMB, EMB);

    finalize_kernel<<<32, 256>>>(out, out_size);
}

// round 7
// speedup vs baseline: 2.1116x; 1.6939x over previous
#include <cuda_runtime.h>
#include <mma.h>
#include <math.h>

using namespace nvcuda;

#define BATCH 2
#define SEQ   2048
#define EMB   1024
#define NH    32
#define KSEL  8
#define HD    128
#define NTOK  (BATCH*SEQ)      // 4096
#define HDALL (NH*HD)          // 4096
#define KD    (KSEL*HD)        // 1024

// ---------------- scratch (device globals: no runtime alloc allowed) ----------------
__device__ float g_q[(size_t)BATCH*KSEL*SEQ*HD];   // 16MB  [B*K, S, D]
__device__ float g_k[(size_t)BATCH*KSEL*SEQ*HD];
__device__ float g_v[(size_t)BATCH*KSEL*SEQ*HD];
__device__ float g_attn[(size_t)NTOK*KD];          // 16MB  [B,S,K,D]
__device__ int   g_list[NH*NTOK];                  // per-head (tok<<3|slot)
__device__ int   g_cnt[NH];
__device__ float g_hw[NTOK*KSEL];
__device__ float g_pacc[BATCH*NH];
__device__ float g_facc[BATCH*NH];
__device__ float g_ent[1];

// ---------------- zero accumulators ----------------
__global__ void zero_stats_kernel() {
    int t = threadIdx.x;
    if (t < BATCH*NH) { g_pacc[t] = 0.f; g_facc[t] = 0.f; }
    if (t < NH) g_cnt[t] = 0;
    if (t == 0) g_ent[0] = 0.f;
}

// ---------------- router: logits, softmax, top-8, aux stats, head lists ----------------
__global__ void router_kernel(const float* __restrict__ x, const float* __restrict__ Wr) {
    __shared__ float xs[EMB];
    __shared__ float lg[NH];
    int tok = blockIdx.x;
    int tid = threadIdx.x;                // 32 threads, one per head
    const float* xr = x + (size_t)tok * EMB;
    for (int e = tid; e < EMB; e += 32) xs[e] = xr[e];
    __syncwarp();
    float acc = 0.f;
    #pragma unroll 8
    for (int e = 0; e < EMB; e++) acc += xs[e] * Wr[e*NH + tid];
    lg[tid] = acc;
    float m = acc;
    #pragma unroll
    for (int o = 16; o; o >>= 1) m = fmaxf(m, __shfl_xor_sync(0xffffffffu, m, o));
    float ex = expf(acc - m);
    float sum = ex;
    #pragma unroll
    for (int o = 16; o; o >>= 1) sum += __shfl_xor_sync(0xffffffffu, sum, o);
    float p = ex / sum;
    int b = tok / SEQ;
    atomicAdd(&g_pacc[b*NH + tid], p);
    float term = p * logf(p + 1e-8f);
    float esum = term;
    #pragma unroll
    for (int o = 16; o; o >>= 1) esum += __shfl_xor_sync(0xffffffffu, esum, o);
    if (tid == 0) atomicAdd(&g_ent[0], -esum);
    __syncwarp();
    if (tid == 0) {
        float tl[KSEL]; int ti[KSEL];
        unsigned mask = 0;
        for (int k = 0; k < KSEL; k++) {
            float best = -1e30f; int bi = 0;
            for (int h = 0; h < NH; h++)
                if (!((mask >> h) & 1u) && lg[h] > best) { best = lg[h]; bi = h; }
            mask |= 1u << bi; tl[k] = best; ti[k] = bi;
        }
        float ws = 0.f, w[KSEL];
        for (int k = 0; k < KSEL; k++) { w[k] = expf(tl[k] - tl[0]); ws += w[k]; }
        for (int k = 0; k < KSEL; k++) {
            g_hw[tok*KSEL + k] = w[k] / ws;
            int h = ti[k];
            int pos = atomicAdd(&g_cnt[h], 1);
            g_list[h*NTOK + pos] = (tok << 3) | k;
        }
        atomicAdd(&g_facc[b*NH + ti[0]], 1.0f);
    }
}

// ---------------- GEMM common ----------------
#define BM 128
#define BN 128
#define BKt 32
#define LDA 36      // 144B rows, 16B-aligned
#define LDB 132
#define LDC 132

#define CPA16(dst, src) asm volatile("cp.async.cg.shared.global [%0], [%1], 16;\n" \
        :: "r"(dst), "l"(src))
#define CPA_COMMIT() asm volatile("cp.async.commit_group;\n")
#define CPA_WAIT1()  asm volatile("cp.async.wait_group 1;\n")
#define CPA_WAIT0()  asm volatile("cp.async.wait_group 0;\n")

// ---------------- grouped TF32 projection GEMM ----------------
// For head h: C[rows,128] = x[gathered rows, 0:1024] @ W[:, h*128:(h+1)*128]
// dst layout [B*KSEL, SEQ, HD]; row -> ((b*KSEL+j)*SEQ + s)
__global__ void __launch_bounds__(256) moh_proj_kernel(
    const float* __restrict__ x, const float* __restrict__ W, float* __restrict__ dst)
{
    int h = blockIdx.y;
    int cnt = g_cnt[h];
    int m0 = blockIdx.x * BM;
    if (m0 >= cnt) return;
    int rows = min(BM, cnt - m0);

    extern __shared__ float sm[];
    float* As[2] = { sm, sm + BM*LDA };
    float* Bs[2] = { sm + 2*BM*LDA, sm + 2*BM*LDA + BKt*LDB };
    float* Csm   = sm;                       // reused for epilogue
    __shared__ int s_pk[BM];

    int tid = threadIdx.x;
    if (tid < BM) {
        int r = tid < rows ? tid : rows - 1;
        s_pk[tid] = g_list[h*NTOK + m0 + r];
    }
    __syncthreads();

    int wid = tid >> 5;
    int wm = wid >> 2, wn = wid & 3;
    int col0 = h * HD;

    // loader mapping
    int ar[4], ac[4], br[4], bc[4];
    const float* abase[4];
    #pragma unroll
    for (int i = 0; i < 4; i++) {
        int idx = tid + i*256;
        ar[i] = idx >> 3;  ac[i] = (idx & 7) * 4;
        br[i] = idx >> 5;  bc[i] = (idx & 31) * 4;
        abase[i] = x + (size_t)(s_pk[ar[i]] >> 3) * EMB + ac[i];
    }

    wmma::fragment<wmma::accumulator, 16, 16, 8, float> cfr[4][2];
    #pragma unroll
    for (int i = 0; i < 4; i++)
        #pragma unroll
        for (int j = 0; j < 2; j++) wmma::fill_fragment(cfr[i][j], 0.0f);

    const int ntiles = EMB / BKt;      // 32
    #pragma unroll
    for (int i = 0; i < 4; i++) {
        unsigned da = (unsigned)__cvta_generic_to_shared(As[0] + ar[i]*LDA + ac[i]);
        CPA16(da, abase[i]);
        unsigned db = (unsigned)__cvta_generic_to_shared(Bs[0] + br[i]*LDB + bc[i]);
        CPA16(db, W + (size_t)br[i] * HDALL + col0 + bc[i]);
    }
    CPA_COMMIT();

    for (int t = 0; t < ntiles; t++) {
        int buf = t & 1;
        if (t + 1 < ntiles) {
            int nb = (t + 1) & 1;
            int k0 = (t + 1) * BKt;
            #pragma unroll
            for (int i = 0; i < 4; i++) {
                unsigned da = (unsigned)__cvta_generic_to_shared(As[nb] + ar[i]*LDA + ac[i]);
                CPA16(da, abase[i] + k0);
                unsigned db = (unsigned)__cvta_generic_to_shared(Bs[nb] + br[i]*LDB + bc[i]);
                CPA16(db, W + (size_t)(k0 + br[i]) * HDALL + col0 + bc[i]);
            }
            CPA_COMMIT();
            CPA_WAIT1();
        } else {
            CPA_WAIT0();
        }
        __syncthreads();

        float* Ab = As[buf];
        float* Bb = Bs[buf];
        #pragma unroll
        for (int kk = 0; kk < BKt/8; kk++) {
            wmma::fragment<wmma::matrix_a, 16, 16, 8, wmma::precision::tf32, wmma::row_major> af[4];
            wmma::fragment<wmma::matrix_b, 16, 16, 8, wmma::precision::tf32, wmma::row_major> bf[2];
            #pragma unroll
            for (int i = 0; i < 4; i++) {
                wmma::load_matrix_sync(af[i], Ab + (wm*64 + i*16)*LDA + kk*8, LDA);
                #pragma unroll
                for (int e = 0; e < af[i].num_elements; e++)
                    af[i].x[e] = wmma::__float_to_tf32(af[i].x[e]);
            }
            #pragma unroll
            for (int j = 0; j < 2; j++) {
                wmma::load_matrix_sync(bf[j], Bb + kk*8*LDB + wn*32 + j*16, LDB);
                #pragma unroll
                for (int e = 0; e < bf[j].num_elements; e++)
                    bf[j].x[e] = wmma::__float_to_tf32(bf[j].x[e]);
            }
            #pragma unroll
            for (int i = 0; i < 4; i++)
                #pragma unroll
                for (int j = 0; j < 2; j++)
                    wmma::mma_sync(cfr[i][j], af[i], bf[j], cfr[i][j]);
        }
        __syncthreads();
    }

    // epilogue: stage C in smem, scatter rows to dst
    #pragma unroll
    for (int i = 0; i < 4; i++)
        #pragma unroll
        for (int j = 0; j < 2; j++)
            wmma::store_matrix_sync(Csm + (wm*64 + i*16)*LDC + wn*32 + j*16,
                                    cfr[i][j], LDC, wmma::mem_row_major);
    __syncthreads();

    for (int i = tid; i < BM * (HD/4); i += 256) {
        int row = i >> 5;
        if (row >= rows) break;
        int c = (i & 31) * 4;
        int pk = s_pk[row];
        int tok = pk >> 3, j = pk & 7;
        int b = tok / SEQ, s = tok % SEQ;
        size_t off = (((size_t)(b*KSEL + j)) * SEQ + s) * HD + c;
        *(float4*)&dst[off] = *(float4*)&Csm[row*LDC + c];
    }
}

// ---------------- dense TF32 GEMM (for Wo) ----------------
__global__ void __launch_bounds__(256) tf32_gemm_kernel(
    const float* __restrict__ A, const float* __restrict__ Bm, float* __restrict__ C,
    int M, int N, int Kd)
{
    extern __shared__ float sm[];
    float* As[2] = { sm, sm + BM*LDA };
    float* Bs[2] = { sm + 2*BM*LDA, sm + 2*BM*LDA + BKt*LDB };

    int tid = threadIdx.x;
    int wid = tid >> 5;
    int wm = wid >> 2, wn = wid & 3;
    int row0 = blockIdx.y * BM, col0 = blockIdx.x * BN;

    int ar[4], ac[4], br[4], bc[4];
    #pragma unroll
    for (int i = 0; i < 4; i++) {
        int idx = tid + i*256;
        ar[i] = idx >> 3;  ac[i] = (idx & 7) * 4;
        br[i] = idx >> 5;  bc[i] = (idx & 31) * 4;
    }

    wmma::fragment<wmma::accumulator, 16, 16, 8, float> cfr[4][2];
    #pragma unroll
    for (int i = 0; i < 4; i++)
        #pragma unroll
        for (int j = 0; j < 2; j++) wmma::fill_fragment(cfr[i][j], 0.0f);

    int ntiles = Kd / BKt;
    #pragma unroll
    for (int i = 0; i < 4; i++) {
        unsigned da = (unsigned)__cvta_generic_to_shared(As[0] + ar[i]*LDA + ac[i]);
        CPA16(da, A + (size_t)(row0 + ar[i]) * Kd + ac[i]);
        unsigned db = (unsigned)__cvta_generic_to_shared(Bs[0] + br[i]*LDB + bc[i]);
        CPA16(db, Bm + (size_t)br[i] * N + col0 + bc[i]);
    }
    CPA_COMMIT();

    for (int t = 0; t < ntiles; t++) {
        int buf = t & 1;
        if (t + 1 < ntiles) {
            int nb = (t + 1) & 1;
            int k0 = (t + 1) * BKt;
            #pragma unroll
            for (int i = 0; i < 4; i++) {
                unsigned da = (unsigned)__cvta_generic_to_shared(As[nb] + ar[i]*LDA + ac[i]);
                CPA16(da, A + (size_t)(row0 + ar[i]) * Kd + k0 + ac[i]);
                unsigned db = (unsigned)__cvta_generic_to_shared(Bs[nb] + br[i]*LDB + bc[i]);
                CPA16(db, Bm + (size_t)(k0 + br[i]) * N + col0 + bc[i]);
            }
            CPA_COMMIT();
            CPA_WAIT1();
        } else {
            CPA_WAIT0();
        }
        __syncthreads();

        float* Ab = As[buf];
        float* Bb = Bs[buf];
        #pragma unroll
        for (int kk = 0; kk < BKt/8; kk++) {
            wmma::fragment<wmma::matrix_a, 16, 16, 8, wmma::precision::tf32, wmma::row_major> af[4];
            wmma::fragment<wmma::matrix_b, 16, 16, 8, wmma::precision::tf32, wmma::row_major> bf[2];
            #pragma unroll
            for (int i = 0; i < 4; i++) {
                wmma::load_matrix_sync(af[i], Ab + (wm*64 + i*16)*LDA + kk*8, LDA);
                #pragma unroll
                for (int e = 0; e < af[i].num_elements; e++)
                    af[i].x[e] = wmma::__float_to_tf32(af[i].x[e]);
            }
            #pragma unroll
            for (int j = 0; j < 2; j++) {
                wmma::load_matrix_sync(bf[j], Bb + kk*8*LDB + wn*32 + j*16, LDB);
                #pragma unroll
                for (int e = 0; e < bf[j].num_elements; e++)
                    bf[j].x[e] = wmma::__float_to_tf32(bf[j].x[e]);
            }
            #pragma unroll
            for (int i = 0; i < 4; i++)
                #pragma unroll
                for (int j = 0; j < 2; j++)
                    wmma::mma_sync(cfr[i][j], af[i], bf[j], cfr[i][j]);
        }
        __syncthreads();
    }

    #pragma unroll
    for (int i = 0; i < 4; i++)
        #pragma unroll
        for (int j = 0; j < 2; j++)
            wmma::store_matrix_sync(
                C + (size_t)(row0 + wm*64 + i*16) * N + col0 + wn*32 + j*16,
                cfr[i][j], N, wmma::mem_row_major);
}

// ---------------- in-place RoPE on q and k ([B*K, S, D]) ----------------
__global__ void rope_kernel(float* __restrict__ q, float* __restrict__ k) {
    int row = blockIdx.x;                 // 0 .. B*K*S-1
    int s = row % SEQ;
    int tid = threadIdx.x;                // 128: 0-63 -> q, 64-127 -> k
    float* p = (tid < 64) ? q : k;
    int d = tid & 63;
    float invf = powf(10000.0f, -(float)d / 64.0f);
    float ang = (float)s * invf;
    float c = cosf(ang), sn = sinf(ang);
    size_t off = (size_t)row * HD;
    float x1 = p[off + d];
    float x2 = p[off + d + 64];
    p[off + d]      = x1 * c - x2 * sn;
    p[off + d + 64] = x2 * c + x1 * sn;
}

// ---------------- causal flash attention (fp32) ----------------
#define FBR 64
#define FBC 32
__global__ void __launch_bounds__(256) flash_kernel(
    const float* __restrict__ Q, const float* __restrict__ Kx, const float* __restrict__ Vx,
    const float* __restrict__ HWp, float* __restrict__ Out)
{
    extern __shared__ float smf[];
    float* Qs   = smf;
    float* Ks   = Qs + 64*132;
    float* Vs   = Ks + 32*132;
    float* Ps   = Vs + 32*132;
    float* mrow = Ps + 64*33;
    float* lrow = mrow + 64;
    float* arow = lrow + 64;

    int tid = threadIdx.x;
    int bk = blockIdx.y;
    int q0 = blockIdx.x * FBR;
    const float* Qp = Q  + (size_t)bk * SEQ * HD;
    const float* Kp = Kx + (size_t)bk * SEQ * HD;
    const float* Vp = Vx + (size_t)bk * SEQ * HD;

    for (int i = tid; i < FBR * (HD/4); i += 256) {
        int r = i >> 5, cc = (i & 31) * 4;
        *(float4*)&Qs[r*132 + cc] = *(const float4*)(Qp + (size_t)(q0 + r) * HD + cc);
    }
    if (tid < FBR) { mrow[tid] = -1e30f; lrow[tid] = 0.f; }
    float Oa[4][8];
    #pragma unroll
    for (int r = 0; r < 4; r++)
        #pragma unroll
        for (int cidx = 0; cidx < 8; cidx++) Oa[r][cidx] = 0.f;
    int rg = tid >> 4, cg = tid & 15;
    __syncthreads();

    int nkt = (q0 + FBR) / FBC;
    const float scale = 0.08838834764831845f;

    for (int kt = 0; kt < nkt; kt++) {
        int kb = kt * FBC;
        for (int i = tid; i < FBC * (HD/4); i += 256) {
            int r = i >> 5, cc = (i & 31) * 4;
            *(float4*)&Ks[r*132 + cc] = *(const float4*)(Kp + (size_t)(kb + r) * HD + cc);
            *(float4*)&Vs[r*132 + cc] = *(const float4*)(Vp + (size_t)(kb + r) * HD + cc);
        }
        __syncthreads();

        float sa[4][2] = {};
        #pragma unroll 4
        for (int c4 = 0; c4 < 32; c4++) {
            float4 k0 = *(float4*)&Ks[(cg*2)   * 132 + c4*4];
            float4 k1 = *(float4*)&Ks[(cg*2+1) * 132 + c4*4];
            #pragma unroll
            for (int r = 0; r < 4; r++) {
                float4 q = *(float4*)&Qs[(rg*4 + r) * 132 + c4*4];
                sa[r][0] += q.x*k0.x + q.y*k0.y + q.z*k0.z + q.w*k0.w;
                sa[r][1] += q.x*k1.x + q.y*k1.y + q.z*k1.z + q.w*k1.w;
            }
        }
        #pragma unroll
        for (int r = 0; r < 4; r++) {
            Ps[(rg*4 + r)*33 + cg*2    ] = sa[r][0] * scale;
            Ps[(rg*4 + r)*33 + cg*2 + 1] = sa[r][1] * scale;
        }
        __syncthreads();

        if (tid < FBR) {
            int r = tid, gq = q0 + r;
            int lim = gq - kb;
            float mx = -1e30f;
            for (int cc = 0; cc < FBC; cc++)
                if (cc <= lim) mx = fmaxf(mx, Ps[r*33 + cc]);
            float mo = mrow[r];
            float mn = fmaxf(mo, mx);
            float al = __expf(mo - mn);
            float ss = 0.f;
            for (int cc = 0; cc < FBC; cc++) {
                float pv = (cc <= lim) ? __expf(Ps[r*33 + cc] - mn) : 0.f;
                Ps[r*33 + cc] = pv;
                ss += pv;
            }
            lrow[r] = lrow[r] * al + ss;
            mrow[r] = mn;
            arow[r] = al;
        }
        __syncthreads();

        float alr[4];
        #pragma unroll
        for (int r = 0; r < 4; r++) alr[r] = arow[rg*4 + r];
        #pragma unroll
        for (int r = 0; r < 4; r++)
            #pragma unroll
            for (int cidx = 0; cidx < 8; cidx++) Oa[r][cidx] *= alr[r];
        for (int jj = 0; jj < FBC; jj++) {
            float p0 = Ps[(rg*4+0)*33 + jj];
            float p1 = Ps[(rg*4+1)*33 + jj];
            float p2 = Ps[(rg*4+2)*33 + jj];
            float p3 = Ps[(rg*4+3)*33 + jj];
            float4 v0 = *(float4*)&Vs[jj*132 + cg*8];
            float4 v1 = *(float4*)&Vs[jj*132 + cg*8 + 4];
            Oa[0][0]+=p0*v0.x; Oa[0][1]+=p0*v0.y; Oa[0][2]+=p0*v0.z; Oa[0][3]+=p0*v0.w;
            Oa[0][4]+=p0*v1.x; Oa[0][5]+=p0*v1.y; Oa[0][6]+=p0*v1.z; Oa[0][7]+=p0*v1.w;
            Oa[1][0]+=p1*v0.x; Oa[1][1]+=p1*v0.y; Oa[1][2]+=p1*v0.z; Oa[1][3]+=p1*v0.w;
            Oa[1][4]+=p1*v1.x; Oa[1][5]+=p1*v1.y; Oa[1][6]+=p1*v1.z; Oa[1][7]+=p1*v1.w;
            Oa[2][0]+=p2*v0.x; Oa[2][1]+=p2*v0.y; Oa[2][2]+=p2*v0.z; Oa[2][3]+=p2*v0.w;
            Oa[2][4]+=p2*v1.x; Oa[2][5]+=p2*v1.y; Oa[2][6]+=p2*v1.z; Oa[2][7]+=p2*v1.w;
            Oa[3][0]+=p3*v0.x; Oa[3][1]+=p3*v0.y; Oa[3][2]+=p3*v0.z; Oa[3][3]+=p3*v0.w;
            Oa[3][4]+=p3*v1.x; Oa[3][5]+=p3*v1.y; Oa[3][6]+=p3*v1.z; Oa[3][7]+=p3*v1.w;
        }
        __syncthreads();
    }

    int b = bk >> 3, j = bk & 7;
    #pragma unroll
    for (int r = 0; r < 4; r++) {
        int row = rg*4 + r, gq = q0 + row;
        float w = HWp[((size_t)(b*SEQ + gq)) * KSEL + j] / lrow[row];
        float4 o0 = make_float4(Oa[r][0]*w, Oa[r][1]*w, Oa[r][2]*w, Oa[r][3]*w);
        float4 o1 = make_float4(Oa[r][4]*w, Oa[r][5]*w, Oa[r][6]*w, Oa[r][7]*w);
        size_t off = (((size_t)(b*SEQ + gq)) * KSEL + j) * HD + cg*8;
        *(float4*)&Out[off]     = o0;
        *(float4*)&Out[off + 4] = o1;
    }
}

// ---------------- aux loss + head_counts tail ----------------
__global__ void finalize_kernel(float* __restrict__ out, int out_size) {
    int base = NTOK * EMB;
    int extra = out_size - base;
    if (extra <= 0) return;
    bool has_aux = (extra == BATCH*NH + 1) || (extra == 1);
    int zend = has_aux ? out_size - 1 : out_size;
    int gtid = blockIdx.x * blockDim.x + threadIdx.x;
    for (int i = base + gtid; i < zend; i += gridDim.x * blockDim.x) out[i] = 0.f;
    if (gtid == 0 && has_aux) {
        float aux = 0.f;
        for (int b = 0; b < BATCH; b++) {
            float sb = 0.f;
            for (int h = 0; h < NH; h++)
                sb += (g_facc[b*NH + h] / (float)SEQ) * (g_pacc[b*NH + h] / (float)SEQ);
            aux += sb;
        }
        aux = (float)NH * aux / (float)BATCH - 0.01f * (g_ent[0] / (float)(BATCH*SEQ));
        out[out_size - 1] = aux;
    }
}

// ---------------- launcher ----------------
extern "C" void kernel_launch(void* const* d_in, const int* in_sizes, int n_in,
                              void* d_out, int out_size)
{
    (void)in_sizes; (void)n_in;
    const float* x  = (const float*)d_in[0];
    const float* Wq = (const float*)d_in[1];
    const float* Wk = (const float*)d_in[2];
    const float* Wv = (const float*)d_in[3];
    const float* Wr = (const float*)d_in[4];
    const float* Wo = (const float*)d_in[5];
    float* out = (float*)d_out;

    float *p_q, *p_k, *p_v, *p_attn, *p_hw;
    cudaGetSymbolAddress((void**)&p_q,    g_q);
    cudaGetSymbolAddress((void**)&p_k,    g_k);
    cudaGetSymbolAddress((void**)&p_v,    g_v);
    cudaGetSymbolAddress((void**)&p_attn, g_attn);
    cudaGetSymbolAddress((void**)&p_hw,   g_hw);

    size_t gemm_smem = (size_t)(2*BM*LDA + 2*BKt*LDB) * sizeof(float);   // 70656 B
    cudaFuncSetAttribute(moh_proj_kernel, cudaFuncAttributeMaxDynamicSharedMemorySize,
                         (int)gemm_smem);
    cudaFuncSetAttribute(tf32_gemm_kernel, cudaFuncAttributeMaxDynamicSharedMemorySize,
                         (int)gemm_smem);
    size_t flash_smem = (size_t)(64*132 + 32*132 + 32*132 + 64*33 + 3*64) * sizeof(float);
    cudaFuncSetAttribute(flash_kernel, cudaFuncAttributeMaxDynamicSharedMemorySize,
                         (int)flash_smem);

    zero_stats_kernel<<<1, 128>>>();
    router_kernel<<<NTOK, 32>>>(x, Wr);

    dim3 gproj(NTOK/BM, NH);           // (32, 32), most tiles exit early
    moh_proj_kernel<<<gproj, 256, gemm_smem>>>(x, Wq, p_q);
    moh_proj_kernel<<<gproj, 256, gemm_smem>>>(x, Wk, p_k);
    moh_proj_kernel<<<gproj, 256, gemm_smem>>>(x, Wv, p_v);

    rope_kernel<<<BATCH*KSEL*SEQ, 128>>>(p_q, p_k);

    dim3 gflash(SEQ/FBR, BATCH*KSEL);  // (32, 16)
    flash_kernel<<<gflash, 256, flash_smem>>>(p_q, p_k, p_v, p_hw, p_attn);

    dim3 gout(EMB/BN, NTOK/BM);        // (8, 32)
    tf32_gemm_kernel<<<gout, 256, gemm_smem>>>(p_attn, Wo, out, NTOK, EMB, EMB);

    finalize_kernel<<<32, 256>>>(out, out_size);
}

// round 8
// speedup vs baseline: 3.4059x; 1.6129x over previous
#include <cuda_runtime.h>
#include <mma.h>
#include <math.h>

using namespace nvcuda;

#define BATCH 2
#define SEQ   2048
#define EMB   1024
#define NH    32
#define KSEL  8
#define HD    128
#define NTOK  (BATCH*SEQ)      // 4096
#define HDALL (NH*HD)          // 4096
#define KD    (KSEL*HD)        // 1024

// ---------------- scratch ----------------
__device__ float g_q[(size_t)BATCH*KSEL*SEQ*HD];   // [B*K, S, D]
__device__ float g_k[(size_t)BATCH*KSEL*SEQ*HD];
__device__ float g_v[(size_t)BATCH*KSEL*SEQ*HD];
__device__ float g_attn[(size_t)NTOK*KD];          // [B,S,K,D]
__device__ int   g_list[NH*NTOK];
__device__ int   g_cnt[NH];
__device__ float g_hw[NTOK*KSEL];
__device__ float g_pacc[BATCH*NH];
__device__ float g_facc[BATCH*NH];
__device__ float g_ent[1];

__global__ void zero_stats_kernel() {
    int t = threadIdx.x;
    if (t < BATCH*NH) { g_pacc[t] = 0.f; g_facc[t] = 0.f; }
    if (t < NH) g_cnt[t] = 0;
    if (t == 0) g_ent[0] = 0.f;
}

// ---------------- router ----------------
__global__ void router_kernel(const float* __restrict__ x, const float* __restrict__ Wr) {
    __shared__ float xs[EMB];
    __shared__ float lg[NH];
    int tok = blockIdx.x;
    int tid = threadIdx.x;
    const float* xr = x + (size_t)tok * EMB;
    for (int e = tid; e < EMB; e += 32) xs[e] = xr[e];
    __syncwarp();
    float acc = 0.f;
    #pragma unroll 8
    for (int e = 0; e < EMB; e++) acc += xs[e] * Wr[e*NH + tid];
    lg[tid] = acc;
    float m = acc;
    #pragma unroll
    for (int o = 16; o; o >>= 1) m = fmaxf(m, __shfl_xor_sync(0xffffffffu, m, o));
    float ex = expf(acc - m);
    float sum = ex;
    #pragma unroll
    for (int o = 16; o; o >>= 1) sum += __shfl_xor_sync(0xffffffffu, sum, o);
    float p = ex / sum;
    int b = tok / SEQ;
    atomicAdd(&g_pacc[b*NH + tid], p);
    float term = p * logf(p + 1e-8f);
    float esum = term;
    #pragma unroll
    for (int o = 16; o; o >>= 1) esum += __shfl_xor_sync(0xffffffffu, esum, o);
    if (tid == 0) atomicAdd(&g_ent[0], -esum);
    __syncwarp();
    if (tid == 0) {
        float tl[KSEL]; int ti[KSEL];
        unsigned mask = 0;
        for (int k = 0; k < KSEL; k++) {
            float best = -1e30f; int bi = 0;
            for (int h = 0; h < NH; h++)
                if (!((mask >> h) & 1u) && lg[h] > best) { best = lg[h]; bi = h; }
            mask |= 1u << bi; tl[k] = best; ti[k] = bi;
        }
        float ws = 0.f, w[KSEL];
        for (int k = 0; k < KSEL; k++) { w[k] = expf(tl[k] - tl[0]); ws += w[k]; }
        for (int k = 0; k < KSEL; k++) {
            g_hw[tok*KSEL + k] = w[k] / ws;
            int h = ti[k];
            int pos = atomicAdd(&g_cnt[h], 1);
            g_list[h*NTOK + pos] = (tok << 3) | k;
        }
        atomicAdd(&g_facc[b*NH + ti[0]], 1.0f);
    }
}

// ---------------- GEMM common ----------------
#define BM 128
#define BN 128
#define BKt 32
#define LDA 36
#define LDB 132
#define LDC 132

#define CPA16(dst, src) asm volatile("cp.async.cg.shared.global [%0], [%1], 16;\n" \
        :: "r"(dst), "l"(src))
#define CPA_COMMIT() asm volatile("cp.async.commit_group;\n")
#define CPA_WAIT1()  asm volatile("cp.async.wait_group 1;\n")
#define CPA_WAIT0()  asm volatile("cp.async.wait_group 0;\n")

// ---------------- grouped TF32 projection GEMM (q,k,v fused via blockIdx.z) ------
__global__ void __launch_bounds__(256) moh_proj_kernel(
    const float* __restrict__ x,
    const float* __restrict__ Wq, const float* __restrict__ Wk, const float* __restrict__ Wv,
    float* __restrict__ dq, float* __restrict__ dk, float* __restrict__ dv)
{
    int h = blockIdx.y;
    int cnt = g_cnt[h];
    int m0 = blockIdx.x * BM;
    if (m0 >= cnt) return;
    int rows = min(BM, cnt - m0);
    int z = blockIdx.z;
    const float* W = (z == 0) ? Wq : (z == 1) ? Wk : Wv;
    float* dst     = (z == 0) ? dq : (z == 1) ? dk : dv;

    extern __shared__ float sm[];
    float* As[2] = { sm, sm + BM*LDA };
    float* Bs[2] = { sm + 2*BM*LDA, sm + 2*BM*LDA + BKt*LDB };
    float* Csm   = sm;
    __shared__ int s_pk[BM];

    int tid = threadIdx.x;
    if (tid < BM) {
        int r = tid < rows ? tid : rows - 1;
        s_pk[tid] = g_list[h*NTOK + m0 + r];
    }
    __syncthreads();

    int wid = tid >> 5;
    int wm = wid >> 2, wn = wid & 3;
    int col0 = h * HD;

    int ar[4], ac[4], br[4], bc[4];
    const float* abase[4];
    #pragma unroll
    for (int i = 0; i < 4; i++) {
        int idx = tid + i*256;
        ar[i] = idx >> 3;  ac[i] = (idx & 7) * 4;
        br[i] = idx >> 5;  bc[i] = (idx & 31) * 4;
        abase[i] = x + (size_t)(s_pk[ar[i]] >> 3) * EMB + ac[i];
    }

    wmma::fragment<wmma::accumulator, 16, 16, 8, float> cfr[4][2];
    #pragma unroll
    for (int i = 0; i < 4; i++)
        #pragma unroll
        for (int j = 0; j < 2; j++) wmma::fill_fragment(cfr[i][j], 0.0f);

    const int ntiles = EMB / BKt;
    #pragma unroll
    for (int i = 0; i < 4; i++) {
        unsigned da = (unsigned)__cvta_generic_to_shared(As[0] + ar[i]*LDA + ac[i]);
        CPA16(da, abase[i]);
        unsigned db = (unsigned)__cvta_generic_to_shared(Bs[0] + br[i]*LDB + bc[i]);
        CPA16(db, W + (size_t)br[i] * HDALL + col0 + bc[i]);
    }
    CPA_COMMIT();

    for (int t = 0; t < ntiles; t++) {
        int buf = t & 1;
        if (t + 1 < ntiles) {
            int nb = (t + 1) & 1;
            int k0 = (t + 1) * BKt;
            #pragma unroll
            for (int i = 0; i < 4; i++) {
                unsigned da = (unsigned)__cvta_generic_to_shared(As[nb] + ar[i]*LDA + ac[i]);
                CPA16(da, abase[i] + k0);
                unsigned db = (unsigned)__cvta_generic_to_shared(Bs[nb] + br[i]*LDB + bc[i]);
                CPA16(db, W + (size_t)(k0 + br[i]) * HDALL + col0 + bc[i]);
            }
            CPA_COMMIT();
            CPA_WAIT1();
        } else {
            CPA_WAIT0();
        }
        __syncthreads();

        float* Ab = As[buf];
        float* Bb = Bs[buf];
        #pragma unroll
        for (int kk = 0; kk < BKt/8; kk++) {
            wmma::fragment<wmma::matrix_a, 16, 16, 8, wmma::precision::tf32, wmma::row_major> af[4];
            wmma::fragment<wmma::matrix_b, 16, 16, 8, wmma::precision::tf32, wmma::row_major> bf[2];
            #pragma unroll
            for (int i = 0; i < 4; i++) {
                wmma::load_matrix_sync(af[i], Ab + (wm*64 + i*16)*LDA + kk*8, LDA);
                #pragma unroll
                for (int e = 0; e < af[i].num_elements; e++)
                    af[i].x[e] = wmma::__float_to_tf32(af[i].x[e]);
            }
            #pragma unroll
            for (int j = 0; j < 2; j++) {
                wmma::load_matrix_sync(bf[j], Bb + kk*8*LDB + wn*32 + j*16, LDB);
                #pragma unroll
                for (int e = 0; e < bf[j].num_elements; e++)
                    bf[j].x[e] = wmma::__float_to_tf32(bf[j].x[e]);
            }
            #pragma unroll
            for (int i = 0; i < 4; i++)
                #pragma unroll
                for (int j = 0; j < 2; j++)
                    wmma::mma_sync(cfr[i][j], af[i], bf[j], cfr[i][j]);
        }
        __syncthreads();
    }

    #pragma unroll
    for (int i = 0; i < 4; i++)
        #pragma unroll
        for (int j = 0; j < 2; j++)
            wmma::store_matrix_sync(Csm + (wm*64 + i*16)*LDC + wn*32 + j*16,
                                    cfr[i][j], LDC, wmma::mem_row_major);
    __syncthreads();

    for (int i = tid; i < BM * (HD/4); i += 256) {
        int row = i >> 5;
        if (row >= rows) break;
        int c = (i & 31) * 4;
        int pk = s_pk[row];
        int tok = pk >> 3, j = pk & 7;
        int b = tok / SEQ, s = tok % SEQ;
        size_t off = (((size_t)(b*KSEL + j)) * SEQ + s) * HD + c;
        *(float4*)&dst[off] = *(float4*)&Csm[row*LDC + c];
    }
}

// ---------------- dense TF32 GEMM (Wo) ----------------
__global__ void __launch_bounds__(256) tf32_gemm_kernel(
    const float* __restrict__ A, const float* __restrict__ Bm, float* __restrict__ C,
    int M, int N, int Kd)
{
    extern __shared__ float sm[];
    float* As[2] = { sm, sm + BM*LDA };
    float* Bs[2] = { sm + 2*BM*LDA, sm + 2*BM*LDA + BKt*LDB };

    int tid = threadIdx.x;
    int wid = tid >> 5;
    int wm = wid >> 2, wn = wid & 3;
    int row0 = blockIdx.y * BM, col0 = blockIdx.x * BN;

    int ar[4], ac[4], br[4], bc[4];
    #pragma unroll
    for (int i = 0; i < 4; i++) {
        int idx = tid + i*256;
        ar[i] = idx >> 3;  ac[i] = (idx & 7) * 4;
        br[i] = idx >> 5;  bc[i] = (idx & 31) * 4;
    }

    wmma::fragment<wmma::accumulator, 16, 16, 8, float> cfr[4][2];
    #pragma unroll
    for (int i = 0; i < 4; i++)
        #pragma unroll
        for (int j = 0; j < 2; j++) wmma::fill_fragment(cfr[i][j], 0.0f);

    int ntiles = Kd / BKt;
    #pragma unroll
    for (int i = 0; i < 4; i++) {
        unsigned da = (unsigned)__cvta_generic_to_shared(As[0] + ar[i]*LDA + ac[i]);
        CPA16(da, A + (size_t)(row0 + ar[i]) * Kd + ac[i]);
        unsigned db = (unsigned)__cvta_generic_to_shared(Bs[0] + br[i]*LDB + bc[i]);
        CPA16(db, Bm + (size_t)br[i] * N + col0 + bc[i]);
    }
    CPA_COMMIT();

    for (int t = 0; t < ntiles; t++) {
        int buf = t & 1;
        if (t + 1 < ntiles) {
            int nb = (t + 1) & 1;
            int k0 = (t + 1) * BKt;
            #pragma unroll
            for (int i = 0; i < 4; i++) {
                unsigned da = (unsigned)__cvta_generic_to_shared(As[nb] + ar[i]*LDA + ac[i]);
                CPA16(da, A + (size_t)(row0 + ar[i]) * Kd + k0 + ac[i]);
                unsigned db = (unsigned)__cvta_generic_to_shared(Bs[nb] + br[i]*LDB + bc[i]);
                CPA16(db, Bm + (size_t)(k0 + br[i]) * N + col0 + bc[i]);
            }
            CPA_COMMIT();
            CPA_WAIT1();
        } else {
            CPA_WAIT0();
        }
        __syncthreads();

        float* Ab = As[buf];
        float* Bb = Bs[buf];
        #pragma unroll
        for (int kk = 0; kk < BKt/8; kk++) {
            wmma::fragment<wmma::matrix_a, 16, 16, 8, wmma::precision::tf32, wmma::row_major> af[4];
            wmma::fragment<wmma::matrix_b, 16, 16, 8, wmma::precision::tf32, wmma::row_major> bf[2];
            #pragma unroll
            for (int i = 0; i < 4; i++) {
                wmma::load_matrix_sync(af[i], Ab + (wm*64 + i*16)*LDA + kk*8, LDA);
                #pragma unroll
                for (int e = 0; e < af[i].num_elements; e++)
                    af[i].x[e] = wmma::__float_to_tf32(af[i].x[e]);
            }
            #pragma unroll
            for (int j = 0; j < 2; j++) {
                wmma::load_matrix_sync(bf[j], Bb + kk*8*LDB + wn*32 + j*16, LDB);
                #pragma unroll
                for (int e = 0; e < bf[j].num_elements; e++)
                    bf[j].x[e] = wmma::__float_to_tf32(bf[j].x[e]);
            }
            #pragma unroll
            for (int i = 0; i < 4; i++)
                #pragma unroll
                for (int j = 0; j < 2; j++)
                    wmma::mma_sync(cfr[i][j], af[i], bf[j], cfr[i][j]);
        }
        __syncthreads();
    }

    #pragma unroll
    for (int i = 0; i < 4; i++)
        #pragma unroll
        for (int j = 0; j < 2; j++)
            wmma::store_matrix_sync(
                C + (size_t)(row0 + wm*64 + i*16) * N + col0 + wn*32 + j*16,
                cfr[i][j], N, wmma::mem_row_major);
}

// ---------------- in-place RoPE ----------------
__global__ void rope_kernel(float* __restrict__ q, float* __restrict__ k) {
    int row = blockIdx.x;
    int s = row % SEQ;
    int tid = threadIdx.x;
    float* p = (tid < 64) ? q : k;
    int d = tid & 63;
    float invf = powf(10000.0f, -(float)d / 64.0f);
    float ang = (float)s * invf;
    float c = cosf(ang), sn = sinf(ang);
    size_t off = (size_t)row * HD;
    float x1 = p[off + d];
    float x2 = p[off + d + 64];
    p[off + d]      = x1 * c - x2 * sn;
    p[off + d + 64] = x2 * c + x1 * sn;
}

// ---------------- TF32 tensor-core causal flash attention ----------------
// Br=64, Bc=32, D=128, 8 warps, mma.m16n8k8 tf32
#define LQ 132
#define LK 132
#define LV 136
#define LP 36

__device__ __forceinline__ unsigned f2tf(float f) {
    unsigned u;
    asm("cvt.rna.tf32.f32 %0, %1;\n" : "=r"(u) : "f"(f));
    return u;
}
#define MMA_TF32(c0,c1,c2,c3,a0,a1,a2,a3,b0,b1) \
    asm volatile("mma.sync.aligned.m16n8k8.row.col.f32.tf32.tf32.f32 " \
        "{%0,%1,%2,%3}, {%4,%5,%6,%7}, {%8,%9}, {%0,%1,%2,%3};\n" \
        : "+f"(c0), "+f"(c1), "+f"(c2), "+f"(c3) \
        : "r"(a0), "r"(a1), "r"(a2), "r"(a3), "r"(b0), "r"(b1))

__global__ void __launch_bounds__(256) flash_tc_kernel(
    const float* __restrict__ Q, const float* __restrict__ Kx, const float* __restrict__ Vx,
    const float* __restrict__ HWp, float* __restrict__ Out)
{
    extern __shared__ float smf[];
    float* Qs   = smf;                 // [64][LQ]
    float* Ks   = Qs + 64*LQ;          // [32][LK]
    float* Vs   = Ks + 32*LK;          // [32][LV]
    float* Ps   = Vs + 32*LV;          // [64][LP]
    float* mrow = Ps + 64*LP;          // [64]
    float* lrow = mrow + 64;
    float* arow = lrow + 64;

    int tid = threadIdx.x;
    int wid = tid >> 5, lane = tid & 31;
    int lr = lane >> 2, lc = lane & 3;          // quad row / col
    int rw = wid >> 1, ch = wid & 1;            // warp row tile / col half
    int bk = blockIdx.y;
    int q0 = blockIdx.x * 64;

    const float* Qp = Q  + (size_t)bk * SEQ * HD;
    const float* Kp = Kx + (size_t)bk * SEQ * HD;
    const float* Vp = Vx + (size_t)bk * SEQ * HD;

    for (int i = tid; i < 64 * (HD/4); i += 256) {
        int r = i >> 5, cc = (i & 31) * 4;
        *(float4*)&Qs[r*LQ + cc] = *(const float4*)(Qp + (size_t)(q0 + r) * HD + cc);
    }
    if (tid < 64) { mrow[tid] = -1e30f; lrow[tid] = 0.f; }

    float o[8][4];
    #pragma unroll
    for (int j = 0; j < 8; j++)
        #pragma unroll
        for (int e = 0; e < 4; e++) o[j][e] = 0.f;

    __syncthreads();

    const int nkt = (q0 + 64) / 32;
    const float scale = 0.08838834764831845f;

    for (int kt = 0; kt < nkt; kt++) {
        int kb = kt * 32;
        // load K,V tiles
        for (int i = tid; i < 32 * (HD/4); i += 256) {
            int r = i >> 5, cc = (i & 31) * 4;
            *(float4*)&Ks[r*LK + cc] = *(const float4*)(Kp + (size_t)(kb + r) * HD + cc);
            *(float4*)&Vs[r*LV + cc] = *(const float4*)(Vp + (size_t)(kb + r) * HD + cc);
        }
        __syncthreads();

        // ---- S = Q K^T : each warp two 16x8 tiles ----
        float s0[4] = {0,0,0,0}, s1[4] = {0,0,0,0};
        {
            int arw = rw*16 + lr;
            int nc0 = ch*16 + lr;        // B col for tile j=0
            int nc1 = ch*16 + 8 + lr;    // tile j=1
            #pragma unroll
            for (int kk = 0; kk < 16; kk++) {
                int k0 = kk*8;
                unsigned a0 = f2tf(Qs[arw*LQ + k0 + lc]);
                unsigned a1 = f2tf(Qs[(arw+8)*LQ + k0 + lc]);
                unsigned a2 = f2tf(Qs[arw*LQ + k0 + lc + 4]);
                unsigned a3 = f2tf(Qs[(arw+8)*LQ + k0 + lc + 4]);
                unsigned b0 = f2tf(Ks[nc0*LK + k0 + lc]);
                unsigned b1 = f2tf(Ks[nc0*LK + k0 + lc + 4]);
                MMA_TF32(s0[0],s0[1],s0[2],s0[3], a0,a1,a2,a3, b0,b1);
                unsigned c0 = f2tf(Ks[nc1*LK + k0 + lc]);
                unsigned c1 = f2tf(Ks[nc1*LK + k0 + lc + 4]);
                MMA_TF32(s1[0],s1[1],s1[2],s1[3], a0,a1,a2,a3, c0,c1);
            }
            int r0 = rw*16 + lr;
            int cb0 = ch*16 + 2*lc;
            int cb1 = ch*16 + 8 + 2*lc;
            Ps[r0*LP + cb0]     = s0[0]*scale;  Ps[r0*LP + cb0 + 1] = s0[1]*scale;
            Ps[(r0+8)*LP + cb0] = s0[2]*scale;  Ps[(r0+8)*LP + cb0+1] = s0[3]*scale;
            Ps[r0*LP + cb1]     = s1[0]*scale;  Ps[r0*LP + cb1 + 1] = s1[1]*scale;
            Ps[(r0+8)*LP + cb1] = s1[2]*scale;  Ps[(r0+8)*LP + cb1+1] = s1[3]*scale;
        }
        __syncthreads();

        // ---- online softmax: 4 threads per row ----
        {
            int r = tid >> 2, sub = tid & 3;
            int gq = q0 + r;
            int lim = gq - kb;                 // valid col index <= lim
            int base = sub * 8;
            float pv[8];
            float mx = -1e30f;
            #pragma unroll
            for (int i = 0; i < 8; i++) {
                float v = Ps[r*LP + base + i];
                bool ok = (base + i) <= lim;
                pv[i] = ok ? v : -1e30f;
                mx = fmaxf(mx, pv[i]);
            }
            mx = fmaxf(mx, __shfl_xor_sync(0xffffffffu, mx, 1));
            mx = fmaxf(mx, __shfl_xor_sync(0xffffffffu, mx, 2));
            float mo = mrow[r];
            float mn = fmaxf(mo, mx);
            float al = __expf(mo - mn);
            float ss = 0.f;
            #pragma unroll
            for (int i = 0; i < 8; i++) {
                float e = ((base + i) <= lim) ? __expf(pv[i] - mn) : 0.f;
                Ps[r*LP + base + i] = e;
                ss += e;
            }
            ss += __shfl_xor_sync(0xffffffffu, ss, 1);
            ss += __shfl_xor_sync(0xffffffffu, ss, 2);
            if (sub == 0) {
                lrow[r] = lrow[r] * al + ss;
                mrow[r] = mn;
                arow[r] = al;
            }
        }
        __syncthreads();

        // ---- O = O*alpha + P V ----
        {
            float a_lo = arow[rw*16 + lr];
            float a_hi = arow[rw*16 + lr + 8];
            #pragma unroll
            for (int j = 0; j < 8; j++) {
                o[j][0] *= a_lo; o[j][1] *= a_lo;
                o[j][2] *= a_hi; o[j][3] *= a_hi;
            }
            int pr = rw*16 + lr;
            #pragma unroll
            for (int kk = 0; kk < 4; kk++) {
                int k0 = kk*8;
                unsigned a0 = f2tf(Ps[pr*LP + k0 + lc]);
                unsigned a1 = f2tf(Ps[(pr+8)*LP + k0 + lc]);
                unsigned a2 = f2tf(Ps[pr*LP + k0 + lc + 4]);
                unsigned a3 = f2tf(Ps[(pr+8)*LP + k0 + lc + 4]);
                #pragma unroll
                for (int j = 0; j < 8; j++) {
                    int vc = ch*64 + j*8 + lr;
                    unsigned b0 = f2tf(Vs[(k0 + lc)*LV + vc]);
                    unsigned b1 = f2tf(Vs[(k0 + lc + 4)*LV + vc]);
                    MMA_TF32(o[j][0],o[j][1],o[j][2],o[j][3], a0,a1,a2,a3, b0,b1);
                }
            }
        }
        __syncthreads();
    }

    // ---- epilogue: weight + normalize, write [B,S,K,D] ----
    int b = bk >> 3, jslot = bk & 7;
    int r0 = rw*16 + lr;
    int gq0 = q0 + r0, gq1 = q0 + r0 + 8;
    float w_lo = HWp[((size_t)(b*SEQ + gq0)) * KSEL + jslot] / lrow[r0];
    float w_hi = HWp[((size_t)(b*SEQ + gq1)) * KSEL + jslot] / lrow[r0 + 8];
    #pragma unroll
    for (int j = 0; j < 8; j++) {
        int cb = ch*64 + j*8 + 2*lc;
        size_t off0 = (((size_t)(b*SEQ + gq0)) * KSEL + jslot) * HD + cb;
        size_t off1 = (((size_t)(b*SEQ + gq1)) * KSEL + jslot) * HD + cb;
        float2 v0 = make_float2(o[j][0]*w_lo, o[j][1]*w_lo);
        float2 v1 = make_float2(o[j][2]*w_hi, o[j][3]*w_hi);
        *(float2*)&Out[off0] = v0;
        *(float2*)&Out[off1] = v1;
    }
}

// ---------------- aux loss + head_counts tail ----------------
__global__ void finalize_kernel(float* __restrict__ out, int out_size) {
    int base = NTOK * EMB;
    int extra = out_size - base;
    if (extra <= 0) return;
    bool has_aux = (extra == BATCH*NH + 1) || (extra == 1);
    int zend = has_aux ? out_size - 1 : out_size;
    int gtid = blockIdx.x * blockDim.x + threadIdx.x;
    for (int i = base + gtid; i < zend; i += gridDim.x * blockDim.x) out[i] = 0.f;
    if (gtid == 0 && has_aux) {
        float aux = 0.f;
        for (int b = 0; b < BATCH; b++) {
            float sb = 0.f;
            for (int h = 0; h < NH; h++)
                sb += (g_facc[b*NH + h] / (float)SEQ) * (g_pacc[b*NH + h] / (float)SEQ);
            aux += sb;
        }
        aux = (float)NH * aux / (float)BATCH - 0.01f * (g_ent[0] / (float)(BATCH*SEQ));
        out[out_size - 1] = aux;
    }
}

// ---------------- launcher ----------------
extern "C" void kernel_launch(void* const* d_in, const int* in_sizes, int n_in,
                              void* d_out, int out_size)
{
    (void)in_sizes; (void)n_in;
    const float* x  = (const float*)d_in[0];
    const float* Wq = (const float*)d_in[1];
    const float* Wk = (const float*)d_in[2];
    const float* Wv = (const float*)d_in[3];
    const float* Wr = (const float*)d_in[4];
    const float* Wo = (const float*)d_in[5];
    float* out = (float*)d_out;

    float *p_q, *p_k, *p_v, *p_attn, *p_hw;
    cudaGetSymbolAddress((void**)&p_q,    g_q);
    cudaGetSymbolAddress((void**)&p_k,    g_k);
    cudaGetSymbolAddress((void**)&p_v,    g_v);
    cudaGetSymbolAddress((void**)&p_attn, g_attn);
    cudaGetSymbolAddress((void**)&p_hw,   g_hw);

    size_t gemm_smem = (size_t)(2*BM*LDA + 2*BKt*LDB) * sizeof(float);
    cudaFuncSetAttribute(moh_proj_kernel, cudaFuncAttributeMaxDynamicSharedMemorySize,
                         (int)gemm_smem);
    cudaFuncSetAttribute(tf32_gemm_kernel, cudaFuncAttributeMaxDynamicSharedMemorySize,
                         (int)gemm_smem);
    size_t flash_smem = (size_t)(64*LQ + 32*LK + 32*LV + 64*LP + 3*64) * sizeof(float);
    cudaFuncSetAttribute(flash_tc_kernel, cudaFuncAttributeMaxDynamicSharedMemorySize,
                         (int)flash_smem);

    zero_stats_kernel<<<1, 128>>>();
    router_kernel<<<NTOK, 32>>>(x, Wr);

    dim3 gproj(NTOK/BM, NH, 3);        // fused q,k,v
    moh_proj_kernel<<<gproj, 256, gemm_smem>>>(x, Wq, Wk, Wv, p_q, p_k, p_v);

    rope_kernel<<<BATCH*KSEL*SEQ, 128>>>(p_q, p_k);

    dim3 gflash(SEQ/64, BATCH*KSEL);   // (32, 16)
    flash_tc_kernel<<<gflash, 256, flash_smem>>>(p_q, p_k, p_v, p_hw, p_attn);

    dim3 gout(EMB/BN, NTOK/BM);        // (8, 32)
    tf32_gemm_kernel<<<gout, 256, gemm_smem>>>(p_attn, Wo, out, NTOK, EMB, EMB);

    finalize_kernel<<<32, 256>>>(out, out_size);
}

// round 9
// speedup vs baseline: 3.5445x; 1.0407x over previous
#include <cuda_runtime.h>
#include <mma.h>
#include <math.h>

using namespace nvcuda;

#define BATCH 2
#define SEQ   2048
#define EMB   1024
#define NH    32
#define KSEL  8
#define HD    128
#define NTOK  (BATCH*SEQ)      // 4096
#define HDALL (NH*HD)          // 4096
#define KD    (KSEL*HD)        // 1024

// ---------------- scratch ----------------
__device__ float g_q[(size_t)BATCH*KSEL*SEQ*HD];   // [B*K, S, D]
__device__ float g_k[(size_t)BATCH*KSEL*SEQ*HD];
__device__ float g_v[(size_t)BATCH*KSEL*SEQ*HD];
__device__ float g_attn[(size_t)NTOK*KD];          // [B,S,K,D]
__device__ int   g_list[NH*NTOK];
__device__ int   g_cnt[NH];
__device__ float g_hw[NTOK*KSEL];
__device__ float g_pacc[BATCH*NH];
__device__ float g_facc[BATCH*NH];
__device__ float g_ent[1];

__global__ void zero_stats_kernel() {
    int t = threadIdx.x;
    if (t < BATCH*NH) { g_pacc[t] = 0.f; g_facc[t] = 0.f; }
    if (t < NH) g_cnt[t] = 0;
    if (t == 0) g_ent[0] = 0.f;
}

// ---------------- router ----------------
__global__ void router_kernel(const float* __restrict__ x, const float* __restrict__ Wr) {
    __shared__ float xs[EMB];
    __shared__ float lg[NH];
    int tok = blockIdx.x;
    int tid = threadIdx.x;
    const float* xr = x + (size_t)tok * EMB;
    for (int e = tid; e < EMB; e += 32) xs[e] = xr[e];
    __syncwarp();
    float acc = 0.f;
    #pragma unroll 8
    for (int e = 0; e < EMB; e++) acc += xs[e] * Wr[e*NH + tid];
    lg[tid] = acc;
    float m = acc;
    #pragma unroll
    for (int o = 16; o; o >>= 1) m = fmaxf(m, __shfl_xor_sync(0xffffffffu, m, o));
    float ex = expf(acc - m);
    float sum = ex;
    #pragma unroll
    for (int o = 16; o; o >>= 1) sum += __shfl_xor_sync(0xffffffffu, sum, o);
    float p = ex / sum;
    int b = tok / SEQ;
    atomicAdd(&g_pacc[b*NH + tid], p);
    float term = p * logf(p + 1e-8f);
    float esum = term;
    #pragma unroll
    for (int o = 16; o; o >>= 1) esum += __shfl_xor_sync(0xffffffffu, esum, o);
    if (tid == 0) atomicAdd(&g_ent[0], -esum);
    __syncwarp();
    if (tid == 0) {
        float tl[KSEL]; int ti[KSEL];
        unsigned mask = 0;
        for (int k = 0; k < KSEL; k++) {
            float best = -1e30f; int bi = 0;
            for (int h = 0; h < NH; h++)
                if (!((mask >> h) & 1u) && lg[h] > best) { best = lg[h]; bi = h; }
            mask |= 1u << bi; tl[k] = best; ti[k] = bi;
        }
        float ws = 0.f, w[KSEL];
        for (int k = 0; k < KSEL; k++) { w[k] = expf(tl[k] - tl[0]); ws += w[k]; }
        for (int k = 0; k < KSEL; k++) {
            g_hw[tok*KSEL + k] = w[k] / ws;
            int h = ti[k];
            int pos = atomicAdd(&g_cnt[h], 1);
            g_list[h*NTOK + pos] = (tok << 3) | k;
        }
        atomicAdd(&g_facc[b*NH + ti[0]], 1.0f);
    }
}

// ---------------- GEMM common ----------------
#define BM 128
#define BN 128
#define BKt 32
#define LDA 36
#define LDB 132
#define LDC 132

#define CPA16(dst, src) asm volatile("cp.async.cg.shared.global [%0], [%1], 16;\n" \
        :: "r"(dst), "l"(src))
#define CPA_COMMIT() asm volatile("cp.async.commit_group;\n")
#define CPA_WAIT1()  asm volatile("cp.async.wait_group 1;\n")
#define CPA_WAIT0()  asm volatile("cp.async.wait_group 0;\n")

// ---------------- grouped TF32 projection GEMM (q,k,v fused; rope fused for q,k) --
__global__ void __launch_bounds__(256, 2) moh_proj_kernel(
    const float* __restrict__ x,
    const float* __restrict__ Wq, const float* __restrict__ Wk, const float* __restrict__ Wv,
    float* __restrict__ dq, float* __restrict__ dk, float* __restrict__ dv)
{
    int h = blockIdx.y;
    int cnt = g_cnt[h];
    int m0 = blockIdx.x * BM;
    if (m0 >= cnt) return;
    int rows = min(BM, cnt - m0);
    int z = blockIdx.z;
    const float* W = (z == 0) ? Wq : (z == 1) ? Wk : Wv;
    float* dst     = (z == 0) ? dq : (z == 1) ? dk : dv;

    extern __shared__ float sm[];
    float* As[2] = { sm, sm + BM*LDA };
    float* Bs[2] = { sm + 2*BM*LDA, sm + 2*BM*LDA + BKt*LDB };
    float* Csm   = sm;
    __shared__ int s_pk[BM];

    int tid = threadIdx.x;
    if (tid < BM) {
        int r = tid < rows ? tid : rows - 1;
        s_pk[tid] = g_list[h*NTOK + m0 + r];
    }
    __syncthreads();

    int wid = tid >> 5;
    int wm = wid >> 2, wn = wid & 3;
    int col0 = h * HD;

    int ar[4], ac[4], br[4], bc[4];
    const float* abase[4];
    #pragma unroll
    for (int i = 0; i < 4; i++) {
        int idx = tid + i*256;
        ar[i] = idx >> 3;  ac[i] = (idx & 7) * 4;
        br[i] = idx >> 5;  bc[i] = (idx & 31) * 4;
        abase[i] = x + (size_t)(s_pk[ar[i]] >> 3) * EMB + ac[i];
    }

    wmma::fragment<wmma::accumulator, 16, 16, 8, float> cfr[4][2];
    #pragma unroll
    for (int i = 0; i < 4; i++)
        #pragma unroll
        for (int j = 0; j < 2; j++) wmma::fill_fragment(cfr[i][j], 0.0f);

    const int ntiles = EMB / BKt;
    #pragma unroll
    for (int i = 0; i < 4; i++) {
        unsigned da = (unsigned)__cvta_generic_to_shared(As[0] + ar[i]*LDA + ac[i]);
        CPA16(da, abase[i]);
        unsigned db = (unsigned)__cvta_generic_to_shared(Bs[0] + br[i]*LDB + bc[i]);
        CPA16(db, W + (size_t)br[i] * HDALL + col0 + bc[i]);
    }
    CPA_COMMIT();

    for (int t = 0; t < ntiles; t++) {
        int buf = t & 1;
        if (t + 1 < ntiles) {
            int nb = (t + 1) & 1;
            int k0 = (t + 1) * BKt;
            #pragma unroll
            for (int i = 0; i < 4; i++) {
                unsigned da = (unsigned)__cvta_generic_to_shared(As[nb] + ar[i]*LDA + ac[i]);
                CPA16(da, abase[i] + k0);
                unsigned db = (unsigned)__cvta_generic_to_shared(Bs[nb] + br[i]*LDB + bc[i]);
                CPA16(db, W + (size_t)(k0 + br[i]) * HDALL + col0 + bc[i]);
            }
            CPA_COMMIT();
            CPA_WAIT1();
        } else {
            CPA_WAIT0();
        }
        __syncthreads();

        float* Ab = As[buf];
        float* Bb = Bs[buf];
        #pragma unroll
        for (int kk = 0; kk < BKt/8; kk++) {
            wmma::fragment<wmma::matrix_a, 16, 16, 8, wmma::precision::tf32, wmma::row_major> af[4];
            wmma::fragment<wmma::matrix_b, 16, 16, 8, wmma::precision::tf32, wmma::row_major> bf[2];
            #pragma unroll
            for (int i = 0; i < 4; i++) {
                wmma::load_matrix_sync(af[i], Ab + (wm*64 + i*16)*LDA + kk*8, LDA);
                #pragma unroll
                for (int e = 0; e < af[i].num_elements; e++)
                    af[i].x[e] = wmma::__float_to_tf32(af[i].x[e]);
            }
            #pragma unroll
            for (int j = 0; j < 2; j++) {
                wmma::load_matrix_sync(bf[j], Bb + kk*8*LDB + wn*32 + j*16, LDB);
                #pragma unroll
                for (int e = 0; e < bf[j].num_elements; e++)
                    bf[j].x[e] = wmma::__float_to_tf32(bf[j].x[e]);
            }
            #pragma unroll
            for (int i = 0; i < 4; i++)
                #pragma unroll
                for (int j = 0; j < 2; j++)
                    wmma::mma_sync(cfr[i][j], af[i], bf[j], cfr[i][j]);
        }
        __syncthreads();
    }

    #pragma unroll
    for (int i = 0; i < 4; i++)
        #pragma unroll
        for (int j = 0; j < 2; j++)
            wmma::store_matrix_sync(Csm + (wm*64 + i*16)*LDC + wn*32 + j*16,
                                    cfr[i][j], LDC, wmma::mem_row_major);
    __syncthreads();

    if (z < 2) {
        // rope-fused scatter: each iter handles 4 lower-half cols + their pairs
        for (int i = tid; i < BM * 16; i += 256) {
            int row = i >> 4;
            if (row >= rows) break;
            int c4 = (i & 15) * 4;         // 0..60
            int pk = s_pk[row];
            int tok = pk >> 3, j = pk & 7;
            int b = tok / SEQ, s = tok % SEQ;
            float4 lo = *(float4*)&Csm[row*LDC + c4];
            float4 hi = *(float4*)&Csm[row*LDC + c4 + 64];
            float4 olo, ohi;
            float fs = (float)s;
            {
                float cc, sn, ang;
                ang = fs * powf(10000.0f, -(float)(c4+0) / 64.0f);
                cc = cosf(ang); sn = sinf(ang);
                olo.x = lo.x*cc - hi.x*sn;  ohi.x = hi.x*cc + lo.x*sn;
                ang = fs * powf(10000.0f, -(float)(c4+1) / 64.0f);
                cc = cosf(ang); sn = sinf(ang);
                olo.y = lo.y*cc - hi.y*sn;  ohi.y = hi.y*cc + lo.y*sn;
                ang = fs * powf(10000.0f, -(float)(c4+2) / 64.0f);
                cc = cosf(ang); sn = sinf(ang);
                olo.z = lo.z*cc - hi.z*sn;  ohi.z = hi.z*cc + lo.z*sn;
                ang = fs * powf(10000.0f, -(float)(c4+3) / 64.0f);
                cc = cosf(ang); sn = sinf(ang);
                olo.w = lo.w*cc - hi.w*sn;  ohi.w = hi.w*cc + lo.w*sn;
            }
            size_t off = (((size_t)(b*KSEL + j)) * SEQ + s) * HD;
            *(float4*)&dst[off + c4]      = olo;
            *(float4*)&dst[off + c4 + 64] = ohi;
        }
    } else {
        for (int i = tid; i < BM * (HD/4); i += 256) {
            int row = i >> 5;
            if (row >= rows) break;
            int c = (i & 31) * 4;
            int pk = s_pk[row];
            int tok = pk >> 3, j = pk & 7;
            int b = tok / SEQ, s = tok % SEQ;
            size_t off = (((size_t)(b*KSEL + j)) * SEQ + s) * HD + c;
            *(float4*)&dst[off] = *(float4*)&Csm[row*LDC + c];
        }
    }
}

// ---------------- dense TF32 GEMM (Wo) ----------------
__global__ void __launch_bounds__(256, 2) tf32_gemm_kernel(
    const float* __restrict__ A, const float* __restrict__ Bm, float* __restrict__ C,
    int M, int N, int Kd)
{
    extern __shared__ float sm[];
    float* As[2] = { sm, sm + BM*LDA };
    float* Bs[2] = { sm + 2*BM*LDA, sm + 2*BM*LDA + BKt*LDB };

    int tid = threadIdx.x;
    int wid = tid >> 5;
    int wm = wid >> 2, wn = wid & 3;
    int row0 = blockIdx.y * BM, col0 = blockIdx.x * BN;

    int ar[4], ac[4], br[4], bc[4];
    #pragma unroll
    for (int i = 0; i < 4; i++) {
        int idx = tid + i*256;
        ar[i] = idx >> 3;  ac[i] = (idx & 7) * 4;
        br[i] = idx >> 5;  bc[i] = (idx & 31) * 4;
    }

    wmma::fragment<wmma::accumulator, 16, 16, 8, float> cfr[4][2];
    #pragma unroll
    for (int i = 0; i < 4; i++)
        #pragma unroll
        for (int j = 0; j < 2; j++) wmma::fill_fragment(cfr[i][j], 0.0f);

    int ntiles = Kd / BKt;
    #pragma unroll
    for (int i = 0; i < 4; i++) {
        unsigned da = (unsigned)__cvta_generic_to_shared(As[0] + ar[i]*LDA + ac[i]);
        CPA16(da, A + (size_t)(row0 + ar[i]) * Kd + ac[i]);
        unsigned db = (unsigned)__cvta_generic_to_shared(Bs[0] + br[i]*LDB + bc[i]);
        CPA16(db, Bm + (size_t)br[i] * N + col0 + bc[i]);
    }
    CPA_COMMIT();

    for (int t = 0; t < ntiles; t++) {
        int buf = t & 1;
        if (t + 1 < ntiles) {
            int nb = (t + 1) & 1;
            int k0 = (t + 1) * BKt;
            #pragma unroll
            for (int i = 0; i < 4; i++) {
                unsigned da = (unsigned)__cvta_generic_to_shared(As[nb] + ar[i]*LDA + ac[i]);
                CPA16(da, A + (size_t)(row0 + ar[i]) * Kd + k0 + ac[i]);
                unsigned db = (unsigned)__cvta_generic_to_shared(Bs[nb] + br[i]*LDB + bc[i]);
                CPA16(db, Bm + (size_t)(k0 + br[i]) * N + col0 + bc[i]);
            }
            CPA_COMMIT();
            CPA_WAIT1();
        } else {
            CPA_WAIT0();
        }
        __syncthreads();

        float* Ab = As[buf];
        float* Bb = Bs[buf];
        #pragma unroll
        for (int kk = 0; kk < BKt/8; kk++) {
            wmma::fragment<wmma::matrix_a, 16, 16, 8, wmma::precision::tf32, wmma::row_major> af[4];
            wmma::fragment<wmma::matrix_b, 16, 16, 8, wmma::precision::tf32, wmma::row_major> bf[2];
            #pragma unroll
            for (int i = 0; i < 4; i++) {
                wmma::load_matrix_sync(af[i], Ab + (wm*64 + i*16)*LDA + kk*8, LDA);
                #pragma unroll
                for (int e = 0; e < af[i].num_elements; e++)
                    af[i].x[e] = wmma::__float_to_tf32(af[i].x[e]);
            }
            #pragma unroll
            for (int j = 0; j < 2; j++) {
                wmma::load_matrix_sync(bf[j], Bb + kk*8*LDB + wn*32 + j*16, LDB);
                #pragma unroll
                for (int e = 0; e < bf[j].num_elements; e++)
                    bf[j].x[e] = wmma::__float_to_tf32(bf[j].x[e]);
            }
            #pragma unroll
            for (int i = 0; i < 4; i++)
                #pragma unroll
                for (int j = 0; j < 2; j++)
                    wmma::mma_sync(cfr[i][j], af[i], bf[j], cfr[i][j]);
        }
        __syncthreads();
    }

    #pragma unroll
    for (int i = 0; i < 4; i++)
        #pragma unroll
        for (int j = 0; j < 2; j++)
            wmma::store_matrix_sync(
                C + (size_t)(row0 + wm*64 + i*16) * N + col0 + wn*32 + j*16,
                cfr[i][j], N, wmma::mem_row_major);
}

// ---------------- TF32 tensor-core causal flash attention ----------------
#define LQ 132
#define LK 132
#define LV 136
#define LP 36

__device__ __forceinline__ unsigned f2tf(float f) {
    unsigned u;
    asm("cvt.rna.tf32.f32 %0, %1;\n" : "=r"(u) : "f"(f));
    return u;
}
#define MMA_TF32(c0,c1,c2,c3,a0,a1,a2,a3,b0,b1) \
    asm volatile("mma.sync.aligned.m16n8k8.row.col.f32.tf32.tf32.f32 " \
        "{%0,%1,%2,%3}, {%4,%5,%6,%7}, {%8,%9}, {%0,%1,%2,%3};\n" \
        : "+f"(c0), "+f"(c1), "+f"(c2), "+f"(c3) \
        : "r"(a0), "r"(a1), "r"(a2), "r"(a3), "r"(b0), "r"(b1))

__global__ void __launch_bounds__(256, 2) flash_tc_kernel(
    const float* __restrict__ Q, const float* __restrict__ Kx, const float* __restrict__ Vx,
    const float* __restrict__ HWp, float* __restrict__ Out)
{
    extern __shared__ float smf[];
    float* Qs   = smf;                 // [64][LQ]
    float* Ks   = Qs + 64*LQ;          // [32][LK]
    float* Vs   = Ks + 32*LK;          // [32][LV]
    float* Ps   = Vs + 32*LV;          // [64][LP]
    float* mrow = Ps + 64*LP;          // [64]
    float* lrow = mrow + 64;
    float* arow = lrow + 64;

    int tid = threadIdx.x;
    int wid = tid >> 5, lane = tid & 31;
    int lr = lane >> 2, lc = lane & 3;
    int rw = wid >> 1, ch = wid & 1;
    int bk = blockIdx.y;
    int q0 = blockIdx.x * 64;

    const float* Qp = Q  + (size_t)bk * SEQ * HD;
    const float* Kp = Kx + (size_t)bk * SEQ * HD;
    const float* Vp = Vx + (size_t)bk * SEQ * HD;

    for (int i = tid; i < 64 * (HD/4); i += 256) {
        int r = i >> 5, cc = (i & 31) * 4;
        *(float4*)&Qs[r*LQ + cc] = *(const float4*)(Qp + (size_t)(q0 + r) * HD + cc);
    }
    if (tid < 64) { mrow[tid] = -1e30f; lrow[tid] = 0.f; }

    float o[8][4];
    #pragma unroll
    for (int j = 0; j < 8; j++)
        #pragma unroll
        for (int e = 0; e < 4; e++) o[j][e] = 0.f;

    __syncthreads();

    const int nkt = (q0 + 64) / 32;
    const float scale = 0.08838834764831845f;

    for (int kt = 0; kt < nkt; kt++) {
        int kb = kt * 32;
        for (int i = tid; i < 32 * (HD/4); i += 256) {
            int r = i >> 5, cc = (i & 31) * 4;
            *(float4*)&Ks[r*LK + cc] = *(const float4*)(Kp + (size_t)(kb + r) * HD + cc);
            *(float4*)&Vs[r*LV + cc] = *(const float4*)(Vp + (size_t)(kb + r) * HD + cc);
        }
        __syncthreads();

        float s0[4] = {0,0,0,0}, s1[4] = {0,0,0,0};
        {
            int arw = rw*16 + lr;
            int nc0 = ch*16 + lr;
            int nc1 = ch*16 + 8 + lr;
            #pragma unroll
            for (int kk = 0; kk < 16; kk++) {
                int k0 = kk*8;
                unsigned a0 = f2tf(Qs[arw*LQ + k0 + lc]);
                unsigned a1 = f2tf(Qs[(arw+8)*LQ + k0 + lc]);
                unsigned a2 = f2tf(Qs[arw*LQ + k0 + lc + 4]);
                unsigned a3 = f2tf(Qs[(arw+8)*LQ + k0 + lc + 4]);
                unsigned b0 = f2tf(Ks[nc0*LK + k0 + lc]);
                unsigned b1 = f2tf(Ks[nc0*LK + k0 + lc + 4]);
                MMA_TF32(s0[0],s0[1],s0[2],s0[3], a0,a1,a2,a3, b0,b1);
                unsigned c0 = f2tf(Ks[nc1*LK + k0 + lc]);
                unsigned c1 = f2tf(Ks[nc1*LK + k0 + lc + 4]);
                MMA_TF32(s1[0],s1[1],s1[2],s1[3], a0,a1,a2,a3, c0,c1);
            }
            int r0 = rw*16 + lr;
            int cb0 = ch*16 + 2*lc;
            int cb1 = ch*16 + 8 + 2*lc;
            Ps[r0*LP + cb0]     = s0[0]*scale;  Ps[r0*LP + cb0 + 1] = s0[1]*scale;
            Ps[(r0+8)*LP + cb0] = s0[2]*scale;  Ps[(r0+8)*LP + cb0+1] = s0[3]*scale;
            Ps[r0*LP + cb1]     = s1[0]*scale;  Ps[r0*LP + cb1 + 1] = s1[1]*scale;
            Ps[(r0+8)*LP + cb1] = s1[2]*scale;  Ps[(r0+8)*LP + cb1+1] = s1[3]*scale;
        }
        __syncthreads();

        {
            int r = tid >> 2, sub = tid & 3;
            int gq = q0 + r;
            int lim = gq - kb;
            int base = sub * 8;
            float pv[8];
            float mx = -1e30f;
            #pragma unroll
            for (int i = 0; i < 8; i++) {
                float v = Ps[r*LP + base + i];
                bool ok = (base + i) <= lim;
                pv[i] = ok ? v : -1e30f;
                mx = fmaxf(mx, pv[i]);
            }
            mx = fmaxf(mx, __shfl_xor_sync(0xffffffffu, mx, 1));
            mx = fmaxf(mx, __shfl_xor_sync(0xffffffffu, mx, 2));
            float mo = mrow[r];
            float mn = fmaxf(mo, mx);
            float al = __expf(mo - mn);
            float ss = 0.f;
            #pragma unroll
            for (int i = 0; i < 8; i++) {
                float e = ((base + i) <= lim) ? __expf(pv[i] - mn) : 0.f;
                Ps[r*LP + base + i] = e;
                ss += e;
            }
            ss += __shfl_xor_sync(0xffffffffu, ss, 1);
            ss += __shfl_xor_sync(0xffffffffu, ss, 2);
            if (sub == 0) {
                lrow[r] = lrow[r] * al + ss;
                mrow[r] = mn;
                arow[r] = al;
            }
        }
        __syncthreads();

        {
            float a_lo = arow[rw*16 + lr];
            float a_hi = arow[rw*16 + lr + 8];
            #pragma unroll
            for (int j = 0; j < 8; j++) {
                o[j][0] *= a_lo; o[j][1] *= a_lo;
                o[j][2] *= a_hi; o[j][3] *= a_hi;
            }
            int pr = rw*16 + lr;
            #pragma unroll
            for (int kk = 0; kk < 4; kk++) {
                int k0 = kk*8;
                unsigned a0 = f2tf(Ps[pr*LP + k0 + lc]);
                unsigned a1 = f2tf(Ps[(pr+8)*LP + k0 + lc]);
                unsigned a2 = f2tf(Ps[pr*LP + k0 + lc + 4]);
                unsigned a3 = f2tf(Ps[(pr+8)*LP + k0 + lc + 4]);
                #pragma unroll
                for (int j = 0; j < 8; j++) {
                    int vc = ch*64 + j*8 + lr;
                    unsigned b0 = f2tf(Vs[(k0 + lc)*LV + vc]);
                    unsigned b1 = f2tf(Vs[(k0 + lc + 4)*LV + vc]);
                    MMA_TF32(o[j][0],o[j][1],o[j][2],o[j][3], a0,a1,a2,a3, b0,b1);
                }
            }
        }
        __syncthreads();
    }

    int b = bk >> 3, jslot = bk & 7;
    int r0 = rw*16 + lr;
    int gq0 = q0 + r0, gq1 = q0 + r0 + 8;
    float w_lo = HWp[((size_t)(b*SEQ + gq0)) * KSEL + jslot] / lrow[r0];
    float w_hi = HWp[((size_t)(b*SEQ + gq1)) * KSEL + jslot] / lrow[r0 + 8];
    #pragma unroll
    for (int j = 0; j < 8; j++) {
        int cb = ch*64 + j*8 + 2*lc;
        size_t off0 = (((size_t)(b*SEQ + gq0)) * KSEL + jslot) * HD + cb;
        size_t off1 = (((size_t)(b*SEQ + gq1)) * KSEL + jslot) * HD + cb;
        float2 v0 = make_float2(o[j][0]*w_lo, o[j][1]*w_lo);
        float2 v1 = make_float2(o[j][2]*w_hi, o[j][3]*w_hi);
        *(float2*)&Out[off0] = v0;
        *(float2*)&Out[off1] = v1;
    }
}

// ---------------- aux loss + head_counts tail ----------------
__global__ void finalize_kernel(float* __restrict__ out, int out_size) {
    int base = NTOK * EMB;
    int extra = out_size - base;
    if (extra <= 0) return;
    bool has_aux = (extra == BATCH*NH + 1) || (extra == 1);
    int zend = has_aux ? out_size - 1 : out_size;
    int gtid = blockIdx.x * blockDim.x + threadIdx.x;
    for (int i = base + gtid; i < zend; i += gridDim.x * blockDim.x) out[i] = 0.f;
    if (gtid == 0 && has_aux) {
        float aux = 0.f;
        for (int b = 0; b < BATCH; b++) {
            float sb = 0.f;
            for (int h = 0; h < NH; h++)
                sb += (g_facc[b*NH + h] / (float)SEQ) * (g_pacc[b*NH + h] / (float)SEQ);
            aux += sb;
        }
        aux = (float)NH * aux / (float)BATCH - 0.01f * (g_ent[0] / (float)(BATCH*SEQ));
        out[out_size - 1] = aux;
    }
}

// ---------------- launcher ----------------
extern "C" void kernel_launch(void* const* d_in, const int* in_sizes, int n_in,
                              void* d_out, int out_size)
{
    (void)in_sizes; (void)n_in;
    const float* x  = (const float*)d_in[0];
    const float* Wq = (const float*)d_in[1];
    const float* Wk = (const float*)d_in[2];
    const float* Wv = (const float*)d_in[3];
    const float* Wr = (const float*)d_in[4];
    const float* Wo = (const float*)d_in[5];
    float* out = (float*)d_out;

    float *p_q, *p_k, *p_v, *p_attn, *p_hw;
    cudaGetSymbolAddress((void**)&p_q,    g_q);
    cudaGetSymbolAddress((void**)&p_k,    g_k);
    cudaGetSymbolAddress((void**)&p_v,    g_v);
    cudaGetSymbolAddress((void**)&p_attn, g_attn);
    cudaGetSymbolAddress((void**)&p_hw,   g_hw);

    size_t gemm_smem = (size_t)(2*BM*LDA + 2*BKt*LDB) * sizeof(float);
    cudaFuncSetAttribute(moh_proj_kernel, cudaFuncAttributeMaxDynamicSharedMemorySize,
                         (int)gemm_smem);
    cudaFuncSetAttribute(tf32_gemm_kernel, cudaFuncAttributeMaxDynamicSharedMemorySize,
                         (int)gemm_smem);
    size_t flash_smem = (size_t)(64*LQ + 32*LK + 32*LV + 64*LP + 3*64) * sizeof(float);
    cudaFuncSetAttribute(flash_tc_kernel, cudaFuncAttributeMaxDynamicSharedMemorySize,
                         (int)flash_smem);

    zero_stats_kernel<<<1, 128>>>();
    router_kernel<<<NTOK, 32>>>(x, Wr);

    dim3 gproj(NTOK/BM, NH, 3);
    moh_proj_kernel<<<gproj, 256, gemm_smem>>>(x, Wq, Wk, Wv, p_q, p_k, p_v);

    dim3 gflash(SEQ/64, BATCH*KSEL);
    flash_tc_kernel<<<gflash, 256, flash_smem>>>(p_q, p_k, p_v, p_hw, p_attn);

    dim3 gout(EMB/BN, NTOK/BM);
    tf32_gemm_kernel<<<gout, 256, gemm_smem>>>(p_attn, Wo, out, NTOK, EMB, EMB);

    finalize_kernel<<<32, 256>>>(out, out_size);
}

// round 10
// speedup vs baseline: 3.5656x; 1.0060x over previous
#include <cuda_runtime.h>
#include <mma.h>
#include <math.h>

using namespace nvcuda;

#define BATCH 2
#define SEQ   2048
#define EMB   1024
#define NH    32
#define KSEL  8
#define HD    128
#define NTOK  (BATCH*SEQ)      // 4096
#define HDALL (NH*HD)          // 4096
#define KD    (KSEL*HD)        // 1024

// ---------------- scratch ----------------
__device__ float g_q[(size_t)BATCH*KSEL*SEQ*HD];   // [B*K, S, D]
__device__ float g_k[(size_t)BATCH*KSEL*SEQ*HD];
__device__ float g_v[(size_t)BATCH*KSEL*SEQ*HD];
__device__ float g_attn[(size_t)NTOK*KD];          // [B,S,K,D]
__device__ int   g_list[NH*NTOK];
__device__ int   g_cnt[NH];
__device__ float g_hw[NTOK*KSEL];
__device__ float g_pacc[BATCH*NH];
__device__ float g_facc[BATCH*NH];
__device__ float g_ent[1];

__global__ void zero_stats_kernel() {
    int t = threadIdx.x;
    if (t < BATCH*NH) { g_pacc[t] = 0.f; g_facc[t] = 0.f; }
    if (t < NH) g_cnt[t] = 0;
    if (t == 0) g_ent[0] = 0.f;
}

// ---------------- router ----------------
__global__ void router_kernel(const float* __restrict__ x, const float* __restrict__ Wr) {
    __shared__ float xs[EMB];
    __shared__ float lg[NH];
    int tok = blockIdx.x;
    int tid = threadIdx.x;
    const float* xr = x + (size_t)tok * EMB;
    for (int e = tid; e < EMB; e += 32) xs[e] = xr[e];
    __syncwarp();
    float acc = 0.f;
    #pragma unroll 8
    for (int e = 0; e < EMB; e++) acc += xs[e] * Wr[e*NH + tid];
    lg[tid] = acc;
    float m = acc;
    #pragma unroll
    for (int o = 16; o; o >>= 1) m = fmaxf(m, __shfl_xor_sync(0xffffffffu, m, o));
    float ex = expf(acc - m);
    float sum = ex;
    #pragma unroll
    for (int o = 16; o; o >>= 1) sum += __shfl_xor_sync(0xffffffffu, sum, o);
    float p = ex / sum;
    int b = tok / SEQ;
    atomicAdd(&g_pacc[b*NH + tid], p);
    float term = p * logf(p + 1e-8f);
    float esum = term;
    #pragma unroll
    for (int o = 16; o; o >>= 1) esum += __shfl_xor_sync(0xffffffffu, esum, o);
    if (tid == 0) atomicAdd(&g_ent[0], -esum);
    __syncwarp();
    if (tid == 0) {
        float tl[KSEL]; int ti[KSEL];
        unsigned mask = 0;
        for (int k = 0; k < KSEL; k++) {
            float best = -1e30f; int bi = 0;
            for (int h = 0; h < NH; h++)
                if (!((mask >> h) & 1u) && lg[h] > best) { best = lg[h]; bi = h; }
            mask |= 1u << bi; tl[k] = best; ti[k] = bi;
        }
        float ws = 0.f, w[KSEL];
        for (int k = 0; k < KSEL; k++) { w[k] = expf(tl[k] - tl[0]); ws += w[k]; }
        for (int k = 0; k < KSEL; k++) {
            g_hw[tok*KSEL + k] = w[k] / ws;
            int h = ti[k];
            int pos = atomicAdd(&g_cnt[h], 1);
            g_list[h*NTOK + pos] = (tok << 3) | k;
        }
        atomicAdd(&g_facc[b*NH + ti[0]], 1.0f);
    }
}

// ---------------- GEMM common ----------------
#define BM 128
#define BN 128
#define BKt 32
#define LDA 36
#define LDB 132
#define LDC 132

#define CPA16(dst, src) asm volatile("cp.async.cg.shared.global [%0], [%1], 16;\n" \
        :: "r"(dst), "l"(src))
#define CPA_COMMIT() asm volatile("cp.async.commit_group;\n")
#define CPA_WAIT1()  asm volatile("cp.async.wait_group 1;\n")
#define CPA_WAIT0()  asm volatile("cp.async.wait_group 0;\n")

// ---------------- grouped TF32 projection GEMM (q,k,v fused; rope fused for q,k) --
__global__ void __launch_bounds__(256, 2) moh_proj_kernel(
    const float* __restrict__ x,
    const float* __restrict__ Wq, const float* __restrict__ Wk, const float* __restrict__ Wv,
    float* __restrict__ dq, float* __restrict__ dk, float* __restrict__ dv)
{
    int h = blockIdx.y;
    int cnt = g_cnt[h];
    int m0 = blockIdx.x * BM;
    if (m0 >= cnt) return;
    int rows = min(BM, cnt - m0);
    int z = blockIdx.z;
    const float* W = (z == 0) ? Wq : (z == 1) ? Wk : Wv;
    float* dst     = (z == 0) ? dq : (z == 1) ? dk : dv;

    extern __shared__ float sm[];
    float* As[2] = { sm, sm + BM*LDA };
    float* Bs[2] = { sm + 2*BM*LDA, sm + 2*BM*LDA + BKt*LDB };
    float* Csm   = sm;
    __shared__ int s_pk[BM];

    int tid = threadIdx.x;
    if (tid < BM) {
        int r = tid < rows ? tid : rows - 1;
        s_pk[tid] = g_list[h*NTOK + m0 + r];
    }
    __syncthreads();

    int wid = tid >> 5;
    int wm = wid >> 2, wn = wid & 3;
    int col0 = h * HD;

    int ar[4], ac[4], br[4], bc[4];
    const float* abase[4];
    #pragma unroll
    for (int i = 0; i < 4; i++) {
        int idx = tid + i*256;
        ar[i] = idx >> 3;  ac[i] = (idx & 7) * 4;
        br[i] = idx >> 5;  bc[i] = (idx & 31) * 4;
        abase[i] = x + (size_t)(s_pk[ar[i]] >> 3) * EMB + ac[i];
    }

    wmma::fragment<wmma::accumulator, 16, 16, 8, float> cfr[4][2];
    #pragma unroll
    for (int i = 0; i < 4; i++)
        #pragma unroll
        for (int j = 0; j < 2; j++) wmma::fill_fragment(cfr[i][j], 0.0f);

    const int ntiles = EMB / BKt;
    #pragma unroll
    for (int i = 0; i < 4; i++) {
        unsigned da = (unsigned)__cvta_generic_to_shared(As[0] + ar[i]*LDA + ac[i]);
        CPA16(da, abase[i]);
        unsigned db = (unsigned)__cvta_generic_to_shared(Bs[0] + br[i]*LDB + bc[i]);
        CPA16(db, W + (size_t)br[i] * HDALL + col0 + bc[i]);
    }
    CPA_COMMIT();

    for (int t = 0; t < ntiles; t++) {
        int buf = t & 1;
        if (t + 1 < ntiles) {
            int nb = (t + 1) & 1;
            int k0 = (t + 1) * BKt;
            #pragma unroll
            for (int i = 0; i < 4; i++) {
                unsigned da = (unsigned)__cvta_generic_to_shared(As[nb] + ar[i]*LDA + ac[i]);
                CPA16(da, abase[i] + k0);
                unsigned db = (unsigned)__cvta_generic_to_shared(Bs[nb] + br[i]*LDB + bc[i]);
                CPA16(db, W + (size_t)(k0 + br[i]) * HDALL + col0 + bc[i]);
            }
            CPA_COMMIT();
            CPA_WAIT1();
        } else {
            CPA_WAIT0();
        }
        __syncthreads();

        float* Ab = As[buf];
        float* Bb = Bs[buf];
        #pragma unroll
        for (int kk = 0; kk < BKt/8; kk++) {
            wmma::fragment<wmma::matrix_a, 16, 16, 8, wmma::precision::tf32, wmma::row_major> af[4];
            wmma::fragment<wmma::matrix_b, 16, 16, 8, wmma::precision::tf32, wmma::row_major> bf[2];
            #pragma unroll
            for (int i = 0; i < 4; i++) {
                wmma::load_matrix_sync(af[i], Ab + (wm*64 + i*16)*LDA + kk*8, LDA);
                #pragma unroll
                for (int e = 0; e < af[i].num_elements; e++)
                    af[i].x[e] = wmma::__float_to_tf32(af[i].x[e]);
            }
            #pragma unroll
            for (int j = 0; j < 2; j++) {
                wmma::load_matrix_sync(bf[j], Bb + kk*8*LDB + wn*32 + j*16, LDB);
                #pragma unroll
                for (int e = 0; e < bf[j].num_elements; e++)
                    bf[j].x[e] = wmma::__float_to_tf32(bf[j].x[e]);
            }
            #pragma unroll
            for (int i = 0; i < 4; i++)
                #pragma unroll
                for (int j = 0; j < 2; j++)
                    wmma::mma_sync(cfr[i][j], af[i], bf[j], cfr[i][j]);
        }
        __syncthreads();
    }

    #pragma unroll
    for (int i = 0; i < 4; i++)
        #pragma unroll
        for (int j = 0; j < 2; j++)
            wmma::store_matrix_sync(Csm + (wm*64 + i*16)*LDC + wn*32 + j*16,
                                    cfr[i][j], LDC, wmma::mem_row_major);
    __syncthreads();

    if (z < 2) {
        for (int i = tid; i < BM * 16; i += 256) {
            int row = i >> 4;
            if (row >= rows) break;
            int c4 = (i & 15) * 4;
            int pk = s_pk[row];
            int tok = pk >> 3, j = pk & 7;
            int b = tok / SEQ, s = tok % SEQ;
            float4 lo = *(float4*)&Csm[row*LDC + c4];
            float4 hi = *(float4*)&Csm[row*LDC + c4 + 64];
            float4 olo, ohi;
            float fs = (float)s;
            {
                float cc, sn, ang;
                ang = fs * powf(10000.0f, -(float)(c4+0) / 64.0f);
                cc = cosf(ang); sn = sinf(ang);
                olo.x = lo.x*cc - hi.x*sn;  ohi.x = hi.x*cc + lo.x*sn;
                ang = fs * powf(10000.0f, -(float)(c4+1) / 64.0f);
                cc = cosf(ang); sn = sinf(ang);
                olo.y = lo.y*cc - hi.y*sn;  ohi.y = hi.y*cc + lo.y*sn;
                ang = fs * powf(10000.0f, -(float)(c4+2) / 64.0f);
                cc = cosf(ang); sn = sinf(ang);
                olo.z = lo.z*cc - hi.z*sn;  ohi.z = hi.z*cc + lo.z*sn;
                ang = fs * powf(10000.0f, -(float)(c4+3) / 64.0f);
                cc = cosf(ang); sn = sinf(ang);
                olo.w = lo.w*cc - hi.w*sn;  ohi.w = hi.w*cc + lo.w*sn;
            }
            size_t off = (((size_t)(b*KSEL + j)) * SEQ + s) * HD;
            *(float4*)&dst[off + c4]      = olo;
            *(float4*)&dst[off + c4 + 64] = ohi;
        }
    } else {
        for (int i = tid; i < BM * (HD/4); i += 256) {
            int row = i >> 5;
            if (row >= rows) break;
            int c = (i & 31) * 4;
            int pk = s_pk[row];
            int tok = pk >> 3, j = pk & 7;
            int b = tok / SEQ, s = tok % SEQ;
            size_t off = (((size_t)(b*KSEL + j)) * SEQ + s) * HD + c;
            *(float4*)&dst[off] = *(float4*)&Csm[row*LDC + c];
        }
    }
}

// ---------------- dense TF32 GEMM (Wo) ----------------
__global__ void __launch_bounds__(256, 2) tf32_gemm_kernel(
    const float* __restrict__ A, const float* __restrict__ Bm, float* __restrict__ C,
    int M, int N, int Kd)
{
    extern __shared__ float sm[];
    float* As[2] = { sm, sm + BM*LDA };
    float* Bs[2] = { sm + 2*BM*LDA, sm + 2*BM*LDA + BKt*LDB };

    int tid = threadIdx.x;
    int wid = tid >> 5;
    int wm = wid >> 2, wn = wid & 3;
    int row0 = blockIdx.y * BM, col0 = blockIdx.x * BN;

    int ar[4], ac[4], br[4], bc[4];
    #pragma unroll
    for (int i = 0; i < 4; i++) {
        int idx = tid + i*256;
        ar[i] = idx >> 3;  ac[i] = (idx & 7) * 4;
        br[i] = idx >> 5;  bc[i] = (idx & 31) * 4;
    }

    wmma::fragment<wmma::accumulator, 16, 16, 8, float> cfr[4][2];
    #pragma unroll
    for (int i = 0; i < 4; i++)
        #pragma unroll
        for (int j = 0; j < 2; j++) wmma::fill_fragment(cfr[i][j], 0.0f);

    int ntiles = Kd / BKt;
    #pragma unroll
    for (int i = 0; i < 4; i++) {
        unsigned da = (unsigned)__cvta_generic_to_shared(As[0] + ar[i]*LDA + ac[i]);
        CPA16(da, A + (size_t)(row0 + ar[i]) * Kd + ac[i]);
        unsigned db = (unsigned)__cvta_generic_to_shared(Bs[0] + br[i]*LDB + bc[i]);
        CPA16(db, Bm + (size_t)br[i] * N + col0 + bc[i]);
    }
    CPA_COMMIT();

    for (int t = 0; t < ntiles; t++) {
        int buf = t & 1;
        if (t + 1 < ntiles) {
            int nb = (t + 1) & 1;
            int k0 = (t + 1) * BKt;
            #pragma unroll
            for (int i = 0; i < 4; i++) {
                unsigned da = (unsigned)__cvta_generic_to_shared(As[nb] + ar[i]*LDA + ac[i]);
                CPA16(da, A + (size_t)(row0 + ar[i]) * Kd + k0 + ac[i]);
                unsigned db = (unsigned)__cvta_generic_to_shared(Bs[nb] + br[i]*LDB + bc[i]);
                CPA16(db, Bm + (size_t)(k0 + br[i]) * N + col0 + bc[i]);
            }
            CPA_COMMIT();
            CPA_WAIT1();
        } else {
            CPA_WAIT0();
        }
        __syncthreads();

        float* Ab = As[buf];
        float* Bb = Bs[buf];
        #pragma unroll
        for (int kk = 0; kk < BKt/8; kk++) {
            wmma::fragment<wmma::matrix_a, 16, 16, 8, wmma::precision::tf32, wmma::row_major> af[4];
            wmma::fragment<wmma::matrix_b, 16, 16, 8, wmma::precision::tf32, wmma::row_major> bf[2];
            #pragma unroll
            for (int i = 0; i < 4; i++) {
                wmma::load_matrix_sync(af[i], Ab + (wm*64 + i*16)*LDA + kk*8, LDA);
                #pragma unroll
                for (int e = 0; e < af[i].num_elements; e++)
                    af[i].x[e] = wmma::__float_to_tf32(af[i].x[e]);
            }
            #pragma unroll
            for (int j = 0; j < 2; j++) {
                wmma::load_matrix_sync(bf[j], Bb + kk*8*LDB + wn*32 + j*16, LDB);
                #pragma unroll
                for (int e = 0; e < bf[j].num_elements; e++)
                    bf[j].x[e] = wmma::__float_to_tf32(bf[j].x[e]);
            }
            #pragma unroll
            for (int i = 0; i < 4; i++)
                #pragma unroll
                for (int j = 0; j < 2; j++)
                    wmma::mma_sync(cfr[i][j], af[i], bf[j], cfr[i][j]);
        }
        __syncthreads();
    }

    #pragma unroll
    for (int i = 0; i < 4; i++)
        #pragma unroll
        for (int j = 0; j < 2; j++)
            wmma::store_matrix_sync(
                C + (size_t)(row0 + wm*64 + i*16) * N + col0 + wn*32 + j*16,
                cfr[i][j], N, wmma::mem_row_major);
}

// ---------------- TF32 tensor-core causal flash attention ----------------
// Q/K/V/P stored in smem as PRE-CONVERTED tf32 bit patterns -> inner loops are LDS+MMA only.
#define LQ 132
#define LK 132
#define LV 136
#define LP 36

__device__ __forceinline__ unsigned f2tf(float f) {
    unsigned u;
    asm("cvt.rna.tf32.f32 %0, %1;\n" : "=r"(u) : "f"(f));
    return u;
}
#define MMA_TF32(c0,c1,c2,c3,a0,a1,a2,a3,b0,b1) \
    asm volatile("mma.sync.aligned.m16n8k8.row.col.f32.tf32.tf32.f32 " \
        "{%0,%1,%2,%3}, {%4,%5,%6,%7}, {%8,%9}, {%0,%1,%2,%3};\n" \
        : "+f"(c0), "+f"(c1), "+f"(c2), "+f"(c3) \
        : "r"(a0), "r"(a1), "r"(a2), "r"(a3), "r"(b0), "r"(b1))

__global__ void __launch_bounds__(256, 2) flash_tc_kernel(
    const float* __restrict__ Q, const float* __restrict__ Kx, const float* __restrict__ Vx,
    const float* __restrict__ HWp, float* __restrict__ Out)
{
    extern __shared__ float smf[];
    unsigned* Qs = (unsigned*)smf;          // [64][LQ] tf32 bits
    unsigned* Ks = Qs + 64*LQ;              // [32][LK] tf32 bits
    unsigned* Vs = Ks + 32*LK;              // [32][LV] tf32 bits
    float*    Ps = (float*)(Vs + 32*LV);    // [64][LP] float (S), tf32 bits (P)
    unsigned* Pu = (unsigned*)Ps;
    float* mrow = Ps + 64*LP;               // [64]
    float* lrow = mrow + 64;
    float* arow = lrow + 64;

    int tid = threadIdx.x;
    int wid = tid >> 5, lane = tid & 31;
    int lr = lane >> 2, lc = lane & 3;
    int rw = wid >> 1, ch = wid & 1;
    int bk = blockIdx.y;
    int q0 = blockIdx.x * 64;

    const float* Qp = Q  + (size_t)bk * SEQ * HD;
    const float* Kp = Kx + (size_t)bk * SEQ * HD;
    const float* Vp = Vx + (size_t)bk * SEQ * HD;

    for (int i = tid; i < 64 * (HD/4); i += 256) {
        int r = i >> 5, cc = (i & 31) * 4;
        float4 qv = *(const float4*)(Qp + (size_t)(q0 + r) * HD + cc);
        uint4 qu = make_uint4(f2tf(qv.x), f2tf(qv.y), f2tf(qv.z), f2tf(qv.w));
        *(uint4*)&Qs[r*LQ + cc] = qu;
    }
    if (tid < 64) { mrow[tid] = -1e30f; lrow[tid] = 0.f; }

    float o[8][4];
    #pragma unroll
    for (int j = 0; j < 8; j++)
        #pragma unroll
        for (int e = 0; e < 4; e++) o[j][e] = 0.f;

    __syncthreads();

    const int nkt = (q0 + 64) / 32;
    const float scale = 0.08838834764831845f;

    for (int kt = 0; kt < nkt; kt++) {
        int kb = kt * 32;
        for (int i = tid; i < 32 * (HD/4); i += 256) {
            int r = i >> 5, cc = (i & 31) * 4;
            float4 kv = *(const float4*)(Kp + (size_t)(kb + r) * HD + cc);
            float4 vv = *(const float4*)(Vp + (size_t)(kb + r) * HD + cc);
            *(uint4*)&Ks[r*LK + cc] = make_uint4(f2tf(kv.x), f2tf(kv.y), f2tf(kv.z), f2tf(kv.w));
            *(uint4*)&Vs[r*LV + cc] = make_uint4(f2tf(vv.x), f2tf(vv.y), f2tf(vv.z), f2tf(vv.w));
        }
        __syncthreads();

        // ---- S = Q K^T ----
        float s0[4] = {0,0,0,0}, s1[4] = {0,0,0,0};
        {
            int arw = rw*16 + lr;
            int nc0 = ch*16 + lr;
            int nc1 = ch*16 + 8 + lr;
            #pragma unroll
            for (int kk = 0; kk < 16; kk++) {
                int k0 = kk*8;
                unsigned a0 = Qs[arw*LQ + k0 + lc];
                unsigned a1 = Qs[(arw+8)*LQ + k0 + lc];
                unsigned a2 = Qs[arw*LQ + k0 + lc + 4];
                unsigned a3 = Qs[(arw+8)*LQ + k0 + lc + 4];
                unsigned b0 = Ks[nc0*LK + k0 + lc];
                unsigned b1 = Ks[nc0*LK + k0 + lc + 4];
                MMA_TF32(s0[0],s0[1],s0[2],s0[3], a0,a1,a2,a3, b0,b1);
                unsigned c0 = Ks[nc1*LK + k0 + lc];
                unsigned c1 = Ks[nc1*LK + k0 + lc + 4];
                MMA_TF32(s1[0],s1[1],s1[2],s1[3], a0,a1,a2,a3, c0,c1);
            }
            int r0 = rw*16 + lr;
            int cb0 = ch*16 + 2*lc;
            int cb1 = ch*16 + 8 + 2*lc;
            Ps[r0*LP + cb0]     = s0[0]*scale;  Ps[r0*LP + cb0 + 1] = s0[1]*scale;
            Ps[(r0+8)*LP + cb0] = s0[2]*scale;  Ps[(r0+8)*LP + cb0+1] = s0[3]*scale;
            Ps[r0*LP + cb1]     = s1[0]*scale;  Ps[r0*LP + cb1 + 1] = s1[1]*scale;
            Ps[(r0+8)*LP + cb1] = s1[2]*scale;  Ps[(r0+8)*LP + cb1+1] = s1[3]*scale;
        }
        __syncthreads();

        // ---- online softmax: 4 threads per row; write exp back as tf32 bits ----
        {
            int r = tid >> 2, sub = tid & 3;
            int gq = q0 + r;
            int lim = gq - kb;
            int base = sub * 8;
            float pv[8];
            float mx = -1e30f;
            #pragma unroll
            for (int i = 0; i < 8; i++) {
                float v = Ps[r*LP + base + i];
                bool ok = (base + i) <= lim;
                pv[i] = ok ? v : -1e30f;
                mx = fmaxf(mx, pv[i]);
            }
            mx = fmaxf(mx, __shfl_xor_sync(0xffffffffu, mx, 1));
            mx = fmaxf(mx, __shfl_xor_sync(0xffffffffu, mx, 2));
            float mo = mrow[r];
            float mn = fmaxf(mo, mx);
            float al = __expf(mo - mn);
            float ss = 0.f;
            #pragma unroll
            for (int i = 0; i < 8; i++) {
                float e = ((base + i) <= lim) ? __expf(pv[i] - mn) : 0.f;
                Pu[r*LP + base + i] = f2tf(e);
                ss += e;
            }
            ss += __shfl_xor_sync(0xffffffffu, ss, 1);
            ss += __shfl_xor_sync(0xffffffffu, ss, 2);
            if (sub == 0) {
                lrow[r] = lrow[r] * al + ss;
                mrow[r] = mn;
                arow[r] = al;
            }
        }
        __syncthreads();

        // ---- O = O*alpha + P V ----
        {
            float a_lo = arow[rw*16 + lr];
            float a_hi = arow[rw*16 + lr + 8];
            #pragma unroll
            for (int j = 0; j < 8; j++) {
                o[j][0] *= a_lo; o[j][1] *= a_lo;
                o[j][2] *= a_hi; o[j][3] *= a_hi;
            }
            int pr = rw*16 + lr;
            #pragma unroll
            for (int kk = 0; kk < 4; kk++) {
                int k0 = kk*8;
                unsigned a0 = Pu[pr*LP + k0 + lc];
                unsigned a1 = Pu[(pr+8)*LP + k0 + lc];
                unsigned a2 = Pu[pr*LP + k0 + lc + 4];
                unsigned a3 = Pu[(pr+8)*LP + k0 + lc + 4];
                #pragma unroll
                for (int j = 0; j < 8; j++) {
                    int vc = ch*64 + j*8 + lr;
                    unsigned b0 = Vs[(k0 + lc)*LV + vc];
                    unsigned b1 = Vs[(k0 + lc + 4)*LV + vc];
                    MMA_TF32(o[j][0],o[j][1],o[j][2],o[j][3], a0,a1,a2,a3, b0,b1);
                }
            }
        }
        __syncthreads();
    }

    int b = bk >> 3, jslot = bk & 7;
    int r0 = rw*16 + lr;
    int gq0 = q0 + r0, gq1 = q0 + r0 + 8;
    float w_lo = HWp[((size_t)(b*SEQ + gq0)) * KSEL + jslot] / lrow[r0];
    float w_hi = HWp[((size_t)(b*SEQ + gq1)) * KSEL + jslot] / lrow[r0 + 8];
    #pragma unroll
    for (int j = 0; j < 8; j++) {
        int cb = ch*64 + j*8 + 2*lc;
        size_t off0 = (((size_t)(b*SEQ + gq0)) * KSEL + jslot) * HD + cb;
        size_t off1 = (((size_t)(b*SEQ + gq1)) * KSEL + jslot) * HD + cb;
        float2 v0 = make_float2(o[j][0]*w_lo, o[j][1]*w_lo);
        float2 v1 = make_float2(o[j][2]*w_hi, o[j][3]*w_hi);
        *(float2*)&Out[off0] = v0;
        *(float2*)&Out[off1] = v1;
    }
}

// ---------------- aux loss + head_counts tail ----------------
__global__ void finalize_kernel(float* __restrict__ out, int out_size) {
    int base = NTOK * EMB;
    int extra = out_size - base;
    if (extra <= 0) return;
    bool has_aux = (extra == BATCH*NH + 1) || (extra == 1);
    int zend = has_aux ? out_size - 1 : out_size;
    int gtid = blockIdx.x * blockDim.x + threadIdx.x;
    for (int i = base + gtid; i < zend; i += gridDim.x * blockDim.x) out[i] = 0.f;
    if (gtid == 0 && has_aux) {
        float aux = 0.f;
        for (int b = 0; b < BATCH; b++) {
            float sb = 0.f;
            for (int h = 0; h < NH; h++)
                sb += (g_facc[b*NH + h] / (float)SEQ) * (g_pacc[b*NH + h] / (float)SEQ);
            aux += sb;
        }
        aux = (float)NH * aux / (float)BATCH - 0.01f * (g_ent[0] / (float)(BATCH*SEQ));
        out[out_size - 1] = aux;
    }
}

// ---------------- launcher ----------------
extern "C" void kernel_launch(void* const* d_in, const int* in_sizes, int n_in,
                              void* d_out, int out_size)
{
    (void)in_sizes; (void)n_in;
    const float* x  = (const float*)d_in[0];
    const float* Wq = (const float*)d_in[1];
    const float* Wk = (const float*)d_in[2];
    const float* Wv = (const float*)d_in[3];
    const float* Wr = (const float*)d_in[4];
    const float* Wo = (const float*)d_in[5];
    float* out = (float*)d_out;

    float *p_q, *p_k, *p_v, *p_attn, *p_hw;
    cudaGetSymbolAddress((void**)&p_q,    g_q);
    cudaGetSymbolAddress((void**)&p_k,    g_k);
    cudaGetSymbolAddress((void**)&p_v,    g_v);
    cudaGetSymbolAddress((void**)&p_attn, g_attn);
    cudaGetSymbolAddress((void**)&p_hw,   g_hw);

    size_t gemm_smem = (size_t)(2*BM*LDA + 2*BKt*LDB) * sizeof(float);
    cudaFuncSetAttribute(moh_proj_kernel, cudaFuncAttributeMaxDynamicSharedMemorySize,
                         (int)gemm_smem);
    cudaFuncSetAttribute(tf32_gemm_kernel, cudaFuncAttributeMaxDynamicSharedMemorySize,
                         (int)gemm_smem);
    size_t flash_smem = (size_t)(64*LQ + 32*LK + 32*LV + 64*LP + 3*64) * sizeof(float);
    cudaFuncSetAttribute(flash_tc_kernel, cudaFuncAttributeMaxDynamicSharedMemorySize,
                         (int)flash_smem);

    zero_stats_kernel<<<1, 128>>>();
    router_kernel<<<NTOK, 32>>>(x, Wr);

    dim3 gproj(NTOK/BM, NH, 3);
    moh_proj_kernel<<<gproj, 256, gemm_smem>>>(x, Wq, Wk, Wv, p_q, p_k, p_v);

    dim3 gflash(SEQ/64, BATCH*KSEL);
    flash_tc_kernel<<<gflash, 256, flash_smem>>>(p_q, p_k, p_v, p_hw, p_attn);

    dim3 gout(EMB/BN, NTOK/BM);
    tf32_gemm_kernel<<<gout, 256, gemm_smem>>>(p_attn, Wo, out, NTOK, EMB, EMB);

    finalize_kernel<<<32, 256>>>(out, out_size);
}

// round 11
// speedup vs baseline: 3.8381x; 1.0764x over previous
#include <cuda_runtime.h>
#include <mma.h>
#include <math.h>

using namespace nvcuda;

#define BATCH 2
#define SEQ   2048
#define EMB   1024
#define NH    32
#define KSEL  8
#define HD    128
#define NTOK  (BATCH*SEQ)      // 4096
#define HDALL (NH*HD)          // 4096
#define KD    (KSEL*HD)        // 1024

// ---------------- scratch ----------------
__device__ float g_q[(size_t)BATCH*KSEL*SEQ*HD];   // [B*K, S, D] (tf32-rounded)
__device__ float g_k[(size_t)BATCH*KSEL*SEQ*HD];
__device__ float g_v[(size_t)BATCH*KSEL*SEQ*HD];
__device__ float g_attn[(size_t)NTOK*KD];          // [B,S,K,D]
__device__ int   g_list[NH*NTOK];
__device__ int   g_cnt[NH];
__device__ float g_hw[NTOK*KSEL];
__device__ float g_pacc[BATCH*NH];
__device__ float g_facc[BATCH*NH];
__device__ float g_ent[1];

__device__ __forceinline__ unsigned f2tf(float f) {
    unsigned u;
    asm("cvt.rna.tf32.f32 %0, %1;\n" : "=r"(u) : "f"(f));
    return u;
}
__device__ __forceinline__ float tfround(float f) {
    return __uint_as_float(f2tf(f));
}

__global__ void zero_stats_kernel() {
    int t = threadIdx.x;
    if (t < BATCH*NH) { g_pacc[t] = 0.f; g_facc[t] = 0.f; }
    if (t < NH) g_cnt[t] = 0;
    if (t == 0) g_ent[0] = 0.f;
}

// ---------------- router ----------------
__global__ void router_kernel(const float* __restrict__ x, const float* __restrict__ Wr) {
    __shared__ float xs[EMB];
    __shared__ float lg[NH];
    int tok = blockIdx.x;
    int tid = threadIdx.x;
    const float* xr = x + (size_t)tok * EMB;
    for (int e = tid; e < EMB; e += 32) xs[e] = xr[e];
    __syncwarp();
    float acc = 0.f;
    #pragma unroll 8
    for (int e = 0; e < EMB; e++) acc += xs[e] * Wr[e*NH + tid];
    lg[tid] = acc;
    float m = acc;
    #pragma unroll
    for (int o = 16; o; o >>= 1) m = fmaxf(m, __shfl_xor_sync(0xffffffffu, m, o));
    float ex = expf(acc - m);
    float sum = ex;
    #pragma unroll
    for (int o = 16; o; o >>= 1) sum += __shfl_xor_sync(0xffffffffu, sum, o);
    float p = ex / sum;
    int b = tok / SEQ;
    atomicAdd(&g_pacc[b*NH + tid], p);
    float term = p * logf(p + 1e-8f);
    float esum = term;
    #pragma unroll
    for (int o = 16; o; o >>= 1) esum += __shfl_xor_sync(0xffffffffu, esum, o);
    if (tid == 0) atomicAdd(&g_ent[0], -esum);
    __syncwarp();
    if (tid == 0) {
        float tl[KSEL]; int ti[KSEL];
        unsigned mask = 0;
        for (int k = 0; k < KSEL; k++) {
            float best = -1e30f; int bi = 0;
            for (int h = 0; h < NH; h++)
                if (!((mask >> h) & 1u) && lg[h] > best) { best = lg[h]; bi = h; }
            mask |= 1u << bi; tl[k] = best; ti[k] = bi;
        }
        float ws = 0.f, w[KSEL];
        for (int k = 0; k < KSEL; k++) { w[k] = expf(tl[k] - tl[0]); ws += w[k]; }
        for (int k = 0; k < KSEL; k++) {
            g_hw[tok*KSEL + k] = w[k] / ws;
            int h = ti[k];
            int pos = atomicAdd(&g_cnt[h], 1);
            g_list[h*NTOK + pos] = (tok << 3) | k;
        }
        atomicAdd(&g_facc[b*NH + ti[0]], 1.0f);
    }
}

// ---------------- GEMM common ----------------
#define BM 128
#define BN 128
#define BKt 32
#define LDA 36
#define LDB 132
#define LDC 132

#define CPA16(dst, src) asm volatile("cp.async.cg.shared.global [%0], [%1], 16;\n" \
        :: "r"(dst), "l"(src))
#define CPA_COMMIT() asm volatile("cp.async.commit_group;\n")
#define CPA_WAIT1()  asm volatile("cp.async.wait_group 1;\n")
#define CPA_WAIT0()  asm volatile("cp.async.wait_group 0;\n")

// ---------------- grouped TF32 projection GEMM (q,k,v fused; rope fused; tf32-round) ----
__global__ void __launch_bounds__(256, 2) moh_proj_kernel(
    const float* __restrict__ x,
    const float* __restrict__ Wq, const float* __restrict__ Wk, const float* __restrict__ Wv,
    float* __restrict__ dq, float* __restrict__ dk, float* __restrict__ dv)
{
    int h = blockIdx.y;
    int cnt = g_cnt[h];
    int m0 = blockIdx.x * BM;
    if (m0 >= cnt) return;
    int rows = min(BM, cnt - m0);
    int z = blockIdx.z;
    const float* W = (z == 0) ? Wq : (z == 1) ? Wk : Wv;
    float* dst     = (z == 0) ? dq : (z == 1) ? dk : dv;

    extern __shared__ float sm[];
    float* As[2] = { sm, sm + BM*LDA };
    float* Bs[2] = { sm + 2*BM*LDA, sm + 2*BM*LDA + BKt*LDB };
    float* Csm   = sm;
    __shared__ int s_pk[BM];

    int tid = threadIdx.x;
    if (tid < BM) {
        int r = tid < rows ? tid : rows - 1;
        s_pk[tid] = g_list[h*NTOK + m0 + r];
    }
    __syncthreads();

    int wid = tid >> 5;
    int wm = wid >> 2, wn = wid & 3;
    int col0 = h * HD;

    int ar[4], ac[4], br[4], bc[4];
    const float* abase[4];
    #pragma unroll
    for (int i = 0; i < 4; i++) {
        int idx = tid + i*256;
        ar[i] = idx >> 3;  ac[i] = (idx & 7) * 4;
        br[i] = idx >> 5;  bc[i] = (idx & 31) * 4;
        abase[i] = x + (size_t)(s_pk[ar[i]] >> 3) * EMB + ac[i];
    }

    wmma::fragment<wmma::accumulator, 16, 16, 8, float> cfr[4][2];
    #pragma unroll
    for (int i = 0; i < 4; i++)
        #pragma unroll
        for (int j = 0; j < 2; j++) wmma::fill_fragment(cfr[i][j], 0.0f);

    const int ntiles = EMB / BKt;
    #pragma unroll
    for (int i = 0; i < 4; i++) {
        unsigned da = (unsigned)__cvta_generic_to_shared(As[0] + ar[i]*LDA + ac[i]);
        CPA16(da, abase[i]);
        unsigned db = (unsigned)__cvta_generic_to_shared(Bs[0] + br[i]*LDB + bc[i]);
        CPA16(db, W + (size_t)br[i] * HDALL + col0 + bc[i]);
    }
    CPA_COMMIT();

    for (int t = 0; t < ntiles; t++) {
        int buf = t & 1;
        if (t + 1 < ntiles) {
            int nb = (t + 1) & 1;
            int k0 = (t + 1) * BKt;
            #pragma unroll
            for (int i = 0; i < 4; i++) {
                unsigned da = (unsigned)__cvta_generic_to_shared(As[nb] + ar[i]*LDA + ac[i]);
                CPA16(da, abase[i] + k0);
                unsigned db = (unsigned)__cvta_generic_to_shared(Bs[nb] + br[i]*LDB + bc[i]);
                CPA16(db, W + (size_t)(k0 + br[i]) * HDALL + col0 + bc[i]);
            }
            CPA_COMMIT();
            CPA_WAIT1();
        } else {
            CPA_WAIT0();
        }
        __syncthreads();

        float* Ab = As[buf];
        float* Bb = Bs[buf];
        #pragma unroll
        for (int kk = 0; kk < BKt/8; kk++) {
            wmma::fragment<wmma::matrix_a, 16, 16, 8, wmma::precision::tf32, wmma::row_major> af[4];
            wmma::fragment<wmma::matrix_b, 16, 16, 8, wmma::precision::tf32, wmma::row_major> bf[2];
            #pragma unroll
            for (int i = 0; i < 4; i++) {
                wmma::load_matrix_sync(af[i], Ab + (wm*64 + i*16)*LDA + kk*8, LDA);
                #pragma unroll
                for (int e = 0; e < af[i].num_elements; e++)
                    af[i].x[e] = wmma::__float_to_tf32(af[i].x[e]);
            }
            #pragma unroll
            for (int j = 0; j < 2; j++) {
                wmma::load_matrix_sync(bf[j], Bb + kk*8*LDB + wn*32 + j*16, LDB);
                #pragma unroll
                for (int e = 0; e < bf[j].num_elements; e++)
                    bf[j].x[e] = wmma::__float_to_tf32(bf[j].x[e]);
            }
            #pragma unroll
            for (int i = 0; i < 4; i++)
                #pragma unroll
                for (int j = 0; j < 2; j++)
                    wmma::mma_sync(cfr[i][j], af[i], bf[j], cfr[i][j]);
        }
        __syncthreads();
    }

    #pragma unroll
    for (int i = 0; i < 4; i++)
        #pragma unroll
        for (int j = 0; j < 2; j++)
            wmma::store_matrix_sync(Csm + (wm*64 + i*16)*LDC + wn*32 + j*16,
                                    cfr[i][j], LDC, wmma::mem_row_major);
    __syncthreads();

    if (z < 2) {
        // rope-fused scatter with tf32 rounding
        for (int i = tid; i < BM * 16; i += 256) {
            int row = i >> 4;
            if (row >= rows) break;
            int c4 = (i & 15) * 4;
            int pk = s_pk[row];
            int tok = pk >> 3, j = pk & 7;
            int b = tok / SEQ, s = tok % SEQ;
            float4 lo = *(float4*)&Csm[row*LDC + c4];
            float4 hi = *(float4*)&Csm[row*LDC + c4 + 64];
            float4 olo, ohi;
            float fs = (float)s;
            {
                float cc, sn, ang;
                ang = fs * powf(10000.0f, -(float)(c4+0) / 64.0f);
                cc = cosf(ang); sn = sinf(ang);
                olo.x = tfround(lo.x*cc - hi.x*sn);  ohi.x = tfround(hi.x*cc + lo.x*sn);
                ang = fs * powf(10000.0f, -(float)(c4+1) / 64.0f);
                cc = cosf(ang); sn = sinf(ang);
                olo.y = tfround(lo.y*cc - hi.y*sn);  ohi.y = tfround(hi.y*cc + lo.y*sn);
                ang = fs * powf(10000.0f, -(float)(c4+2) / 64.0f);
                cc = cosf(ang); sn = sinf(ang);
                olo.z = tfround(lo.z*cc - hi.z*sn);  ohi.z = tfround(hi.z*cc + lo.z*sn);
                ang = fs * powf(10000.0f, -(float)(c4+3) / 64.0f);
                cc = cosf(ang); sn = sinf(ang);
                olo.w = tfround(lo.w*cc - hi.w*sn);  ohi.w = tfround(hi.w*cc + lo.w*sn);
            }
            size_t off = (((size_t)(b*KSEL + j)) * SEQ + s) * HD;
            *(float4*)&dst[off + c4]      = olo;
            *(float4*)&dst[off + c4 + 64] = ohi;
        }
    } else {
        for (int i = tid; i < BM * (HD/4); i += 256) {
            int row = i >> 5;
            if (row >= rows) break;
            int c = (i & 31) * 4;
            int pk = s_pk[row];
            int tok = pk >> 3, j = pk & 7;
            int b = tok / SEQ, s = tok % SEQ;
            float4 v = *(float4*)&Csm[row*LDC + c];
            v.x = tfround(v.x); v.y = tfround(v.y);
            v.z = tfround(v.z); v.w = tfround(v.w);
            size_t off = (((size_t)(b*KSEL + j)) * SEQ + s) * HD + c;
            *(float4*)&dst[off] = v;
        }
    }
}

// ---------------- dense TF32 GEMM (Wo) ----------------
__global__ void __launch_bounds__(256, 2) tf32_gemm_kernel(
    const float* __restrict__ A, const float* __restrict__ Bm, float* __restrict__ C,
    int M, int N, int Kd)
{
    extern __shared__ float sm[];
    float* As[2] = { sm, sm + BM*LDA };
    float* Bs[2] = { sm + 2*BM*LDA, sm + 2*BM*LDA + BKt*LDB };

    int tid = threadIdx.x;
    int wid = tid >> 5;
    int wm = wid >> 2, wn = wid & 3;
    int row0 = blockIdx.y * BM, col0 = blockIdx.x * BN;

    int ar[4], ac[4], br[4], bc[4];
    #pragma unroll
    for (int i = 0; i < 4; i++) {
        int idx = tid + i*256;
        ar[i] = idx >> 3;  ac[i] = (idx & 7) * 4;
        br[i] = idx >> 5;  bc[i] = (idx & 31) * 4;
    }

    wmma::fragment<wmma::accumulator, 16, 16, 8, float> cfr[4][2];
    #pragma unroll
    for (int i = 0; i < 4; i++)
        #pragma unroll
        for (int j = 0; j < 2; j++) wmma::fill_fragment(cfr[i][j], 0.0f);

    int ntiles = Kd / BKt;
    #pragma unroll
    for (int i = 0; i < 4; i++) {
        unsigned da = (unsigned)__cvta_generic_to_shared(As[0] + ar[i]*LDA + ac[i]);
        CPA16(da, A + (size_t)(row0 + ar[i]) * Kd + ac[i]);
        unsigned db = (unsigned)__cvta_generic_to_shared(Bs[0] + br[i]*LDB + bc[i]);
        CPA16(db, Bm + (size_t)br[i] * N + col0 + bc[i]);
    }
    CPA_COMMIT();

    for (int t = 0; t < ntiles; t++) {
        int buf = t & 1;
        if (t + 1 < ntiles) {
            int nb = (t + 1) & 1;
            int k0 = (t + 1) * BKt;
            #pragma unroll
            for (int i = 0; i < 4; i++) {
                unsigned da = (unsigned)__cvta_generic_to_shared(As[nb] + ar[i]*LDA + ac[i]);
                CPA16(da, A + (size_t)(row0 + ar[i]) * Kd + k0 + ac[i]);
                unsigned db = (unsigned)__cvta_generic_to_shared(Bs[nb] + br[i]*LDB + bc[i]);
                CPA16(db, Bm + (size_t)(k0 + br[i]) * N + col0 + bc[i]);
            }
            CPA_COMMIT();
            CPA_WAIT1();
        } else {
            CPA_WAIT0();
        }
        __syncthreads();

        float* Ab = As[buf];
        float* Bb = Bs[buf];
        #pragma unroll
        for (int kk = 0; kk < BKt/8; kk++) {
            wmma::fragment<wmma::matrix_a, 16, 16, 8, wmma::precision::tf32, wmma::row_major> af[4];
            wmma::fragment<wmma::matrix_b, 16, 16, 8, wmma::precision::tf32, wmma::row_major> bf[2];
            #pragma unroll
            for (int i = 0; i < 4; i++) {
                wmma::load_matrix_sync(af[i], Ab + (wm*64 + i*16)*LDA + kk*8, LDA);
                #pragma unroll
                for (int e = 0; e < af[i].num_elements; e++)
                    af[i].x[e] = wmma::__float_to_tf32(af[i].x[e]);
            }
            #pragma unroll
            for (int j = 0; j < 2; j++) {
                wmma::load_matrix_sync(bf[j], Bb + kk*8*LDB + wn*32 + j*16, LDB);
                #pragma unroll
                for (int e = 0; e < bf[j].num_elements; e++)
                    bf[j].x[e] = wmma::__float_to_tf32(bf[j].x[e]);
            }
            #pragma unroll
            for (int i = 0; i < 4; i++)
                #pragma unroll
                for (int j = 0; j < 2; j++)
                    wmma::mma_sync(cfr[i][j], af[i], bf[j], cfr[i][j]);
        }
        __syncthreads();
    }

    #pragma unroll
    for (int i = 0; i < 4; i++)
        #pragma unroll
        for (int j = 0; j < 2; j++)
            wmma::store_matrix_sync(
                C + (size_t)(row0 + wm*64 + i*16) * N + col0 + wn*32 + j*16,
                cfr[i][j], N, wmma::mem_row_major);
}

// ---------------- TF32 tensor-core causal flash attention ----------------
// q/k/v pre-rounded to tf32 in proj -> raw smem bits feed MMA directly.
// K/V cp.async double-buffered; heavy-first block order.
#define LQ 132
#define LK 132
#define LV 136
#define LP 36

#define MMA_TF32(c0,c1,c2,c3,a0,a1,a2,a3,b0,b1) \
    asm volatile("mma.sync.aligned.m16n8k8.row.col.f32.tf32.tf32.f32 " \
        "{%0,%1,%2,%3}, {%4,%5,%6,%7}, {%8,%9}, {%0,%1,%2,%3};\n" \
        : "+f"(c0), "+f"(c1), "+f"(c2), "+f"(c3) \
        : "r"(a0), "r"(a1), "r"(a2), "r"(a3), "r"(b0), "r"(b1))

__global__ void __launch_bounds__(256, 2) flash_tc_kernel(
    const float* __restrict__ Q, const float* __restrict__ Kx, const float* __restrict__ Vx,
    const float* __restrict__ HWp, float* __restrict__ Out)
{
    extern __shared__ float smf[];
    unsigned* Qs    = (unsigned*)smf;           // [64][LQ]
    unsigned* KsBuf = Qs + 64*LQ;               // [2][32][LK]
    unsigned* VsBuf = KsBuf + 2*32*LK;          // [2][32][LV]
    float*    Ps    = (float*)(VsBuf + 2*32*LV);// [64][LP]
    unsigned* Pu    = (unsigned*)Ps;
    float* mrow = Ps + 64*LP;
    float* lrow = mrow + 64;
    float* arow = lrow + 64;

    int tid = threadIdx.x;
    int wid = tid >> 5, lane = tid & 31;
    int lr = lane >> 2, lc = lane & 3;
    int rw = wid >> 1, ch = wid & 1;
    int bk = blockIdx.y;
    int q0 = ((int)gridDim.x - 1 - (int)blockIdx.x) * 64;   // heavy-first

    const float* Qp = Q  + (size_t)bk * SEQ * HD;
    const float* Kp = Kx + (size_t)bk * SEQ * HD;
    const float* Vp = Vx + (size_t)bk * SEQ * HD;

    const int nkt = (q0 + 64) / 32;

    // prologue: prefetch tile 0 K/V into stage 0 (raw 16B, values pre-rounded)
    {
        for (int i = tid; i < 32 * (HD/4); i += 256) {
            int r = i >> 5, cc = (i & 31) * 4;
            unsigned dk = (unsigned)__cvta_generic_to_shared(&KsBuf[r*LK + cc]);
            CPA16(dk, Kp + (size_t)r * HD + cc);
            unsigned dv = (unsigned)__cvta_generic_to_shared(&VsBuf[r*LV + cc]);
            CPA16(dv, Vp + (size_t)r * HD + cc);
        }
        CPA_COMMIT();
    }

    // Q: regular loads (already tf32-rounded)
    for (int i = tid; i < 64 * (HD/4); i += 256) {
        int r = i >> 5, cc = (i & 31) * 4;
        *(uint4*)&Qs[r*LQ + cc] = *(const uint4*)(Qp + (size_t)(q0 + r) * HD + cc);
    }
    if (tid < 64) { mrow[tid] = -1e30f; lrow[tid] = 0.f; }

    float o[8][4];
    #pragma unroll
    for (int j = 0; j < 8; j++)
        #pragma unroll
        for (int e = 0; e < 4; e++) o[j][e] = 0.f;

    const float scale = 0.08838834764831845f;

    for (int kt = 0; kt < nkt; kt++) {
        int stage = kt & 1;
        // prefetch next tile into other stage
        if (kt + 1 < nkt) {
            int ns = (kt + 1) & 1;
            size_t nb = (size_t)(kt + 1) * 32;
            unsigned* Kn = KsBuf + ns*32*LK;
            unsigned* Vn = VsBuf + ns*32*LV;
            for (int i = tid; i < 32 * (HD/4); i += 256) {
                int r = i >> 5, cc = (i & 31) * 4;
                unsigned dk = (unsigned)__cvta_generic_to_shared(&Kn[r*LK + cc]);
                CPA16(dk, Kp + (nb + r) * HD + cc);
                unsigned dv = (unsigned)__cvta_generic_to_shared(&Vn[r*LV + cc]);
                CPA16(dv, Vp + (nb + r) * HD + cc);
            }
            CPA_COMMIT();
            CPA_WAIT1();
        } else {
            CPA_WAIT0();
        }
        __syncthreads();

        unsigned* Ks = KsBuf + stage*32*LK;
        unsigned* Vs = VsBuf + stage*32*LV;
        int kb = kt * 32;

        // ---- S = Q K^T ----
        float s0[4] = {0,0,0,0}, s1[4] = {0,0,0,0};
        {
            int arw = rw*16 + lr;
            int nc0 = ch*16 + lr;
            int nc1 = ch*16 + 8 + lr;
            #pragma unroll
            for (int kk = 0; kk < 16; kk++) {
                int k0 = kk*8;
                unsigned a0 = Qs[arw*LQ + k0 + lc];
                unsigned a1 = Qs[(arw+8)*LQ + k0 + lc];
                unsigned a2 = Qs[arw*LQ + k0 + lc + 4];
                unsigned a3 = Qs[(arw+8)*LQ + k0 + lc + 4];
                unsigned b0 = Ks[nc0*LK + k0 + lc];
                unsigned b1 = Ks[nc0*LK + k0 + lc + 4];
                MMA_TF32(s0[0],s0[1],s0[2],s0[3], a0,a1,a2,a3, b0,b1);
                unsigned c0 = Ks[nc1*LK + k0 + lc];
                unsigned c1 = Ks[nc1*LK + k0 + lc + 4];
                MMA_TF32(s1[0],s1[1],s1[2],s1[3], a0,a1,a2,a3, c0,c1);
            }
            int r0 = rw*16 + lr;
            int cb0 = ch*16 + 2*lc;
            int cb1 = ch*16 + 8 + 2*lc;
            Ps[r0*LP + cb0]     = s0[0]*scale;  Ps[r0*LP + cb0 + 1] = s0[1]*scale;
            Ps[(r0+8)*LP + cb0] = s0[2]*scale;  Ps[(r0+8)*LP + cb0+1] = s0[3]*scale;
            Ps[r0*LP + cb1]     = s1[0]*scale;  Ps[r0*LP + cb1 + 1] = s1[1]*scale;
            Ps[(r0+8)*LP + cb1] = s1[2]*scale;  Ps[(r0+8)*LP + cb1+1] = s1[3]*scale;
        }
        __syncthreads();

        // ---- online softmax: 4 threads/row; write exp back as tf32 bits ----
        {
            int r = tid >> 2, sub = tid & 3;
            int gq = q0 + r;
            int lim = gq - kb;
            int base = sub * 8;
            float pv[8];
            float mx = -1e30f;
            #pragma unroll
            for (int i = 0; i < 8; i++) {
                float v = Ps[r*LP + base + i];
                bool ok = (base + i) <= lim;
                pv[i] = ok ? v : -1e30f;
                mx = fmaxf(mx, pv[i]);
            }
            mx = fmaxf(mx, __shfl_xor_sync(0xffffffffu, mx, 1));
            mx = fmaxf(mx, __shfl_xor_sync(0xffffffffu, mx, 2));
            float mo = mrow[r];
            float mn = fmaxf(mo, mx);
            float al = __expf(mo - mn);
            float ss = 0.f;
            #pragma unroll
            for (int i = 0; i < 8; i++) {
                float e = ((base + i) <= lim) ? __expf(pv[i] - mn) : 0.f;
                Pu[r*LP + base + i] = f2tf(e);
                ss += e;
            }
            ss += __shfl_xor_sync(0xffffffffu, ss, 1);
            ss += __shfl_xor_sync(0xffffffffu, ss, 2);
            if (sub == 0) {
                lrow[r] = lrow[r] * al + ss;
                mrow[r] = mn;
                arow[r] = al;
            }
        }
        __syncthreads();

        // ---- O = O*alpha + P V ----
        {
            float a_lo = arow[rw*16 + lr];
            float a_hi = arow[rw*16 + lr + 8];
            #pragma unroll
            for (int j = 0; j < 8; j++) {
                o[j][0] *= a_lo; o[j][1] *= a_lo;
                o[j][2] *= a_hi; o[j][3] *= a_hi;
            }
            int pr = rw*16 + lr;
            #pragma unroll
            for (int kk = 0; kk < 4; kk++) {
                int k0 = kk*8;
                unsigned a0 = Pu[pr*LP + k0 + lc];
                unsigned a1 = Pu[(pr+8)*LP + k0 + lc];
                unsigned a2 = Pu[pr*LP + k0 + lc + 4];
                unsigned a3 = Pu[(pr+8)*LP + k0 + lc + 4];
                #pragma unroll
                for (int j = 0; j < 8; j++) {
                    int vc = ch*64 + j*8 + lr;
                    unsigned b0 = Vs[(k0 + lc)*LV + vc];
                    unsigned b1 = Vs[(k0 + lc + 4)*LV + vc];
                    MMA_TF32(o[j][0],o[j][1],o[j][2],o[j][3], a0,a1,a2,a3, b0,b1);
                }
            }
        }
        __syncthreads();
    }

    int b = bk >> 3, jslot = bk & 7;
    int r0 = rw*16 + lr;
    int gq0 = q0 + r0, gq1 = q0 + r0 + 8;
    float w_lo = HWp[((size_t)(b*SEQ + gq0)) * KSEL + jslot] / lrow[r0];
    float w_hi = HWp[((size_t)(b*SEQ + gq1)) * KSEL + jslot] / lrow[r0 + 8];
    #pragma unroll
    for (int j = 0; j < 8; j++) {
        int cb = ch*64 + j*8 + 2*lc;
        size_t off0 = (((size_t)(b*SEQ + gq0)) * KSEL + jslot) * HD + cb;
        size_t off1 = (((size_t)(b*SEQ + gq1)) * KSEL + jslot) * HD + cb;
        float2 v0 = make_float2(o[j][0]*w_lo, o[j][1]*w_lo);
        float2 v1 = make_float2(o[j][2]*w_hi, o[j][3]*w_hi);
        *(float2*)&Out[off0] = v0;
        *(float2*)&Out[off1] = v1;
    }
}

// ---------------- aux loss + head_counts tail ----------------
__global__ void finalize_kernel(float* __restrict__ out, int out_size) {
    int base = NTOK * EMB;
    int extra = out_size - base;
    if (extra <= 0) return;
    bool has_aux = (extra == BATCH*NH + 1) || (extra == 1);
    int zend = has_aux ? out_size - 1 : out_size;
    int gtid = blockIdx.x * blockDim.x + threadIdx.x;
    for (int i = base + gtid; i < zend; i += gridDim.x * blockDim.x) out[i] = 0.f;
    if (gtid == 0 && has_aux) {
        float aux = 0.f;
        for (int b = 0; b < BATCH; b++) {
            float sb = 0.f;
            for (int h = 0; h < NH; h++)
                sb += (g_facc[b*NH + h] / (float)SEQ) * (g_pacc[b*NH + h] / (float)SEQ);
            aux += sb;
        }
        aux = (float)NH * aux / (float)BATCH - 0.01f * (g_ent[0] / (float)(BATCH*SEQ));
        out[out_size - 1] = aux;
    }
}

// ---------------- launcher ----------------
extern "C" void kernel_launch(void* const* d_in, const int* in_sizes, int n_in,
                              void* d_out, int out_size)
{
    (void)in_sizes; (void)n_in;
    const float* x  = (const float*)d_in[0];
    const float* Wq = (const float*)d_in[1];
    const float* Wk = (const float*)d_in[2];
    const float* Wv = (const float*)d_in[3];
    const float* Wr = (const float*)d_in[4];
    const float* Wo = (const float*)d_in[5];
    float* out = (float*)d_out;

    float *p_q, *p_k, *p_v, *p_attn, *p_hw;
    cudaGetSymbolAddress((void**)&p_q,    g_q);
    cudaGetSymbolAddress((void**)&p_k,    g_k);
    cudaGetSymbolAddress((void**)&p_v,    g_v);
    cudaGetSymbolAddress((void**)&p_attn, g_attn);
    cudaGetSymbolAddress((void**)&p_hw,   g_hw);

    size_t gemm_smem = (size_t)(2*BM*LDA + 2*BKt*LDB) * sizeof(float);
    cudaFuncSetAttribute(moh_proj_kernel, cudaFuncAttributeMaxDynamicSharedMemorySize,
                         (int)gemm_smem);
    cudaFuncSetAttribute(tf32_gemm_kernel, cudaFuncAttributeMaxDynamicSharedMemorySize,
                         (int)gemm_smem);
    size_t flash_smem = (size_t)(64*LQ + 2*32*LK + 2*32*LV + 64*LP + 3*64) * sizeof(float);
    cudaFuncSetAttribute(flash_tc_kernel, cudaFuncAttributeMaxDynamicSharedMemorySize,
                         (int)flash_smem);

    zero_stats_kernel<<<1, 128>>>();
    router_kernel<<<NTOK, 32>>>(x, Wr);

    dim3 gproj(NTOK/BM, NH, 3);
    moh_proj_kernel<<<gproj, 256, gemm_smem>>>(x, Wq, Wk, Wv, p_q, p_k, p_v);

    dim3 gflash(SEQ/64, BATCH*KSEL);
    flash_tc_kernel<<<gflash, 256, flash_smem>>>(p_q, p_k, p_v, p_hw, p_attn);

    dim3 gout(EMB/BN, NTOK/BM);
    tf32_gemm_kernel<<<gout, 256, gemm_smem>>>(p_attn, Wo, out, NTOK, EMB, EMB);

    finalize_kernel<<<32, 256>>>(out, out_size);
}

// round 12
// speedup vs baseline: 3.8473x; 1.0024x over previous
#include <cuda_runtime.h>
#include <mma.h>
#include <math.h>

using namespace nvcuda;

#define BATCH 2
#define SEQ   2048
#define EMB   1024
#define NH    32
#define KSEL  8
#define HD    128
#define NTOK  (BATCH*SEQ)      // 4096
#define HDALL (NH*HD)          // 4096
#define KD    (KSEL*HD)        // 1024

// ---------------- scratch ----------------
__device__ float g_q[(size_t)BATCH*KSEL*SEQ*HD];   // [B*K, S, D] (tf32-rounded)
__device__ float g_k[(size_t)BATCH*KSEL*SEQ*HD];
__device__ float g_v[(size_t)BATCH*KSEL*SEQ*HD];
__device__ float g_attn[(size_t)NTOK*KD];          // [B,S,K,D]
__device__ int   g_list[NH*NTOK];
__device__ int   g_cnt[NH];
__device__ float g_hw[NTOK*KSEL];
__device__ float g_pacc[BATCH*NH];
__device__ float g_facc[BATCH*NH];
__device__ float g_ent[1];

__device__ __forceinline__ unsigned f2tf(float f) {
    unsigned u;
    asm("cvt.rna.tf32.f32 %0, %1;\n" : "=r"(u) : "f"(f));
    return u;
}
__device__ __forceinline__ float tfround(float f) {
    return __uint_as_float(f2tf(f));
}

__global__ void zero_stats_kernel() {
    int t = threadIdx.x;
    if (t < BATCH*NH) { g_pacc[t] = 0.f; g_facc[t] = 0.f; }
    if (t < NH) g_cnt[t] = 0;
    if (t == 0) g_ent[0] = 0.f;
}

// ---------------- router ----------------
__global__ void router_kernel(const float* __restrict__ x, const float* __restrict__ Wr) {
    __shared__ float xs[EMB];
    __shared__ float lg[NH];
    int tok = blockIdx.x;
    int tid = threadIdx.x;
    const float* xr = x + (size_t)tok * EMB;
    for (int e = tid; e < EMB; e += 32) xs[e] = xr[e];
    __syncwarp();
    float acc = 0.f;
    #pragma unroll 8
    for (int e = 0; e < EMB; e++) acc += xs[e] * Wr[e*NH + tid];
    lg[tid] = acc;
    float m = acc;
    #pragma unroll
    for (int o = 16; o; o >>= 1) m = fmaxf(m, __shfl_xor_sync(0xffffffffu, m, o));
    float ex = expf(acc - m);
    float sum = ex;
    #pragma unroll
    for (int o = 16; o; o >>= 1) sum += __shfl_xor_sync(0xffffffffu, sum, o);
    float p = ex / sum;
    int b = tok / SEQ;
    atomicAdd(&g_pacc[b*NH + tid], p);
    float term = p * logf(p + 1e-8f);
    float esum = term;
    #pragma unroll
    for (int o = 16; o; o >>= 1) esum += __shfl_xor_sync(0xffffffffu, esum, o);
    if (tid == 0) atomicAdd(&g_ent[0], -esum);
    __syncwarp();
    if (tid == 0) {
        float tl[KSEL]; int ti[KSEL];
        unsigned mask = 0;
        for (int k = 0; k < KSEL; k++) {
            float best = -1e30f; int bi = 0;
            for (int h = 0; h < NH; h++)
                if (!((mask >> h) & 1u) && lg[h] > best) { best = lg[h]; bi = h; }
            mask |= 1u << bi; tl[k] = best; ti[k] = bi;
        }
        float ws = 0.f, w[KSEL];
        for (int k = 0; k < KSEL; k++) { w[k] = expf(tl[k] - tl[0]); ws += w[k]; }
        for (int k = 0; k < KSEL; k++) {
            g_hw[tok*KSEL + k] = w[k] / ws;
            int h = ti[k];
            int pos = atomicAdd(&g_cnt[h], 1);
            g_list[h*NTOK + pos] = (tok << 3) | k;
        }
        atomicAdd(&g_facc[b*NH + ti[0]], 1.0f);
    }
}

// ---------------- GEMM common ----------------
#define BM 128
#define BN 128
#define BKt 32
#define LDA 36
#define LDB 132
#define LDC 132

#define CPA16(dst, src) asm volatile("cp.async.cg.shared.global [%0], [%1], 16;\n" \
        :: "r"(dst), "l"(src))
#define CPA_COMMIT() asm volatile("cp.async.commit_group;\n")
#define CPA_WAIT1()  asm volatile("cp.async.wait_group 1;\n")
#define CPA_WAIT0()  asm volatile("cp.async.wait_group 0;\n")

// ---------------- grouped TF32 projection GEMM (q,k,v fused; rope fused; tf32-round) ----
__global__ void __launch_bounds__(256, 2) moh_proj_kernel(
    const float* __restrict__ x,
    const float* __restrict__ Wq, const float* __restrict__ Wk, const float* __restrict__ Wv,
    float* __restrict__ dq, float* __restrict__ dk, float* __restrict__ dv)
{
    int h = blockIdx.y;
    int cnt = g_cnt[h];
    int m0 = blockIdx.x * BM;
    if (m0 >= cnt) return;
    int rows = min(BM, cnt - m0);
    int z = blockIdx.z;
    const float* W = (z == 0) ? Wq : (z == 1) ? Wk : Wv;
    float* dst     = (z == 0) ? dq : (z == 1) ? dk : dv;

    extern __shared__ float sm[];
    float* As[2] = { sm, sm + BM*LDA };
    float* Bs[2] = { sm + 2*BM*LDA, sm + 2*BM*LDA + BKt*LDB };
    float* Csm   = sm;
    __shared__ int s_pk[BM];

    int tid = threadIdx.x;
    if (tid < BM) {
        int r = tid < rows ? tid : rows - 1;
        s_pk[tid] = g_list[h*NTOK + m0 + r];
    }
    __syncthreads();

    int wid = tid >> 5;
    int wm = wid >> 2, wn = wid & 3;
    int col0 = h * HD;

    int ar[4], ac[4], br[4], bc[4];
    const float* abase[4];
    #pragma unroll
    for (int i = 0; i < 4; i++) {
        int idx = tid + i*256;
        ar[i] = idx >> 3;  ac[i] = (idx & 7) * 4;
        br[i] = idx >> 5;  bc[i] = (idx & 31) * 4;
        abase[i] = x + (size_t)(s_pk[ar[i]] >> 3) * EMB + ac[i];
    }

    wmma::fragment<wmma::accumulator, 16, 16, 8, float> cfr[4][2];
    #pragma unroll
    for (int i = 0; i < 4; i++)
        #pragma unroll
        for (int j = 0; j < 2; j++) wmma::fill_fragment(cfr[i][j], 0.0f);

    const int ntiles = EMB / BKt;
    #pragma unroll
    for (int i = 0; i < 4; i++) {
        unsigned da = (unsigned)__cvta_generic_to_shared(As[0] + ar[i]*LDA + ac[i]);
        CPA16(da, abase[i]);
        unsigned db = (unsigned)__cvta_generic_to_shared(Bs[0] + br[i]*LDB + bc[i]);
        CPA16(db, W + (size_t)br[i] * HDALL + col0 + bc[i]);
    }
    CPA_COMMIT();

    for (int t = 0; t < ntiles; t++) {
        int buf = t & 1;
        if (t + 1 < ntiles) {
            int nb = (t + 1) & 1;
            int k0 = (t + 1) * BKt;
            #pragma unroll
            for (int i = 0; i < 4; i++) {
                unsigned da = (unsigned)__cvta_generic_to_shared(As[nb] + ar[i]*LDA + ac[i]);
                CPA16(da, abase[i] + k0);
                unsigned db = (unsigned)__cvta_generic_to_shared(Bs[nb] + br[i]*LDB + bc[i]);
                CPA16(db, W + (size_t)(k0 + br[i]) * HDALL + col0 + bc[i]);
            }
            CPA_COMMIT();
            CPA_WAIT1();
        } else {
            CPA_WAIT0();
        }
        __syncthreads();

        float* Ab = As[buf];
        float* Bb = Bs[buf];
        #pragma unroll
        for (int kk = 0; kk < BKt/8; kk++) {
            wmma::fragment<wmma::matrix_a, 16, 16, 8, wmma::precision::tf32, wmma::row_major> af[4];
            wmma::fragment<wmma::matrix_b, 16, 16, 8, wmma::precision::tf32, wmma::row_major> bf[2];
            #pragma unroll
            for (int i = 0; i < 4; i++) {
                wmma::load_matrix_sync(af[i], Ab + (wm*64 + i*16)*LDA + kk*8, LDA);
                #pragma unroll
                for (int e = 0; e < af[i].num_elements; e++)
                    af[i].x[e] = wmma::__float_to_tf32(af[i].x[e]);
            }
            #pragma unroll
            for (int j = 0; j < 2; j++) {
                wmma::load_matrix_sync(bf[j], Bb + kk*8*LDB + wn*32 + j*16, LDB);
                #pragma unroll
                for (int e = 0; e < bf[j].num_elements; e++)
                    bf[j].x[e] = wmma::__float_to_tf32(bf[j].x[e]);
            }
            #pragma unroll
            for (int i = 0; i < 4; i++)
                #pragma unroll
                for (int j = 0; j < 2; j++)
                    wmma::mma_sync(cfr[i][j], af[i], bf[j], cfr[i][j]);
        }
        __syncthreads();
    }

    #pragma unroll
    for (int i = 0; i < 4; i++)
        #pragma unroll
        for (int j = 0; j < 2; j++)
            wmma::store_matrix_sync(Csm + (wm*64 + i*16)*LDC + wn*32 + j*16,
                                    cfr[i][j], LDC, wmma::mem_row_major);
    __syncthreads();

    if (z < 2) {
        // rope-fused scatter with tf32 rounding
        for (int i = tid; i < BM * 16; i += 256) {
            int row = i >> 4;
            if (row >= rows) break;
            int c4 = (i & 15) * 4;
            int pk = s_pk[row];
            int tok = pk >> 3, j = pk & 7;
            int b = tok / SEQ, s = tok % SEQ;
            float4 lo = *(float4*)&Csm[row*LDC + c4];
            float4 hi = *(float4*)&Csm[row*LDC + c4 + 64];
            float4 olo, ohi;
            float fs = (float)s;
            {
                float cc, sn, ang;
                ang = fs * powf(10000.0f, -(float)(c4+0) / 64.0f);
                cc = cosf(ang); sn = sinf(ang);
                olo.x = tfround(lo.x*cc - hi.x*sn);  ohi.x = tfround(hi.x*cc + lo.x*sn);
                ang = fs * powf(10000.0f, -(float)(c4+1) / 64.0f);
                cc = cosf(ang); sn = sinf(ang);
                olo.y = tfround(lo.y*cc - hi.y*sn);  ohi.y = tfround(hi.y*cc + lo.y*sn);
                ang = fs * powf(10000.0f, -(float)(c4+2) / 64.0f);
                cc = cosf(ang); sn = sinf(ang);
                olo.z = tfround(lo.z*cc - hi.z*sn);  ohi.z = tfround(hi.z*cc + lo.z*sn);
                ang = fs * powf(10000.0f, -(float)(c4+3) / 64.0f);
                cc = cosf(ang); sn = sinf(ang);
                olo.w = tfround(lo.w*cc - hi.w*sn);  ohi.w = tfround(hi.w*cc + lo.w*sn);
            }
            size_t off = (((size_t)(b*KSEL + j)) * SEQ + s) * HD;
            *(float4*)&dst[off + c4]      = olo;
            *(float4*)&dst[off + c4 + 64] = ohi;
        }
    } else {
        for (int i = tid; i < BM * (HD/4); i += 256) {
            int row = i >> 5;
            if (row >= rows) break;
            int c = (i & 31) * 4;
            int pk = s_pk[row];
            int tok = pk >> 3, j = pk & 7;
            int b = tok / SEQ, s = tok % SEQ;
            float4 v = *(float4*)&Csm[row*LDC + c];
            v.x = tfround(v.x); v.y = tfround(v.y);
            v.z = tfround(v.z); v.w = tfround(v.w);
            size_t off = (((size_t)(b*KSEL + j)) * SEQ + s) * HD + c;
            *(float4*)&dst[off] = v;
        }
    }
}

// ---------------- dense TF32 GEMM (Wo) ----------------
__global__ void __launch_bounds__(256, 2) tf32_gemm_kernel(
    const float* __restrict__ A, const float* __restrict__ Bm, float* __restrict__ C,
    int M, int N, int Kd)
{
    extern __shared__ float sm[];
    float* As[2] = { sm, sm + BM*LDA };
    float* Bs[2] = { sm + 2*BM*LDA, sm + 2*BM*LDA + BKt*LDB };

    int tid = threadIdx.x;
    int wid = tid >> 5;
    int wm = wid >> 2, wn = wid & 3;
    int row0 = blockIdx.y * BM, col0 = blockIdx.x * BN;

    int ar[4], ac[4], br[4], bc[4];
    #pragma unroll
    for (int i = 0; i < 4; i++) {
        int idx = tid + i*256;
        ar[i] = idx >> 3;  ac[i] = (idx & 7) * 4;
        br[i] = idx >> 5;  bc[i] = (idx & 31) * 4;
    }

    wmma::fragment<wmma::accumulator, 16, 16, 8, float> cfr[4][2];
    #pragma unroll
    for (int i = 0; i < 4; i++)
        #pragma unroll
        for (int j = 0; j < 2; j++) wmma::fill_fragment(cfr[i][j], 0.0f);

    int ntiles = Kd / BKt;
    #pragma unroll
    for (int i = 0; i < 4; i++) {
        unsigned da = (unsigned)__cvta_generic_to_shared(As[0] + ar[i]*LDA + ac[i]);
        CPA16(da, A + (size_t)(row0 + ar[i]) * Kd + ac[i]);
        unsigned db = (unsigned)__cvta_generic_to_shared(Bs[0] + br[i]*LDB + bc[i]);
        CPA16(db, Bm + (size_t)br[i] * N + col0 + bc[i]);
    }
    CPA_COMMIT();

    for (int t = 0; t < ntiles; t++) {
        int buf = t & 1;
        if (t + 1 < ntiles) {
            int nb = (t + 1) & 1;
            int k0 = (t + 1) * BKt;
            #pragma unroll
            for (int i = 0; i < 4; i++) {
                unsigned da = (unsigned)__cvta_generic_to_shared(As[nb] + ar[i]*LDA + ac[i]);
                CPA16(da, A + (size_t)(row0 + ar[i]) * Kd + k0 + ac[i]);
                unsigned db = (unsigned)__cvta_generic_to_shared(Bs[nb] + br[i]*LDB + bc[i]);
                CPA16(db, Bm + (size_t)(k0 + br[i]) * N + col0 + bc[i]);
            }
            CPA_COMMIT();
            CPA_WAIT1();
        } else {
            CPA_WAIT0();
        }
        __syncthreads();

        float* Ab = As[buf];
        float* Bb = Bs[buf];
        #pragma unroll
        for (int kk = 0; kk < BKt/8; kk++) {
            wmma::fragment<wmma::matrix_a, 16, 16, 8, wmma::precision::tf32, wmma::row_major> af[4];
            wmma::fragment<wmma::matrix_b, 16, 16, 8, wmma::precision::tf32, wmma::row_major> bf[2];
            #pragma unroll
            for (int i = 0; i < 4; i++) {
                wmma::load_matrix_sync(af[i], Ab + (wm*64 + i*16)*LDA + kk*8, LDA);
                #pragma unroll
                for (int e = 0; e < af[i].num_elements; e++)
                    af[i].x[e] = wmma::__float_to_tf32(af[i].x[e]);
            }
            #pragma unroll
            for (int j = 0; j < 2; j++) {
                wmma::load_matrix_sync(bf[j], Bb + kk*8*LDB + wn*32 + j*16, LDB);
                #pragma unroll
                for (int e = 0; e < bf[j].num_elements; e++)
                    bf[j].x[e] = wmma::__float_to_tf32(bf[j].x[e]);
            }
            #pragma unroll
            for (int i = 0; i < 4; i++)
                #pragma unroll
                for (int j = 0; j < 2; j++)
                    wmma::mma_sync(cfr[i][j], af[i], bf[j], cfr[i][j]);
        }
        __syncthreads();
    }

    #pragma unroll
    for (int i = 0; i < 4; i++)
        #pragma unroll
        for (int j = 0; j < 2; j++)
            wmma::store_matrix_sync(
                C + (size_t)(row0 + wm*64 + i*16) * N + col0 + wn*32 + j*16,
                cfr[i][j], N, wmma::mem_row_major);
}

// ---------------- TF32 tensor-core causal flash attention ----------------
// q/k/v pre-rounded to tf32 in proj -> raw smem bits feed MMA directly.
// K/V cp.async double-buffered; heavy-first block order.
#define LQ 132
#define LK 132
#define LV 136
#define LP 36

#define MMA_TF32(c0,c1,c2,c3,a0,a1,a2,a3,b0,b1) \
    asm volatile("mma.sync.aligned.m16n8k8.row.col.f32.tf32.tf32.f32 " \
        "{%0,%1,%2,%3}, {%4,%5,%6,%7}, {%8,%9}, {%0,%1,%2,%3};\n" \
        : "+f"(c0), "+f"(c1), "+f"(c2), "+f"(c3) \
        : "r"(a0), "r"(a1), "r"(a2), "r"(a3), "r"(b0), "r"(b1))

__global__ void __launch_bounds__(256, 2) flash_tc_kernel(
    const float* __restrict__ Q, const float* __restrict__ Kx, const float* __restrict__ Vx,
    const float* __restrict__ HWp, float* __restrict__ Out)
{
    extern __shared__ float smf[];
    unsigned* Qs    = (unsigned*)smf;           // [64][LQ]
    unsigned* KsBuf = Qs + 64*LQ;               // [2][32][LK]
    unsigned* VsBuf = KsBuf + 2*32*LK;          // [2][32][LV]
    float*    Ps    = (float*)(VsBuf + 2*32*LV);// [64][LP]
    unsigned* Pu    = (unsigned*)Ps;
    float* mrow = Ps + 64*LP;
    float* lrow = mrow + 64;
    float* arow = lrow + 64;

    int tid = threadIdx.x;
    int wid = tid >> 5, lane = tid & 31;
    int lr = lane >> 2, lc = lane & 3;
    int rw = wid >> 1, ch = wid & 1;
    int bk = blockIdx.y;
    int q0 = ((int)gridDim.x - 1 - (int)blockIdx.x) * 64;   // heavy-first

    const float* Qp = Q  + (size_t)bk * SEQ * HD;
    const float* Kp = Kx + (size_t)bk * SEQ * HD;
    const float* Vp = Vx + (size_t)bk * SEQ * HD;

    const int nkt = (q0 + 64) / 32;

    // prologue: prefetch tile 0 K/V into stage 0 (raw 16B, values pre-rounded)
    {
        for (int i = tid; i < 32 * (HD/4); i += 256) {
            int r = i >> 5, cc = (i & 31) * 4;
            unsigned dk = (unsigned)__cvta_generic_to_shared(&KsBuf[r*LK + cc]);
            CPA16(dk, Kp + (size_t)r * HD + cc);
            unsigned dv = (unsigned)__cvta_generic_to_shared(&VsBuf[r*LV + cc]);
            CPA16(dv, Vp + (size_t)r * HD + cc);
        }
        CPA_COMMIT();
    }

    // Q: regular loads (already tf32-rounded)
    for (int i = tid; i < 64 * (HD/4); i += 256) {
        int r = i >> 5, cc = (i & 31) * 4;
        *(uint4*)&Qs[r*LQ + cc] = *(const uint4*)(Qp + (size_t)(q0 + r) * HD + cc);
    }
    if (tid < 64) { mrow[tid] = -1e30f; lrow[tid] = 0.f; }

    float o[8][4];
    #pragma unroll
    for (int j = 0; j < 8; j++)
        #pragma unroll
        for (int e = 0; e < 4; e++) o[j][e] = 0.f;

    const float scale = 0.08838834764831845f;

    for (int kt = 0; kt < nkt; kt++) {
        int stage = kt & 1;
        // prefetch next tile into other stage
        if (kt + 1 < nkt) {
            int ns = (kt + 1) & 1;
            size_t nb = (size_t)(kt + 1) * 32;
            unsigned* Kn = KsBuf + ns*32*LK;
            unsigned* Vn = VsBuf + ns*32*LV;
            for (int i = tid; i < 32 * (HD/4); i += 256) {
                int r = i >> 5, cc = (i & 31) * 4;
                unsigned dk = (unsigned)__cvta_generic_to_shared(&Kn[r*LK + cc]);
                CPA16(dk, Kp + (nb + r) * HD + cc);
                unsigned dv = (unsigned)__cvta_generic_to_shared(&Vn[r*LV + cc]);
                CPA16(dv, Vp + (nb + r) * HD + cc);
            }
            CPA_COMMIT();
            CPA_WAIT1();
        } else {
            CPA_WAIT0();
        }
        __syncthreads();

        unsigned* Ks = KsBuf + stage*32*LK;
        unsigned* Vs = VsBuf + stage*32*LV;
        int kb = kt * 32;

        // ---- S = Q K^T ----
        float s0[4] = {0,0,0,0}, s1[4] = {0,0,0,0};
        {
            int arw = rw*16 + lr;
            int nc0 = ch*16 + lr;
            int nc1 = ch*16 + 8 + lr;
            #pragma unroll
            for (int kk = 0; kk < 16; kk++) {
                int k0 = kk*8;
                unsigned a0 = Qs[arw*LQ + k0 + lc];
                unsigned a1 = Qs[(arw+8)*LQ + k0 + lc];
                unsigned a2 = Qs[arw*LQ + k0 + lc + 4];
                unsigned a3 = Qs[(arw+8)*LQ + k0 + lc + 4];
                unsigned b0 = Ks[nc0*LK + k0 + lc];
                unsigned b1 = Ks[nc0*LK + k0 + lc + 4];
                MMA_TF32(s0[0],s0[1],s0[2],s0[3], a0,a1,a2,a3, b0,b1);
                unsigned c0 = Ks[nc1*LK + k0 + lc];
                unsigned c1 = Ks[nc1*LK + k0 + lc + 4];
                MMA_TF32(s1[0],s1[1],s1[2],s1[3], a0,a1,a2,a3, c0,c1);
            }
            int r0 = rw*16 + lr;
            int cb0 = ch*16 + 2*lc;
            int cb1 = ch*16 + 8 + 2*lc;
            Ps[r0*LP + cb0]     = s0[0]*scale;  Ps[r0*LP + cb0 + 1] = s0[1]*scale;
            Ps[(r0+8)*LP + cb0] = s0[2]*scale;  Ps[(r0+8)*LP + cb0+1] = s0[3]*scale;
            Ps[r0*LP + cb1]     = s1[0]*scale;  Ps[r0*LP + cb1 + 1] = s1[1]*scale;
            Ps[(r0+8)*LP + cb1] = s1[2]*scale;  Ps[(r0+8)*LP + cb1+1] = s1[3]*scale;
        }
        __syncthreads();

        // ---- online softmax: 4 threads/row; write exp back as tf32 bits ----
        {
            int r = tid >> 2, sub = tid & 3;
            int gq = q0 + r;
            int lim = gq - kb;
            int base = sub * 8;
            float pv[8];
            float mx = -1e30f;
            #pragma unroll
            for (int i = 0; i < 8; i++) {
                float v = Ps[r*LP + base + i];
                bool ok = (base + i) <= lim;
                pv[i] = ok ? v : -1e30f;
                mx = fmaxf(mx, pv[i]);
            }
            mx = fmaxf(mx, __shfl_xor_sync(0xffffffffu, mx, 1));
            mx = fmaxf(mx, __shfl_xor_sync(0xffffffffu, mx, 2));
            float mo = mrow[r];
            float mn = fmaxf(mo, mx);
            float al = __expf(mo - mn);
            float ss = 0.f;
            #pragma unroll
            for (int i = 0; i < 8; i++) {
                float e = ((base + i) <= lim) ? __expf(pv[i] - mn) : 0.f;
                Pu[r*LP + base + i] = f2tf(e);
                ss += e;
            }
            ss += __shfl_xor_sync(0xffffffffu, ss, 1);
            ss += __shfl_xor_sync(0xffffffffu, ss, 2);
            if (sub == 0) {
                lrow[r] = lrow[r] * al + ss;
                mrow[r] = mn;
                arow[r] = al;
            }
        }
        __syncthreads();

        // ---- O = O*alpha + P V ----
        {
            float a_lo = arow[rw*16 + lr];
            float a_hi = arow[rw*16 + lr + 8];
            #pragma unroll
            for (int j = 0; j < 8; j++) {
                o[j][0] *= a_lo; o[j][1] *= a_lo;
                o[j][2] *= a_hi; o[j][3] *= a_hi;
            }
            int pr = rw*16 + lr;
            #pragma unroll
            for (int kk = 0; kk < 4; kk++) {
                int k0 = kk*8;
                unsigned a0 = Pu[pr*LP + k0 + lc];
                unsigned a1 = Pu[(pr+8)*LP + k0 + lc];
                unsigned a2 = Pu[pr*LP + k0 + lc + 4];
                unsigned a3 = Pu[(pr+8)*LP + k0 + lc + 4];
                #pragma unroll
                for (int j = 0; j < 8; j++) {
                    int vc = ch*64 + j*8 + lr;
                    unsigned b0 = Vs[(k0 + lc)*LV + vc];
                    unsigned b1 = Vs[(k0 + lc + 4)*LV + vc];
                    MMA_TF32(o[j][0],o[j][1],o[j][2],o[j][3], a0,a1,a2,a3, b0,b1);
                }
            }
        }
        __syncthreads();
    }

    int b = bk >> 3, jslot = bk & 7;
    int r0 = rw*16 + lr;
    int gq0 = q0 + r0, gq1 = q0 + r0 + 8;
    float w_lo = HWp[((size_t)(b*SEQ + gq0)) * KSEL + jslot] / lrow[r0];
    float w_hi = HWp[((size_t)(b*SEQ + gq1)) * KSEL + jslot] / lrow[r0 + 8];
    #pragma unroll
    for (int j = 0; j < 8; j++) {
        int cb = ch*64 + j*8 + 2*lc;
        size_t off0 = (((size_t)(b*SEQ + gq0)) * KSEL + jslot) * HD + cb;
        size_t off1 = (((size_t)(b*SEQ + gq1)) * KSEL + jslot) * HD + cb;
        float2 v0 = make_float2(o[j][0]*w_lo, o[j][1]*w_lo);
        float2 v1 = make_float2(o[j][2]*w_hi, o[j][3]*w_hi);
        *(float2*)&Out[off0] = v0;
        *(float2*)&Out[off1] = v1;
    }
}

// ---------------- aux loss + head_counts tail ----------------
__global__ void finalize_kernel(float* __restrict__ out, int out_size) {
    int base = NTOK * EMB;
    int extra = out_size - base;
    if (extra <= 0) return;
    bool has_aux = (extra == BATCH*NH + 1) || (extra == 1);
    int zend = has_aux ? out_size - 1 : out_size;
    int gtid = blockIdx.x * blockDim.x + threadIdx.x;
    for (int i = base + gtid; i < zend; i += gridDim.x * blockDim.x) out[i] = 0.f;
    if (gtid == 0 && has_aux) {
        float aux = 0.f;
        for (int b = 0; b < BATCH; b++) {
            float sb = 0.f;
            for (int h = 0; h < NH; h++)
                sb += (g_facc[b*NH + h] / (float)SEQ) * (g_pacc[b*NH + h] / (float)SEQ);
            aux += sb;
        }
        aux = (float)NH * aux / (float)BATCH - 0.01f * (g_ent[0] / (float)(BATCH*SEQ));
        out[out_size - 1] = aux;
    }
}

// ---------------- launcher ----------------
extern "C" void kernel_launch(void* const* d_in, const int* in_sizes, int n_in,
                              void* d_out, int out_size)
{
    (void)in_sizes; (void)n_in;
    const float* x  = (const float*)d_in[0];
    const float* Wq = (const float*)d_in[1];
    const float* Wk = (const float*)d_in[2];
    const float* Wv = (const float*)d_in[3];
    const float* Wr = (const float*)d_in[4];
    const float* Wo = (const float*)d_in[5];
    float* out = (float*)d_out;

    float *p_q, *p_k, *p_v, *p_attn, *p_hw;
    cudaGetSymbolAddress((void**)&p_q,    g_q);
    cudaGetSymbolAddress((void**)&p_k,    g_k);
    cudaGetSymbolAddress((void**)&p_v,    g_v);
    cudaGetSymbolAddress((void**)&p_attn, g_attn);
    cudaGetSymbolAddress((void**)&p_hw,   g_hw);

    size_t gemm_smem = (size_t)(2*BM*LDA + 2*BKt*LDB) * sizeof(float);
    cudaFuncSetAttribute(moh_proj_kernel, cudaFuncAttributeMaxDynamicSharedMemorySize,
                         (int)gemm_smem);
    cudaFuncSetAttribute(tf32_gemm_kernel, cudaFuncAttributeMaxDynamicSharedMemorySize,
                         (int)gemm_smem);
    size_t flash_smem = (size_t)(64*LQ + 2*32*LK + 2*32*LV + 64*LP + 3*64) * sizeof(float);
    cudaFuncSetAttribute(flash_tc_kernel, cudaFuncAttributeMaxDynamicSharedMemorySize,
                         (int)flash_smem);

    zero_stats_kernel<<<1, 128>>>();
    router_kernel<<<NTOK, 32>>>(x, Wr);

    dim3 gproj(NTOK/BM, NH, 3);
    moh_proj_kernel<<<gproj, 256, gemm_smem>>>(x, Wq, Wk, Wv, p_q, p_k, p_v);

    dim3 gflash(SEQ/64, BATCH*KSEL);
    flash_tc_kernel<<<gflash, 256, flash_smem>>>(p_q, p_k, p_v, p_hw, p_attn);

    dim3 gout(EMB/BN, NTOK/BM);
    tf32_gemm_kernel<<<gout, 256, gemm_smem>>>(p_attn, Wo, out, NTOK, EMB, EMB);

    finalize_kernel<<<32, 256>>>(out, out_size);
}

// round 13
// speedup vs baseline: 3.9335x; 1.0224x over previous
#include <cuda_runtime.h>
#include <mma.h>
#include <math.h>

using namespace nvcuda;

#define BATCH 2
#define SEQ   2048
#define EMB   1024
#define NH    32
#define KSEL  8
#define HD    128
#define NTOK  (BATCH*SEQ)      // 4096
#define HDALL (NH*HD)          // 4096
#define KD    (KSEL*HD)        // 1024

// ---------------- scratch ----------------
__device__ float g_q[(size_t)BATCH*KSEL*SEQ*HD];   // [B*K, S, D] (tf32-rounded)
__device__ float g_k[(size_t)BATCH*KSEL*SEQ*HD];
__device__ float g_v[(size_t)BATCH*KSEL*SEQ*HD];
__device__ float g_attn[(size_t)NTOK*KD];          // [B,S,K,D]
__device__ int   g_list[NH*NTOK];
__device__ int   g_cnt[NH];
__device__ float g_hw[NTOK*KSEL];
__device__ float g_pacc[BATCH*NH];
__device__ float g_facc[BATCH*NH];
__device__ float g_ent[1];

__device__ __forceinline__ unsigned f2tf(float f) {
    unsigned u;
    asm("cvt.rna.tf32.f32 %0, %1;\n" : "=r"(u) : "f"(f));
    return u;
}
__device__ __forceinline__ float tfround(float f) {
    return __uint_as_float(f2tf(f));
}

__global__ void zero_stats_kernel() {
    int t = threadIdx.x;
    if (t < BATCH*NH) { g_pacc[t] = 0.f; g_facc[t] = 0.f; }
    if (t < NH) g_cnt[t] = 0;
    if (t == 0) g_ent[0] = 0.f;
}

// ---------------- router ----------------
__global__ void router_kernel(const float* __restrict__ x, const float* __restrict__ Wr) {
    __shared__ float xs[EMB];
    __shared__ float lg[NH];
    int tok = blockIdx.x;
    int tid = threadIdx.x;
    const float* xr = x + (size_t)tok * EMB;
    for (int e = tid; e < EMB; e += 32) xs[e] = xr[e];
    __syncwarp();
    float acc = 0.f;
    #pragma unroll 8
    for (int e = 0; e < EMB; e++) acc += xs[e] * Wr[e*NH + tid];
    lg[tid] = acc;
    float m = acc;
    #pragma unroll
    for (int o = 16; o; o >>= 1) m = fmaxf(m, __shfl_xor_sync(0xffffffffu, m, o));
    float ex = expf(acc - m);
    float sum = ex;
    #pragma unroll
    for (int o = 16; o; o >>= 1) sum += __shfl_xor_sync(0xffffffffu, sum, o);
    float p = ex / sum;
    int b = tok / SEQ;
    atomicAdd(&g_pacc[b*NH + tid], p);
    float term = p * logf(p + 1e-8f);
    float esum = term;
    #pragma unroll
    for (int o = 16; o; o >>= 1) esum += __shfl_xor_sync(0xffffffffu, esum, o);
    if (tid == 0) atomicAdd(&g_ent[0], -esum);
    __syncwarp();
    if (tid == 0) {
        float tl[KSEL]; int ti[KSEL];
        unsigned mask = 0;
        for (int k = 0; k < KSEL; k++) {
            float best = -1e30f; int bi = 0;
            for (int h = 0; h < NH; h++)
                if (!((mask >> h) & 1u) && lg[h] > best) { best = lg[h]; bi = h; }
            mask |= 1u << bi; tl[k] = best; ti[k] = bi;
        }
        float ws = 0.f, w[KSEL];
        for (int k = 0; k < KSEL; k++) { w[k] = expf(tl[k] - tl[0]); ws += w[k]; }
        for (int k = 0; k < KSEL; k++) {
            g_hw[tok*KSEL + k] = w[k] / ws;
            int h = ti[k];
            int pos = atomicAdd(&g_cnt[h], 1);
            g_list[h*NTOK + pos] = (tok << 3) | k;
        }
        atomicAdd(&g_facc[b*NH + ti[0]], 1.0f);
    }
}

// ---------------- GEMM common ----------------
#define BM 128
#define BN 128
#define BKt 32
#define LDA 36
#define LDB 132
#define LDC 132

#define CPA16(dst, src) asm volatile("cp.async.cg.shared.global [%0], [%1], 16;\n" \
        :: "r"(dst), "l"(src))
#define CPA_COMMIT() asm volatile("cp.async.commit_group;\n")
#define CPA_WAIT1()  asm volatile("cp.async.wait_group 1;\n")
#define CPA_WAIT0()  asm volatile("cp.async.wait_group 0;\n")

// ---------------- grouped TF32 projection GEMM (q,k,v fused; rope fused; tf32-round) ----
__global__ void __launch_bounds__(256, 2) moh_proj_kernel(
    const float* __restrict__ x,
    const float* __restrict__ Wq, const float* __restrict__ Wk, const float* __restrict__ Wv,
    float* __restrict__ dq, float* __restrict__ dk, float* __restrict__ dv)
{
    int h = blockIdx.y;
    int cnt = g_cnt[h];
    int m0 = blockIdx.x * BM;
    if (m0 >= cnt) return;
    int rows = min(BM, cnt - m0);
    int z = blockIdx.z;
    const float* W = (z == 0) ? Wq : (z == 1) ? Wk : Wv;
    float* dst     = (z == 0) ? dq : (z == 1) ? dk : dv;

    extern __shared__ float sm[];
    float* As[2] = { sm, sm + BM*LDA };
    float* Bs[2] = { sm + 2*BM*LDA, sm + 2*BM*LDA + BKt*LDB };
    float* Csm   = sm;
    __shared__ int s_pk[BM];

    int tid = threadIdx.x;
    if (tid < BM) {
        int r = tid < rows ? tid : rows - 1;
        s_pk[tid] = g_list[h*NTOK + m0 + r];
    }
    __syncthreads();

    int wid = tid >> 5;
    int wm = wid >> 2, wn = wid & 3;
    int col0 = h * HD;

    int ar[4], ac[4], br[4], bc[4];
    const float* abase[4];
    #pragma unroll
    for (int i = 0; i < 4; i++) {
        int idx = tid + i*256;
        ar[i] = idx >> 3;  ac[i] = (idx & 7) * 4;
        br[i] = idx >> 5;  bc[i] = (idx & 31) * 4;
        abase[i] = x + (size_t)(s_pk[ar[i]] >> 3) * EMB + ac[i];
    }

    wmma::fragment<wmma::accumulator, 16, 16, 8, float> cfr[4][2];
    #pragma unroll
    for (int i = 0; i < 4; i++)
        #pragma unroll
        for (int j = 0; j < 2; j++) wmma::fill_fragment(cfr[i][j], 0.0f);

    const int ntiles = EMB / BKt;
    #pragma unroll
    for (int i = 0; i < 4; i++) {
        unsigned da = (unsigned)__cvta_generic_to_shared(As[0] + ar[i]*LDA + ac[i]);
        CPA16(da, abase[i]);
        unsigned db = (unsigned)__cvta_generic_to_shared(Bs[0] + br[i]*LDB + bc[i]);
        CPA16(db, W + (size_t)br[i] * HDALL + col0 + bc[i]);
    }
    CPA_COMMIT();

    for (int t = 0; t < ntiles; t++) {
        int buf = t & 1;
        if (t + 1 < ntiles) {
            int nb = (t + 1) & 1;
            int k0 = (t + 1) * BKt;
            #pragma unroll
            for (int i = 0; i < 4; i++) {
                unsigned da = (unsigned)__cvta_generic_to_shared(As[nb] + ar[i]*LDA + ac[i]);
                CPA16(da, abase[i] + k0);
                unsigned db = (unsigned)__cvta_generic_to_shared(Bs[nb] + br[i]*LDB + bc[i]);
                CPA16(db, W + (size_t)(k0 + br[i]) * HDALL + col0 + bc[i]);
            }
            CPA_COMMIT();
            CPA_WAIT1();
        } else {
            CPA_WAIT0();
        }
        __syncthreads();

        float* Ab = As[buf];
        float* Bb = Bs[buf];
        #pragma unroll
        for (int kk = 0; kk < BKt/8; kk++) {
            wmma::fragment<wmma::matrix_a, 16, 16, 8, wmma::precision::tf32, wmma::row_major> af[4];
            wmma::fragment<wmma::matrix_b, 16, 16, 8, wmma::precision::tf32, wmma::row_major> bf[2];
            #pragma unroll
            for (int i = 0; i < 4; i++) {
                wmma::load_matrix_sync(af[i], Ab + (wm*64 + i*16)*LDA + kk*8, LDA);
                #pragma unroll
                for (int e = 0; e < af[i].num_elements; e++)
                    af[i].x[e] = wmma::__float_to_tf32(af[i].x[e]);
            }
            #pragma unroll
            for (int j = 0; j < 2; j++) {
                wmma::load_matrix_sync(bf[j], Bb + kk*8*LDB + wn*32 + j*16, LDB);
                #pragma unroll
                for (int e = 0; e < bf[j].num_elements; e++)
                    bf[j].x[e] = wmma::__float_to_tf32(bf[j].x[e]);
            }
            #pragma unroll
            for (int i = 0; i < 4; i++)
                #pragma unroll
                for (int j = 0; j < 2; j++)
                    wmma::mma_sync(cfr[i][j], af[i], bf[j], cfr[i][j]);
        }
        __syncthreads();
    }

    #pragma unroll
    for (int i = 0; i < 4; i++)
        #pragma unroll
        for (int j = 0; j < 2; j++)
            wmma::store_matrix_sync(Csm + (wm*64 + i*16)*LDC + wn*32 + j*16,
                                    cfr[i][j], LDC, wmma::mem_row_major);
    __syncthreads();

    if (z < 2) {
        for (int i = tid; i < BM * 16; i += 256) {
            int row = i >> 4;
            if (row >= rows) break;
            int c4 = (i & 15) * 4;
            int pk = s_pk[row];
            int tok = pk >> 3, j = pk & 7;
            int b = tok / SEQ, s = tok % SEQ;
            float4 lo = *(float4*)&Csm[row*LDC + c4];
            float4 hi = *(float4*)&Csm[row*LDC + c4 + 64];
            float4 olo, ohi;
            float fs = (float)s;
            {
                float cc, sn, ang;
                ang = fs * powf(10000.0f, -(float)(c4+0) / 64.0f);
                cc = cosf(ang); sn = sinf(ang);
                olo.x = tfround(lo.x*cc - hi.x*sn);  ohi.x = tfround(hi.x*cc + lo.x*sn);
                ang = fs * powf(10000.0f, -(float)(c4+1) / 64.0f);
                cc = cosf(ang); sn = sinf(ang);
                olo.y = tfround(lo.y*cc - hi.y*sn);  ohi.y = tfround(hi.y*cc + lo.y*sn);
                ang = fs * powf(10000.0f, -(float)(c4+2) / 64.0f);
                cc = cosf(ang); sn = sinf(ang);
                olo.z = tfround(lo.z*cc - hi.z*sn);  ohi.z = tfround(hi.z*cc + lo.z*sn);
                ang = fs * powf(10000.0f, -(float)(c4+3) / 64.0f);
                cc = cosf(ang); sn = sinf(ang);
                olo.w = tfround(lo.w*cc - hi.w*sn);  ohi.w = tfround(hi.w*cc + lo.w*sn);
            }
            size_t off = (((size_t)(b*KSEL + j)) * SEQ + s) * HD;
            *(float4*)&dst[off + c4]      = olo;
            *(float4*)&dst[off + c4 + 64] = ohi;
        }
    } else {
        for (int i = tid; i < BM * (HD/4); i += 256) {
            int row = i >> 5;
            if (row >= rows) break;
            int c = (i & 31) * 4;
            int pk = s_pk[row];
            int tok = pk >> 3, j = pk & 7;
            int b = tok / SEQ, s = tok % SEQ;
            float4 v = *(float4*)&Csm[row*LDC + c];
            v.x = tfround(v.x); v.y = tfround(v.y);
            v.z = tfround(v.z); v.w = tfround(v.w);
            size_t off = (((size_t)(b*KSEL + j)) * SEQ + s) * HD + c;
            *(float4*)&dst[off] = v;
        }
    }
}

// ---------------- dense TF32 GEMM (Wo) ----------------
__global__ void __launch_bounds__(256, 2) tf32_gemm_kernel(
    const float* __restrict__ A, const float* __restrict__ Bm, float* __restrict__ C,
    int M, int N, int Kd)
{
    extern __shared__ float sm[];
    float* As[2] = { sm, sm + BM*LDA };
    float* Bs[2] = { sm + 2*BM*LDA, sm + 2*BM*LDA + BKt*LDB };

    int tid = threadIdx.x;
    int wid = tid >> 5;
    int wm = wid >> 2, wn = wid & 3;
    int row0 = blockIdx.y * BM, col0 = blockIdx.x * BN;

    int ar[4], ac[4], br[4], bc[4];
    #pragma unroll
    for (int i = 0; i < 4; i++) {
        int idx = tid + i*256;
        ar[i] = idx >> 3;  ac[i] = (idx & 7) * 4;
        br[i] = idx >> 5;  bc[i] = (idx & 31) * 4;
    }

    wmma::fragment<wmma::accumulator, 16, 16, 8, float> cfr[4][2];
    #pragma unroll
    for (int i = 0; i < 4; i++)
        #pragma unroll
        for (int j = 0; j < 2; j++) wmma::fill_fragment(cfr[i][j], 0.0f);

    int ntiles = Kd / BKt;
    #pragma unroll
    for (int i = 0; i < 4; i++) {
        unsigned da = (unsigned)__cvta_generic_to_shared(As[0] + ar[i]*LDA + ac[i]);
        CPA16(da, A + (size_t)(row0 + ar[i]) * Kd + ac[i]);
        unsigned db = (unsigned)__cvta_generic_to_shared(Bs[0] + br[i]*LDB + bc[i]);
        CPA16(db, Bm + (size_t)br[i] * N + col0 + bc[i]);
    }
    CPA_COMMIT();

    for (int t = 0; t < ntiles; t++) {
        int buf = t & 1;
        if (t + 1 < ntiles) {
            int nb = (t + 1) & 1;
            int k0 = (t + 1) * BKt;
            #pragma unroll
            for (int i = 0; i < 4; i++) {
                unsigned da = (unsigned)__cvta_generic_to_shared(As[nb] + ar[i]*LDA + ac[i]);
                CPA16(da, A + (size_t)(row0 + ar[i]) * Kd + k0 + ac[i]);
                unsigned db = (unsigned)__cvta_generic_to_shared(Bs[nb] + br[i]*LDB + bc[i]);
                CPA16(db, Bm + (size_t)(k0 + br[i]) * N + col0 + bc[i]);
            }
            CPA_COMMIT();
            CPA_WAIT1();
        } else {
            CPA_WAIT0();
        }
        __syncthreads();

        float* Ab = As[buf];
        float* Bb = Bs[buf];
        #pragma unroll
        for (int kk = 0; kk < BKt/8; kk++) {
            wmma::fragment<wmma::matrix_a, 16, 16, 8, wmma::precision::tf32, wmma::row_major> af[4];
            wmma::fragment<wmma::matrix_b, 16, 16, 8, wmma::precision::tf32, wmma::row_major> bf[2];
            #pragma unroll
            for (int i = 0; i < 4; i++) {
                wmma::load_matrix_sync(af[i], Ab + (wm*64 + i*16)*LDA + kk*8, LDA);
                #pragma unroll
                for (int e = 0; e < af[i].num_elements; e++)
                    af[i].x[e] = wmma::__float_to_tf32(af[i].x[e]);
            }
            #pragma unroll
            for (int j = 0; j < 2; j++) {
                wmma::load_matrix_sync(bf[j], Bb + kk*8*LDB + wn*32 + j*16, LDB);
                #pragma unroll
                for (int e = 0; e < bf[j].num_elements; e++)
                    bf[j].x[e] = wmma::__float_to_tf32(bf[j].x[e]);
            }
            #pragma unroll
            for (int i = 0; i < 4; i++)
                #pragma unroll
                for (int j = 0; j < 2; j++)
                    wmma::mma_sync(cfr[i][j], af[i], bf[j], cfr[i][j]);
        }
        __syncthreads();
    }

    #pragma unroll
    for (int i = 0; i < 4; i++)
        #pragma unroll
        for (int j = 0; j < 2; j++)
            wmma::store_matrix_sync(
                C + (size_t)(row0 + wm*64 + i*16) * N + col0 + wn*32 + j*16,
                cfr[i][j], N, wmma::mem_row_major);
}

// ---------------- TF32 flash attention, warp-row-ownership (Br=128, Bc=32) ------
// Each warp owns 16 full rows: softmax state in registers, 2 syncthreads/tile.
#define LQ 132
#define LK 132
#define LV 136
#define LP 36

#define MMA_TF32(c0,c1,c2,c3,a0,a1,a2,a3,b0,b1) \
    asm volatile("mma.sync.aligned.m16n8k8.row.col.f32.tf32.tf32.f32 " \
        "{%0,%1,%2,%3}, {%4,%5,%6,%7}, {%8,%9}, {%0,%1,%2,%3};\n" \
        : "+f"(c0), "+f"(c1), "+f"(c2), "+f"(c3) \
        : "r"(a0), "r"(a1), "r"(a2), "r"(a3), "r"(b0), "r"(b1))

__global__ void __launch_bounds__(256, 1) flash_tc_kernel(
    const float* __restrict__ Q, const float* __restrict__ Kx, const float* __restrict__ Vx,
    const float* __restrict__ HWp, float* __restrict__ Out)
{
    extern __shared__ float smf[];
    unsigned* Qs    = (unsigned*)smf;           // [128][LQ]
    unsigned* KsBuf = Qs + 128*LQ;              // [2][32][LK]
    unsigned* VsBuf = KsBuf + 2*32*LK;          // [2][32][LV]
    unsigned* Pu    = VsBuf + 2*32*LV;          // [128][LP]

    int tid = threadIdx.x;
    int wid = tid >> 5, lane = tid & 31;
    int lr = lane >> 2, lc = lane & 3;
    int bk = blockIdx.y;
    int q0 = ((int)gridDim.x - 1 - (int)blockIdx.x) * 128;   // heavy-first

    const float* Qp = Q  + (size_t)bk * SEQ * HD;
    const float* Kp = Kx + (size_t)bk * SEQ * HD;
    const float* Vp = Vx + (size_t)bk * SEQ * HD;

    const int nkt = q0/32 + 4;
    const int rbase = wid*16 + lr;             // this thread's row pair: rbase, rbase+8
    const int gq0 = q0 + rbase, gq1 = gq0 + 8;

    // prefetch K/V tile 0 into stage 0
    for (int i = tid; i < 32 * (HD/4); i += 256) {
        int r = i >> 5, cc = (i & 31) * 4;
        unsigned dk = (unsigned)__cvta_generic_to_shared(&KsBuf[r*LK + cc]);
        CPA16(dk, Kp + (size_t)r * HD + cc);
        unsigned dv = (unsigned)__cvta_generic_to_shared(&VsBuf[r*LV + cc]);
        CPA16(dv, Vp + (size_t)r * HD + cc);
    }
    CPA_COMMIT();

    // load Q (pre-rounded tf32 bits)
    for (int i = tid; i < 128 * (HD/4); i += 256) {
        int r = i >> 5, cc = (i & 31) * 4;
        *(uint4*)&Qs[r*LQ + cc] = *(const uint4*)(Qp + (size_t)(q0 + r) * HD + cc);
    }

    float o[16][4];
    #pragma unroll
    for (int j = 0; j < 16; j++)
        #pragma unroll
        for (int e = 0; e < 4; e++) o[j][e] = 0.f;
    float m0 = -1e30f, m1 = -1e30f, l0 = 0.f, l1 = 0.f;

    const float scale = 0.08838834764831845f;

    for (int kt = 0; kt < nkt; kt++) {
        int stage = kt & 1;
        __syncthreads();   // all warps done reading stage^1 (prev PV) -> safe to overwrite
        if (kt + 1 < nkt) {
            int ns = stage ^ 1;
            size_t nb = (size_t)(kt + 1) * 32;
            unsigned* Kn = KsBuf + ns*32*LK;
            unsigned* Vn = VsBuf + ns*32*LV;
            for (int i = tid; i < 32 * (HD/4); i += 256) {
                int r = i >> 5, cc = (i & 31) * 4;
                unsigned dk = (unsigned)__cvta_generic_to_shared(&Kn[r*LK + cc]);
                CPA16(dk, Kp + (nb + r) * HD + cc);
                unsigned dv = (unsigned)__cvta_generic_to_shared(&Vn[r*LV + cc]);
                CPA16(dv, Vp + (nb + r) * HD + cc);
            }
            CPA_COMMIT();
            CPA_WAIT1();
        } else {
            CPA_WAIT0();
        }
        __syncthreads();   // tile kt's K/V visible to all

        unsigned* Ks = KsBuf + stage*32*LK;
        unsigned* Vs = VsBuf + stage*32*LV;
        int kb = kt * 32;

        // ---- S = Q K^T : warp computes its 16 rows x 32 cols (4 n-tiles) ----
        float s[4][4];
        #pragma unroll
        for (int nt = 0; nt < 4; nt++)
            #pragma unroll
            for (int e = 0; e < 4; e++) s[nt][e] = 0.f;
        #pragma unroll
        for (int kk = 0; kk < 16; kk++) {
            int k0 = kk*8;
            unsigned a0 = Qs[rbase*LQ + k0 + lc];
            unsigned a1 = Qs[(rbase+8)*LQ + k0 + lc];
            unsigned a2 = Qs[rbase*LQ + k0 + lc + 4];
            unsigned a3 = Qs[(rbase+8)*LQ + k0 + lc + 4];
            #pragma unroll
            for (int nt = 0; nt < 4; nt++) {
                int nc = nt*8 + lr;
                unsigned b0 = Ks[nc*LK + k0 + lc];
                unsigned b1 = Ks[nc*LK + k0 + lc + 4];
                MMA_TF32(s[nt][0],s[nt][1],s[nt][2],s[nt][3], a0,a1,a2,a3, b0,b1);
            }
        }

        // ---- warp-local online softmax (regs); write P as tf32 bits ----
        {
            int lim0 = gq0 - kb;               // valid col <= lim
            int lim1 = gq1 - kb;
            float p0[8], p1[8];
            float mx0 = -1e30f, mx1 = -1e30f;
            #pragma unroll
            for (int nt = 0; nt < 4; nt++) {
                int c0 = nt*8 + 2*lc, c1 = c0 + 1;
                p0[nt*2]   = (c0 <= lim0) ? s[nt][0]*scale : -1e30f;
                p0[nt*2+1] = (c1 <= lim0) ? s[nt][1]*scale : -1e30f;
                p1[nt*2]   = (c0 <= lim1) ? s[nt][2]*scale : -1e30f;
                p1[nt*2+1] = (c1 <= lim1) ? s[nt][3]*scale : -1e30f;
                mx0 = fmaxf(mx0, fmaxf(p0[nt*2], p0[nt*2+1]));
                mx1 = fmaxf(mx1, fmaxf(p1[nt*2], p1[nt*2+1]));
            }
            mx0 = fmaxf(mx0, __shfl_xor_sync(0xffffffffu, mx0, 1));
            mx0 = fmaxf(mx0, __shfl_xor_sync(0xffffffffu, mx0, 2));
            mx1 = fmaxf(mx1, __shfl_xor_sync(0xffffffffu, mx1, 1));
            mx1 = fmaxf(mx1, __shfl_xor_sync(0xffffffffu, mx1, 2));
            float mn0 = fmaxf(m0, mx0), mn1 = fmaxf(m1, mx1);
            float al0 = __expf(m0 - mn0), al1 = __expf(m1 - mn1);
            float ss0 = 0.f, ss1 = 0.f;
            #pragma unroll
            for (int nt = 0; nt < 4; nt++) {
                int c0 = nt*8 + 2*lc, c1 = c0 + 1;
                float e00 = (c0 <= lim0) ? __expf(p0[nt*2]   - mn0) : 0.f;
                float e01 = (c1 <= lim0) ? __expf(p0[nt*2+1] - mn0) : 0.f;
                float e10 = (c0 <= lim1) ? __expf(p1[nt*2]   - mn1) : 0.f;
                float e11 = (c1 <= lim1) ? __expf(p1[nt*2+1] - mn1) : 0.f;
                Pu[rbase*LP + c0]     = f2tf(e00);
                Pu[rbase*LP + c1]     = f2tf(e01);
                Pu[(rbase+8)*LP + c0] = f2tf(e10);
                Pu[(rbase+8)*LP + c1] = f2tf(e11);
                ss0 += e00 + e01;
                ss1 += e10 + e11;
            }
            ss0 += __shfl_xor_sync(0xffffffffu, ss0, 1);
            ss0 += __shfl_xor_sync(0xffffffffu, ss0, 2);
            ss1 += __shfl_xor_sync(0xffffffffu, ss1, 1);
            ss1 += __shfl_xor_sync(0xffffffffu, ss1, 2);
            l0 = l0 * al0 + ss0;  m0 = mn0;
            l1 = l1 * al1 + ss1;  m1 = mn1;
            // rescale O
            #pragma unroll
            for (int j = 0; j < 16; j++) {
                o[j][0] *= al0; o[j][1] *= al0;
                o[j][2] *= al1; o[j][3] *= al1;
            }
        }
        __syncwarp();

        // ---- O += P V  (warp-local P rows, full D width) ----
        #pragma unroll
        for (int kk = 0; kk < 4; kk++) {
            int k0 = kk*8;
            unsigned a0 = Pu[rbase*LP + k0 + lc];
            unsigned a1 = Pu[(rbase+8)*LP + k0 + lc];
            unsigned a2 = Pu[rbase*LP + k0 + lc + 4];
            unsigned a3 = Pu[(rbase+8)*LP + k0 + lc + 4];
            #pragma unroll
            for (int j = 0; j < 16; j++) {
                int vc = j*8 + lr;
                unsigned b0 = Vs[(k0 + lc)*LV + vc];
                unsigned b1 = Vs[(k0 + lc + 4)*LV + vc];
                MMA_TF32(o[j][0],o[j][1],o[j][2],o[j][3], a0,a1,a2,a3, b0,b1);
            }
        }
        // no trailing sync: next iteration's first __syncthreads protects stage reuse
    }

    // ---- epilogue ----
    int b = bk >> 3, jslot = bk & 7;
    float w_lo = HWp[((size_t)(b*SEQ + gq0)) * KSEL + jslot] / l0;
    float w_hi = HWp[((size_t)(b*SEQ + gq1)) * KSEL + jslot] / l1;
    #pragma unroll
    for (int j = 0; j < 16; j++) {
        int cb = j*8 + 2*lc;
        size_t off0 = (((size_t)(b*SEQ + gq0)) * KSEL + jslot) * HD + cb;
        size_t off1 = (((size_t)(b*SEQ + gq1)) * KSEL + jslot) * HD + cb;
        float2 v0 = make_float2(o[j][0]*w_lo, o[j][1]*w_lo);
        float2 v1 = make_float2(o[j][2]*w_hi, o[j][3]*w_hi);
        *(float2*)&Out[off0] = v0;
        *(float2*)&Out[off1] = v1;
    }
}

// ---------------- aux loss + head_counts tail ----------------
__global__ void finalize_kernel(float* __restrict__ out, int out_size) {
    int base = NTOK * EMB;
    int extra = out_size - base;
    if (extra <= 0) return;
    bool has_aux = (extra == BATCH*NH + 1) || (extra == 1);
    int zend = has_aux ? out_size - 1 : out_size;
    int gtid = blockIdx.x * blockDim.x + threadIdx.x;
    for (int i = base + gtid; i < zend; i += gridDim.x * blockDim.x) out[i] = 0.f;
    if (gtid == 0 && has_aux) {
        float aux = 0.f;
        for (int b = 0; b < BATCH; b++) {
            float sb = 0.f;
            for (int h = 0; h < NH; h++)
                sb += (g_facc[b*NH + h] / (float)SEQ) * (g_pacc[b*NH + h] / (float)SEQ);
            aux += sb;
        }
        aux = (float)NH * aux / (float)BATCH - 0.01f * (g_ent[0] / (float)(BATCH*SEQ));
        out[out_size - 1] = aux;
    }
}

// ---------------- launcher ----------------
extern "C" void kernel_launch(void* const* d_in, const int* in_sizes, int n_in,
                              void* d_out, int out_size)
{
    (void)in_sizes; (void)n_in;
    const float* x  = (const float*)d_in[0];
    const float* Wq = (const float*)d_in[1];
    const float* Wk = (const float*)d_in[2];
    const float* Wv = (const float*)d_in[3];
    const float* Wr = (const float*)d_in[4];
    const float* Wo = (const float*)d_in[5];
    float* out = (float*)d_out;

    float *p_q, *p_k, *p_v, *p_attn, *p_hw;
    cudaGetSymbolAddress((void**)&p_q,    g_q);
    cudaGetSymbolAddress((void**)&p_k,    g_k);
    cudaGetSymbolAddress((void**)&p_v,    g_v);
    cudaGetSymbolAddress((void**)&p_attn, g_attn);
    cudaGetSymbolAddress((void**)&p_hw,   g_hw);

    size_t gemm_smem = (size_t)(2*BM*LDA + 2*BKt*LDB) * sizeof(float);
    cudaFuncSetAttribute(moh_proj_kernel, cudaFuncAttributeMaxDynamicSharedMemorySize,
                         (int)gemm_smem);
    cudaFuncSetAttribute(tf32_gemm_kernel, cudaFuncAttributeMaxDynamicSharedMemorySize,
                         (int)gemm_smem);
    size_t flash_smem = (size_t)(128*LQ + 2*32*LK + 2*32*LV + 128*LP) * sizeof(float);
    cudaFuncSetAttribute(flash_tc_kernel, cudaFuncAttributeMaxDynamicSharedMemorySize,
                         (int)flash_smem);

    zero_stats_kernel<<<1, 128>>>();
    router_kernel<<<NTOK, 32>>>(x, Wr);

    dim3 gproj(NTOK/BM, NH, 3);
    moh_proj_kernel<<<gproj, 256, gemm_smem>>>(x, Wq, Wk, Wv, p_q, p_k, p_v);

    dim3 gflash(SEQ/128, BATCH*KSEL);   // (16, 16)
    flash_tc_kernel<<<gflash, 256, flash_smem>>>(p_q, p_k, p_v, p_hw, p_attn);

    dim3 gout(EMB/BN, NTOK/BM);
    tf32_gemm_kernel<<<gout, 256, gemm_smem>>>(p_attn, Wo, out, NTOK, EMB, EMB);

    finalize_kernel<<<32, 256>>>(out, out_size);
}

// round 14
// speedup vs baseline: 5.4298x; 1.3804x over previous
#include <cuda_runtime.h>
#include <math.h>

#define BATCH 2
#define SEQ   2048
#define EMB   1024
#define NH    32
#define KSEL  8
#define HD    128
#define NTOK  (BATCH*SEQ)      // 4096
#define HDALL (NH*HD)          // 4096
#define KD    (KSEL*HD)        // 1024

// ---------------- scratch ----------------
__device__ float g_q[(size_t)BATCH*KSEL*SEQ*HD];   // [B*K, S, D] (tf32-rounded)
__device__ float g_k[(size_t)BATCH*KSEL*SEQ*HD];
__device__ float g_v[(size_t)BATCH*KSEL*SEQ*HD];
__device__ float g_attn[(size_t)NTOK*KD];          // [B,S,K,D] (tf32-rounded)
__device__ float g_xr[(size_t)NTOK*EMB];           // tf32-rounded x
__device__ float g_wq[(size_t)EMB*HDALL];          // tf32-rounded weights
__device__ float g_wk[(size_t)EMB*HDALL];
__device__ float g_wv[(size_t)EMB*HDALL];
__device__ float g_wo[(size_t)KD*EMB];
__device__ int   g_list[NH*NTOK];
__device__ int   g_cnt[NH];
__device__ float g_hw[NTOK*KSEL];
__device__ float g_pacc[BATCH*NH];
__device__ float g_facc[BATCH*NH];
__device__ float g_ent[1];

__device__ __forceinline__ unsigned f2tf(float f) {
    unsigned u;
    asm("cvt.rna.tf32.f32 %0, %1;\n" : "=r"(u) : "f"(f));
    return u;
}
__device__ __forceinline__ float tfround(float f) {
    return __uint_as_float(f2tf(f));
}

__global__ void zero_stats_kernel() {
    int t = threadIdx.x;
    if (t < BATCH*NH) { g_pacc[t] = 0.f; g_facc[t] = 0.f; }
    if (t < NH) g_cnt[t] = 0;
    if (t == 0) g_ent[0] = 0.f;
}

// ---------------- tf32 pre-round pass ----------------
__global__ void tfround_kernel(const float4* __restrict__ src, float4* __restrict__ dst, int n4) {
    int i = blockIdx.x * blockDim.x + threadIdx.x;
    for (; i < n4; i += gridDim.x * blockDim.x) {
        float4 v = src[i];
        v.x = tfround(v.x); v.y = tfround(v.y);
        v.z = tfround(v.z); v.w = tfround(v.w);
        dst[i] = v;
    }
}

// ---------------- router (reads original fp32 x) ----------------
__global__ void router_kernel(const float* __restrict__ x, const float* __restrict__ Wr) {
    __shared__ float xs[EMB];
    __shared__ float lg[NH];
    int tok = blockIdx.x;
    int tid = threadIdx.x;
    const float* xr = x + (size_t)tok * EMB;
    for (int e = tid; e < EMB; e += 32) xs[e] = xr[e];
    __syncwarp();
    float acc = 0.f;
    #pragma unroll 8
    for (int e = 0; e < EMB; e++) acc += xs[e] * Wr[e*NH + tid];
    lg[tid] = acc;
    float m = acc;
    #pragma unroll
    for (int o = 16; o; o >>= 1) m = fmaxf(m, __shfl_xor_sync(0xffffffffu, m, o));
    float ex = expf(acc - m);
    float sum = ex;
    #pragma unroll
    for (int o = 16; o; o >>= 1) sum += __shfl_xor_sync(0xffffffffu, sum, o);
    float p = ex / sum;
    int b = tok / SEQ;
    atomicAdd(&g_pacc[b*NH + tid], p);
    float term = p * logf(p + 1e-8f);
    float esum = term;
    #pragma unroll
    for (int o = 16; o; o >>= 1) esum += __shfl_xor_sync(0xffffffffu, esum, o);
    if (tid == 0) atomicAdd(&g_ent[0], -esum);
    __syncwarp();
    if (tid == 0) {
        float tl[KSEL]; int ti[KSEL];
        unsigned mask = 0;
        for (int k = 0; k < KSEL; k++) {
            float best = -1e30f; int bi = 0;
            for (int h = 0; h < NH; h++)
                if (!((mask >> h) & 1u) && lg[h] > best) { best = lg[h]; bi = h; }
            mask |= 1u << bi; tl[k] = best; ti[k] = bi;
        }
        float ws = 0.f, w[KSEL];
        for (int k = 0; k < KSEL; k++) { w[k] = expf(tl[k] - tl[0]); ws += w[k]; }
        for (int k = 0; k < KSEL; k++) {
            g_hw[tok*KSEL + k] = w[k] / ws;
            int h = ti[k];
            int pos = atomicAdd(&g_cnt[h], 1);
            g_list[h*NTOK + pos] = (tok << 3) | k;
        }
        atomicAdd(&g_facc[b*NH + ti[0]], 1.0f);
    }
}

// ---------------- GEMM common ----------------
#define BM 128
#define BN 128
#define BKt 32
#define LDA 36
#define LDB 132
#define LDC 132

#define CPA16(dst, src) asm volatile("cp.async.cg.shared.global [%0], [%1], 16;\n" \
        :: "r"(dst), "l"(src))
#define CPA_COMMIT() asm volatile("cp.async.commit_group;\n")
#define CPA_WAIT1()  asm volatile("cp.async.wait_group 1;\n")
#define CPA_WAIT0()  asm volatile("cp.async.wait_group 0;\n")

#define MMA_TF32(c0,c1,c2,c3,a0,a1,a2,a3,b0,b1) \
    asm volatile("mma.sync.aligned.m16n8k8.row.col.f32.tf32.tf32.f32 " \
        "{%0,%1,%2,%3}, {%4,%5,%6,%7}, {%8,%9}, {%0,%1,%2,%3};\n" \
        : "+f"(c0), "+f"(c1), "+f"(c2), "+f"(c3) \
        : "r"(a0), "r"(a1), "r"(a2), "r"(a3), "r"(b0), "r"(b1))

// ---------------- grouped projection GEMM: raw tf32 MMA, pre-rounded inputs ------
// q,k,v fused via z; rope fused for q,k; outputs tf32-rounded.
__global__ void __launch_bounds__(256, 2) moh_proj_kernel(
    const float* __restrict__ xr,
    const float* __restrict__ Wq, const float* __restrict__ Wk, const float* __restrict__ Wv,
    float* __restrict__ dq, float* __restrict__ dk, float* __restrict__ dv)
{
    int h = blockIdx.y;
    int cnt = g_cnt[h];
    int m0 = blockIdx.x * BM;
    if (m0 >= cnt) return;
    int rows = min(BM, cnt - m0);
    int z = blockIdx.z;
    const float* W = (z == 0) ? Wq : (z == 1) ? Wk : Wv;
    float* dst     = (z == 0) ? dq : (z == 1) ? dk : dv;

    extern __shared__ float sm[];
    float* As[2] = { sm, sm + BM*LDA };
    float* Bs[2] = { sm + 2*BM*LDA, sm + 2*BM*LDA + BKt*LDB };
    float* Csm   = sm;
    __shared__ int s_pk[BM];

    int tid = threadIdx.x;
    if (tid < BM) {
        int r = tid < rows ? tid : rows - 1;
        s_pk[tid] = g_list[h*NTOK + m0 + r];
    }
    __syncthreads();

    int wid = tid >> 5, lane = tid & 31;
    int lr = lane >> 2, lc = lane & 3;
    int wm = wid >> 2, wn = wid & 3;
    int col0 = h * HD;

    int ar[4], ac[4], br[4], bc[4];
    const float* abase[4];
    #pragma unroll
    for (int i = 0; i < 4; i++) {
        int idx = tid + i*256;
        ar[i] = idx >> 3;  ac[i] = (idx & 7) * 4;
        br[i] = idx >> 5;  bc[i] = (idx & 31) * 4;
        abase[i] = xr + (size_t)(s_pk[ar[i]] >> 3) * EMB + ac[i];
    }

    float acc[4][4][4];
    #pragma unroll
    for (int mi = 0; mi < 4; mi++)
        #pragma unroll
        for (int nj = 0; nj < 4; nj++)
            #pragma unroll
            for (int e = 0; e < 4; e++) acc[mi][nj][e] = 0.f;

    const int ntiles = EMB / BKt;
    #pragma unroll
    for (int i = 0; i < 4; i++) {
        unsigned da = (unsigned)__cvta_generic_to_shared(As[0] + ar[i]*LDA + ac[i]);
        CPA16(da, abase[i]);
        unsigned db = (unsigned)__cvta_generic_to_shared(Bs[0] + br[i]*LDB + bc[i]);
        CPA16(db, W + (size_t)br[i] * HDALL + col0 + bc[i]);
    }
    CPA_COMMIT();

    for (int t = 0; t < ntiles; t++) {
        int buf = t & 1;
        if (t + 1 < ntiles) {
            int nb = (t + 1) & 1;
            int k0 = (t + 1) * BKt;
            #pragma unroll
            for (int i = 0; i < 4; i++) {
                unsigned da = (unsigned)__cvta_generic_to_shared(As[nb] + ar[i]*LDA + ac[i]);
                CPA16(da, abase[i] + k0);
                unsigned db = (unsigned)__cvta_generic_to_shared(Bs[nb] + br[i]*LDB + bc[i]);
                CPA16(db, W + (size_t)(k0 + br[i]) * HDALL + col0 + bc[i]);
            }
            CPA_COMMIT();
            CPA_WAIT1();
        } else {
            CPA_WAIT0();
        }
        __syncthreads();

        unsigned* Ab = (unsigned*)As[buf];
        unsigned* Bb = (unsigned*)Bs[buf];
        #pragma unroll
        for (int kk = 0; kk < BKt/8; kk++) {
            int k0 = kk*8;
            unsigned a[4][4];
            #pragma unroll
            for (int mi = 0; mi < 4; mi++) {
                int row = wm*64 + mi*16 + lr;
                a[mi][0] = Ab[row*LDA + k0 + lc];
                a[mi][1] = Ab[(row+8)*LDA + k0 + lc];
                a[mi][2] = Ab[row*LDA + k0 + lc + 4];
                a[mi][3] = Ab[(row+8)*LDA + k0 + lc + 4];
            }
            unsigned b[4][2];
            #pragma unroll
            for (int nj = 0; nj < 4; nj++) {
                int col = wn*32 + nj*8 + lr;
                b[nj][0] = Bb[(k0+lc)*LDB + col];
                b[nj][1] = Bb[(k0+lc+4)*LDB + col];
            }
            #pragma unroll
            for (int mi = 0; mi < 4; mi++)
                #pragma unroll
                for (int nj = 0; nj < 4; nj++)
                    MMA_TF32(acc[mi][nj][0],acc[mi][nj][1],acc[mi][nj][2],acc[mi][nj][3],
                             a[mi][0],a[mi][1],a[mi][2],a[mi][3], b[nj][0],b[nj][1]);
        }
        __syncthreads();
    }

    // stage C in smem
    #pragma unroll
    for (int mi = 0; mi < 4; mi++)
        #pragma unroll
        for (int nj = 0; nj < 4; nj++) {
            int row = wm*64 + mi*16 + lr;
            int col = wn*32 + nj*8 + 2*lc;
            Csm[row*LDC + col]       = acc[mi][nj][0];
            Csm[row*LDC + col + 1]   = acc[mi][nj][1];
            Csm[(row+8)*LDC + col]   = acc[mi][nj][2];
            Csm[(row+8)*LDC + col+1] = acc[mi][nj][3];
        }
    __syncthreads();

    if (z < 2) {
        for (int i = tid; i < BM * 16; i += 256) {
            int row = i >> 4;
            if (row >= rows) break;
            int c4 = (i & 15) * 4;
            int pk = s_pk[row];
            int tok = pk >> 3, j = pk & 7;
            int b = tok / SEQ, s = tok % SEQ;
            float4 lo = *(float4*)&Csm[row*LDC + c4];
            float4 hi = *(float4*)&Csm[row*LDC + c4 + 64];
            float4 olo, ohi;
            float fs = (float)s;
            {
                float cc, sn, ang;
                ang = fs * powf(10000.0f, -(float)(c4+0) / 64.0f);
                cc = cosf(ang); sn = sinf(ang);
                olo.x = tfround(lo.x*cc - hi.x*sn);  ohi.x = tfround(hi.x*cc + lo.x*sn);
                ang = fs * powf(10000.0f, -(float)(c4+1) / 64.0f);
                cc = cosf(ang); sn = sinf(ang);
                olo.y = tfround(lo.y*cc - hi.y*sn);  ohi.y = tfround(hi.y*cc + lo.y*sn);
                ang = fs * powf(10000.0f, -(float)(c4+2) / 64.0f);
                cc = cosf(ang); sn = sinf(ang);
                olo.z = tfround(lo.z*cc - hi.z*sn);  ohi.z = tfround(hi.z*cc + lo.z*sn);
                ang = fs * powf(10000.0f, -(float)(c4+3) / 64.0f);
                cc = cosf(ang); sn = sinf(ang);
                olo.w = tfround(lo.w*cc - hi.w*sn);  ohi.w = tfround(hi.w*cc + lo.w*sn);
            }
            size_t off = (((size_t)(b*KSEL + j)) * SEQ + s) * HD;
            *(float4*)&dst[off + c4]      = olo;
            *(float4*)&dst[off + c4 + 64] = ohi;
        }
    } else {
        for (int i = tid; i < BM * (HD/4); i += 256) {
            int row = i >> 5;
            if (row >= rows) break;
            int c = (i & 31) * 4;
            int pk = s_pk[row];
            int tok = pk >> 3, j = pk & 7;
            int b = tok / SEQ, s = tok % SEQ;
            float4 v = *(float4*)&Csm[row*LDC + c];
            v.x = tfround(v.x); v.y = tfround(v.y);
            v.z = tfround(v.z); v.w = tfround(v.w);
            size_t off = (((size_t)(b*KSEL + j)) * SEQ + s) * HD + c;
            *(float4*)&dst[off] = v;
        }
    }
}

// ---------------- dense GEMM (Wo): raw tf32 MMA, pre-rounded inputs ----------------
__global__ void __launch_bounds__(256, 2) tf32_gemm_kernel(
    const float* __restrict__ A, const float* __restrict__ Bm, float* __restrict__ C,
    int M, int N, int Kd)
{
    extern __shared__ float sm[];
    float* As[2] = { sm, sm + BM*LDA };
    float* Bs[2] = { sm + 2*BM*LDA, sm + 2*BM*LDA + BKt*LDB };

    int tid = threadIdx.x;
    int wid = tid >> 5, lane = tid & 31;
    int lr = lane >> 2, lc = lane & 3;
    int wm = wid >> 2, wn = wid & 3;
    int row0 = blockIdx.y * BM, col0 = blockIdx.x * BN;

    int ar[4], ac[4], br[4], bc[4];
    #pragma unroll
    for (int i = 0; i < 4; i++) {
        int idx = tid + i*256;
        ar[i] = idx >> 3;  ac[i] = (idx & 7) * 4;
        br[i] = idx >> 5;  bc[i] = (idx & 31) * 4;
    }

    float acc[4][4][4];
    #pragma unroll
    for (int mi = 0; mi < 4; mi++)
        #pragma unroll
        for (int nj = 0; nj < 4; nj++)
            #pragma unroll
            for (int e = 0; e < 4; e++) acc[mi][nj][e] = 0.f;

    int ntiles = Kd / BKt;
    #pragma unroll
    for (int i = 0; i < 4; i++) {
        unsigned da = (unsigned)__cvta_generic_to_shared(As[0] + ar[i]*LDA + ac[i]);
        CPA16(da, A + (size_t)(row0 + ar[i]) * Kd + ac[i]);
        unsigned db = (unsigned)__cvta_generic_to_shared(Bs[0] + br[i]*LDB + bc[i]);
        CPA16(db, Bm + (size_t)br[i] * N + col0 + bc[i]);
    }
    CPA_COMMIT();

    for (int t = 0; t < ntiles; t++) {
        int buf = t & 1;
        if (t + 1 < ntiles) {
            int nb = (t + 1) & 1;
            int k0 = (t + 1) * BKt;
            #pragma unroll
            for (int i = 0; i < 4; i++) {
                unsigned da = (unsigned)__cvta_generic_to_shared(As[nb] + ar[i]*LDA + ac[i]);
                CPA16(da, A + (size_t)(row0 + ar[i]) * Kd + k0 + ac[i]);
                unsigned db = (unsigned)__cvta_generic_to_shared(Bs[nb] + br[i]*LDB + bc[i]);
                CPA16(db, Bm + (size_t)(k0 + br[i]) * N + col0 + bc[i]);
            }
            CPA_COMMIT();
            CPA_WAIT1();
        } else {
            CPA_WAIT0();
        }
        __syncthreads();

        unsigned* Ab = (unsigned*)As[buf];
        unsigned* Bb = (unsigned*)Bs[buf];
        #pragma unroll
        for (int kk = 0; kk < BKt/8; kk++) {
            int k0 = kk*8;
            unsigned a[4][4];
            #pragma unroll
            for (int mi = 0; mi < 4; mi++) {
                int row = wm*64 + mi*16 + lr;
                a[mi][0] = Ab[row*LDA + k0 + lc];
                a[mi][1] = Ab[(row+8)*LDA + k0 + lc];
                a[mi][2] = Ab[row*LDA + k0 + lc + 4];
                a[mi][3] = Ab[(row+8)*LDA + k0 + lc + 4];
            }
            unsigned b[4][2];
            #pragma unroll
            for (int nj = 0; nj < 4; nj++) {
                int col = wn*32 + nj*8 + lr;
                b[nj][0] = Bb[(k0+lc)*LDB + col];
                b[nj][1] = Bb[(k0+lc+4)*LDB + col];
            }
            #pragma unroll
            for (int mi = 0; mi < 4; mi++)
                #pragma unroll
                for (int nj = 0; nj < 4; nj++)
                    MMA_TF32(acc[mi][nj][0],acc[mi][nj][1],acc[mi][nj][2],acc[mi][nj][3],
                             a[mi][0],a[mi][1],a[mi][2],a[mi][3], b[nj][0],b[nj][1]);
        }
        __syncthreads();
    }

    #pragma unroll
    for (int mi = 0; mi < 4; mi++)
        #pragma unroll
        for (int nj = 0; nj < 4; nj++) {
            int row = row0 + wm*64 + mi*16 + lr;
            int col = col0 + wn*32 + nj*8 + 2*lc;
            *(float2*)&C[(size_t)row * N + col] =
                make_float2(acc[mi][nj][0], acc[mi][nj][1]);
            *(float2*)&C[(size_t)(row+8) * N + col] =
                make_float2(acc[mi][nj][2], acc[mi][nj][3]);
        }
}

// ---------------- TF32 flash attention, warp-row-ownership (Br=128, Bc=32) ------
#define LQ 132
#define LK 132
#define LV 136
#define LP 36

__global__ void __launch_bounds__(256, 1) flash_tc_kernel(
    const float* __restrict__ Q, const float* __restrict__ Kx, const float* __restrict__ Vx,
    const float* __restrict__ HWp, float* __restrict__ Out)
{
    extern __shared__ float smf[];
    unsigned* Qs    = (unsigned*)smf;           // [128][LQ]
    unsigned* KsBuf = Qs + 128*LQ;              // [2][32][LK]
    unsigned* VsBuf = KsBuf + 2*32*LK;          // [2][32][LV]
    unsigned* Pu    = VsBuf + 2*32*LV;          // [128][LP]

    int tid = threadIdx.x;
    int wid = tid >> 5, lane = tid & 31;
    int lr = lane >> 2, lc = lane & 3;
    int bk = blockIdx.y;
    int q0 = ((int)gridDim.x - 1 - (int)blockIdx.x) * 128;   // heavy-first

    const float* Qp = Q  + (size_t)bk * SEQ * HD;
    const float* Kp = Kx + (size_t)bk * SEQ * HD;
    const float* Vp = Vx + (size_t)bk * SEQ * HD;

    const int nkt = q0/32 + 4;
    const int rbase = wid*16 + lr;
    const int gq0 = q0 + rbase, gq1 = gq0 + 8;

    for (int i = tid; i < 32 * (HD/4); i += 256) {
        int r = i >> 5, cc = (i & 31) * 4;
        unsigned dk = (unsigned)__cvta_generic_to_shared(&KsBuf[r*LK + cc]);
        CPA16(dk, Kp + (size_t)r * HD + cc);
        unsigned dv = (unsigned)__cvta_generic_to_shared(&VsBuf[r*LV + cc]);
        CPA16(dv, Vp + (size_t)r * HD + cc);
    }
    CPA_COMMIT();

    for (int i = tid; i < 128 * (HD/4); i += 256) {
        int r = i >> 5, cc = (i & 31) * 4;
        *(uint4*)&Qs[r*LQ + cc] = *(const uint4*)(Qp + (size_t)(q0 + r) * HD + cc);
    }

    float o[16][4];
    #pragma unroll
    for (int j = 0; j < 16; j++)
        #pragma unroll
        for (int e = 0; e < 4; e++) o[j][e] = 0.f;
    float m0 = -1e30f, m1 = -1e30f, l0 = 0.f, l1 = 0.f;

    const float scale = 0.08838834764831845f;

    for (int kt = 0; kt < nkt; kt++) {
        int stage = kt & 1;
        __syncthreads();
        if (kt + 1 < nkt) {
            int ns = stage ^ 1;
            size_t nb = (size_t)(kt + 1) * 32;
            unsigned* Kn = KsBuf + ns*32*LK;
            unsigned* Vn = VsBuf + ns*32*LV;
            for (int i = tid; i < 32 * (HD/4); i += 256) {
                int r = i >> 5, cc = (i & 31) * 4;
                unsigned dk = (unsigned)__cvta_generic_to_shared(&Kn[r*LK + cc]);
                CPA16(dk, Kp + (nb + r) * HD + cc);
                unsigned dv = (unsigned)__cvta_generic_to_shared(&Vn[r*LV + cc]);
                CPA16(dv, Vp + (nb + r) * HD + cc);
            }
            CPA_COMMIT();
            CPA_WAIT1();
        } else {
            CPA_WAIT0();
        }
        __syncthreads();

        unsigned* Ks = KsBuf + stage*32*LK;
        unsigned* Vs = VsBuf + stage*32*LV;
        int kb = kt * 32;

        float s[4][4];
        #pragma unroll
        for (int nt = 0; nt < 4; nt++)
            #pragma unroll
            for (int e = 0; e < 4; e++) s[nt][e] = 0.f;
        #pragma unroll
        for (int kk = 0; kk < 16; kk++) {
            int k0 = kk*8;
            unsigned a0 = Qs[rbase*LQ + k0 + lc];
            unsigned a1 = Qs[(rbase+8)*LQ + k0 + lc];
            unsigned a2 = Qs[rbase*LQ + k0 + lc + 4];
            unsigned a3 = Qs[(rbase+8)*LQ + k0 + lc + 4];
            #pragma unroll
            for (int nt = 0; nt < 4; nt++) {
                int nc = nt*8 + lr;
                unsigned b0 = Ks[nc*LK + k0 + lc];
                unsigned b1 = Ks[nc*LK + k0 + lc + 4];
                MMA_TF32(s[nt][0],s[nt][1],s[nt][2],s[nt][3], a0,a1,a2,a3, b0,b1);
            }
        }

        {
            int lim0 = gq0 - kb;
            int lim1 = gq1 - kb;
            float p0[8], p1[8];
            float mx0 = -1e30f, mx1 = -1e30f;
            #pragma unroll
            for (int nt = 0; nt < 4; nt++) {
                int c0 = nt*8 + 2*lc, c1 = c0 + 1;
                p0[nt*2]   = (c0 <= lim0) ? s[nt][0]*scale : -1e30f;
                p0[nt*2+1] = (c1 <= lim0) ? s[nt][1]*scale : -1e30f;
                p1[nt*2]   = (c0 <= lim1) ? s[nt][2]*scale : -1e30f;
                p1[nt*2+1] = (c1 <= lim1) ? s[nt][3]*scale : -1e30f;
                mx0 = fmaxf(mx0, fmaxf(p0[nt*2], p0[nt*2+1]));
                mx1 = fmaxf(mx1, fmaxf(p1[nt*2], p1[nt*2+1]));
            }
            mx0 = fmaxf(mx0, __shfl_xor_sync(0xffffffffu, mx0, 1));
            mx0 = fmaxf(mx0, __shfl_xor_sync(0xffffffffu, mx0, 2));
            mx1 = fmaxf(mx1, __shfl_xor_sync(0xffffffffu, mx1, 1));
            mx1 = fmaxf(mx1, __shfl_xor_sync(0xffffffffu, mx1, 2));
            float mn0 = fmaxf(m0, mx0), mn1 = fmaxf(m1, mx1);
            float al0 = __expf(m0 - mn0), al1 = __expf(m1 - mn1);
            float ss0 = 0.f, ss1 = 0.f;
            #pragma unroll
            for (int nt = 0; nt < 4; nt++) {
                int c0 = nt*8 + 2*lc, c1 = c0 + 1;
                float e00 = (c0 <= lim0) ? __expf(p0[nt*2]   - mn0) : 0.f;
                float e01 = (c1 <= lim0) ? __expf(p0[nt*2+1] - mn0) : 0.f;
                float e10 = (c0 <= lim1) ? __expf(p1[nt*2]   - mn1) : 0.f;
                float e11 = (c1 <= lim1) ? __expf(p1[nt*2+1] - mn1) : 0.f;
                Pu[rbase*LP + c0]     = f2tf(e00);
                Pu[rbase*LP + c1]     = f2tf(e01);
                Pu[(rbase+8)*LP + c0] = f2tf(e10);
                Pu[(rbase+8)*LP + c1] = f2tf(e11);
                ss0 += e00 + e01;
                ss1 += e10 + e11;
            }
            ss0 += __shfl_xor_sync(0xffffffffu, ss0, 1);
            ss0 += __shfl_xor_sync(0xffffffffu, ss0, 2);
            ss1 += __shfl_xor_sync(0xffffffffu, ss1, 1);
            ss1 += __shfl_xor_sync(0xffffffffu, ss1, 2);
            l0 = l0 * al0 + ss0;  m0 = mn0;
            l1 = l1 * al1 + ss1;  m1 = mn1;
            #pragma unroll
            for (int j = 0; j < 16; j++) {
                o[j][0] *= al0; o[j][1] *= al0;
                o[j][2] *= al1; o[j][3] *= al1;
            }
        }
        __syncwarp();

        #pragma unroll
        for (int kk = 0; kk < 4; kk++) {
            int k0 = kk*8;
            unsigned a0 = Pu[rbase*LP + k0 + lc];
            unsigned a1 = Pu[(rbase+8)*LP + k0 + lc];
            unsigned a2 = Pu[rbase*LP + k0 + lc + 4];
            unsigned a3 = Pu[(rbase+8)*LP + k0 + lc + 4];
            #pragma unroll
            for (int j = 0; j < 16; j++) {
                int vc = j*8 + lr;
                unsigned b0 = Vs[(k0 + lc)*LV + vc];
                unsigned b1 = Vs[(k0 + lc + 4)*LV + vc];
                MMA_TF32(o[j][0],o[j][1],o[j][2],o[j][3], a0,a1,a2,a3, b0,b1);
            }
        }
    }

    // ---- epilogue (tf32-rounded for the Wo GEMM) ----
    int b = bk >> 3, jslot = bk & 7;
    float w_lo = HWp[((size_t)(b*SEQ + gq0)) * KSEL + jslot] / l0;
    float w_hi = HWp[((size_t)(b*SEQ + gq1)) * KSEL + jslot] / l1;
    #pragma unroll
    for (int j = 0; j < 16; j++) {
        int cb = j*8 + 2*lc;
        size_t off0 = (((size_t)(b*SEQ + gq0)) * KSEL + jslot) * HD + cb;
        size_t off1 = (((size_t)(b*SEQ + gq1)) * KSEL + jslot) * HD + cb;
        float2 v0 = make_float2(tfround(o[j][0]*w_lo), tfround(o[j][1]*w_lo));
        float2 v1 = make_float2(tfround(o[j][2]*w_hi), tfround(o[j][3]*w_hi));
        *(float2*)&Out[off0] = v0;
        *(float2*)&Out[off1] = v1;
    }
}

// ---------------- aux loss + head_counts tail ----------------
__global__ void finalize_kernel(float* __restrict__ out, int out_size) {
    int base = NTOK * EMB;
    int extra = out_size - base;
    if (extra <= 0) return;
    bool has_aux = (extra == BATCH*NH + 1) || (extra == 1);
    int zend = has_aux ? out_size - 1 : out_size;
    int gtid = blockIdx.x * blockDim.x + threadIdx.x;
    for (int i = base + gtid; i < zend; i += gridDim.x * blockDim.x) out[i] = 0.f;
    if (gtid == 0 && has_aux) {
        float aux = 0.f;
        for (int b = 0; b < BATCH; b++) {
            float sb = 0.f;
            for (int h = 0; h < NH; h++)
                sb += (g_facc[b*NH + h] / (float)SEQ) * (g_pacc[b*NH + h] / (float)SEQ);
            aux += sb;
        }
        aux = (float)NH * aux / (float)BATCH - 0.01f * (g_ent[0] / (float)(BATCH*SEQ));
        out[out_size - 1] = aux;
    }
}

// ---------------- launcher ----------------
extern "C" void kernel_launch(void* const* d_in, const int* in_sizes, int n_in,
                              void* d_out, int out_size)
{
    (void)in_sizes; (void)n_in;
    const float* x  = (const float*)d_in[0];
    const float* Wq = (const float*)d_in[1];
    const float* Wk = (const float*)d_in[2];
    const float* Wv = (const float*)d_in[3];
    const float* Wr = (const float*)d_in[4];
    const float* Wo = (const float*)d_in[5];
    float* out = (float*)d_out;

    float *p_q, *p_k, *p_v, *p_attn, *p_hw;
    float *p_xr, *p_wq, *p_wk, *p_wv, *p_wo;
    cudaGetSymbolAddress((void**)&p_q,    g_q);
    cudaGetSymbolAddress((void**)&p_k,    g_k);
    cudaGetSymbolAddress((void**)&p_v,    g_v);
    cudaGetSymbolAddress((void**)&p_attn, g_attn);
    cudaGetSymbolAddress((void**)&p_hw,   g_hw);
    cudaGetSymbolAddress((void**)&p_xr,   g_xr);
    cudaGetSymbolAddress((void**)&p_wq,   g_wq);
    cudaGetSymbolAddress((void**)&p_wk,   g_wk);
    cudaGetSymbolAddress((void**)&p_wv,   g_wv);
    cudaGetSymbolAddress((void**)&p_wo,   g_wo);

    size_t gemm_smem = (size_t)(2*BM*LDA + 2*BKt*LDB) * sizeof(float);
    cudaFuncSetAttribute(moh_proj_kernel, cudaFuncAttributeMaxDynamicSharedMemorySize,
                         (int)gemm_smem);
    cudaFuncSetAttribute(tf32_gemm_kernel, cudaFuncAttributeMaxDynamicSharedMemorySize,
                         (int)gemm_smem);
    size_t flash_smem = (size_t)(128*LQ + 2*32*LK + 2*32*LV + 128*LP) * sizeof(float);
    cudaFuncSetAttribute(flash_tc_kernel, cudaFuncAttributeMaxDynamicSharedMemorySize,
                         (int)flash_smem);

    zero_stats_kernel<<<1, 128>>>();
    router_kernel<<<NTOK, 32>>>(x, Wr);

    // pre-round inputs/weights to tf32
    tfround_kernel<<<512, 256>>>((const float4*)x,  (float4*)p_xr, NTOK*EMB/4);
    tfround_kernel<<<512, 256>>>((const float4*)Wq, (float4*)p_wq, EMB*HDALL/4);
    tfround_kernel<<<512, 256>>>((const float4*)Wk, (float4*)p_wk, EMB*HDALL/4);
    tfround_kernel<<<512, 256>>>((const float4*)Wv, (float4*)p_wv, EMB*HDALL/4);
    tfround_kernel<<<512, 256>>>((const float4*)Wo, (float4*)p_wo, KD*EMB/4);

    dim3 gproj(NTOK/BM, NH, 3);
    moh_proj_kernel<<<gproj, 256, gemm_smem>>>(p_xr, p_wq, p_wk, p_wv, p_q, p_k, p_v);

    dim3 gflash(SEQ/128, BATCH*KSEL);   // (16, 16)
    flash_tc_kernel<<<gflash, 256, flash_smem>>>(p_q, p_k, p_v, p_hw, p_attn);

    dim3 gout(EMB/BN, NTOK/BM);
    tf32_gemm_kernel<<<gout, 256, gemm_smem>>>(p_attn, p_wo, out, NTOK, EMB, EMB);

    finalize_kernel<<<32, 256>>>(out, out_size);
}